// round 7
// baseline (speedup 1.0000x reference)
#include <cuda_runtime.h>
#include <math.h>

// ---------------- problem constants ----------------
#define NH 12      // heads
#define NT 2048    // sequence length
#define ND 64      // head dim
#define NM 266     // performer features
#define NVH 192    // performer value hidden (3D)
#define ND2 128    // 2*D
#define NC4 48     // 4*H conv channels
#define NTH 1024   // T/2

#define DATA_NORM 0.35355339059327373f   // 64^-0.25
#define M_RS      0.06131393394849658f   // 266^-0.5

// ---------------- scratch (device globals; no allocs allowed) ----------------
__device__ float g_pq[NH*NT*NM];
__device__ float g_pk[NH*NT*NM];
__device__ float g_krowmax[NH*NT];
__device__ float g_kdiag[NH*NT];
__device__ float g_kheadmax[NH];
__device__ float g_kv[NH*NM*NVH];
__device__ float g_pksum[NH*NM];
__device__ float g_tperf[NH*NT*NVH];
__device__ float g_tenc[NH*NT*ND2];
__device__ float g_xdec[NC4*NT*ND];
__device__ float g_c1[NC4*NTH*ND];
__device__ float g_c2[NC4*NTH*ND];
__device__ float g_c3[NH*NT*ND];
__device__ unsigned g_maskbits[NH*NT*4];

// ---------------- compensated accumulation helpers ----------------
struct KS { float s, c; };
__device__ __forceinline__ void kinit(KS& a, float v) { a.s = v; a.c = 0.f; }
__device__ __forceinline__ void kadd(KS& a, float v) {
    float t = a.s + v;
    if (fabsf(a.s) >= fabsf(v)) a.c += (a.s - t) + v;
    else                        a.c += (v - t) + a.s;
    a.s = t;
}
__device__ __forceinline__ void kmac(KS& a, float x, float y) {
    float p = x * y;
    float e = fmaf(x, y, -p);   // exact product error
    kadd(a, p);
    a.c += e;
}
__device__ __forceinline__ float kval(const KS& a) { return a.s + a.c; }

__device__ __forceinline__ float blockSum128(float v, float* s4) {
    #pragma unroll
    for (int o = 16; o; o >>= 1) v += __shfl_down_sync(0xffffffffu, v, o);
    int lane = threadIdx.x & 31, wid = threadIdx.x >> 5;
    __syncthreads();
    if (lane == 0) s4[wid] = v;
    __syncthreads();
    return (s4[0] + s4[1]) + (s4[2] + s4[3]);
}

// ---------------- 1) performer feature maps ----------------
template<int IS_Q>
__global__ void phi_kernel(const float* __restrict__ x, const float* __restrict__ proj)
{
    int t = blockIdx.x, h = blockIdx.y, tid = threadIdx.x; // 128 threads
    __shared__ float xs[ND];
    __shared__ float s4[4];
    const float* xr = x + ((size_t)(h*NT + t))*ND;
    if (tid < ND) xs[tid] = xr[tid] * DATA_NORM;
    __syncthreads();

    KS dks; kinit(dks, 0.f);
    #pragma unroll
    for (int d = 0; d < ND; d++) { float vv = xs[d]; kmac(dks, vv, vv); }
    float diag = 0.5f * kval(dks);

    float xp[3]; int ms[3];
    float lmax = -1e30f;
    #pragma unroll
    for (int i = 0; i < 3; i++) {
        int m = tid + i*128; ms[i] = m; xp[i] = 0.f;
        if (m < NM) {
            const float* pr = proj + (size_t)m*ND;
            KS acc; kinit(acc, 0.f);
            #pragma unroll
            for (int u = 0; u < ND; u++) kmac(acc, pr[u], xs[u]);
            xp[i] = kval(acc);
            lmax = fmaxf(lmax, xp[i]);
        }
    }
    #pragma unroll
    for (int o = 16; o; o >>= 1) lmax = fmaxf(lmax, __shfl_down_sync(0xffffffffu, lmax, o));
    if ((tid & 31) == 0) s4[tid >> 5] = lmax;
    __syncthreads();
    float gmax = fmaxf(fmaxf(s4[0], s4[1]), fmaxf(s4[2], s4[3]));

    if (IS_Q) {
        float* orow = g_pq + ((size_t)(h*NT + t))*NM;
        #pragma unroll
        for (int i = 0; i < 3; i++)
            if (ms[i] < NM) orow[ms[i]] = M_RS * (expf((xp[i] - diag) - gmax) + 1e-6f);
    } else {
        float* orow = g_pk + ((size_t)(h*NT + t))*NM;
        #pragma unroll
        for (int i = 0; i < 3; i++)
            if (ms[i] < NM) orow[ms[i]] = xp[i];
        if (tid == 0) { g_krowmax[h*NT + t] = gmax; g_kdiag[h*NT + t] = diag; }
    }
}

__global__ void headmax_kernel() {
    int h = blockIdx.x, tid = threadIdx.x;
    __shared__ float sr[256];
    float m = -1e30f;
    for (int t = tid; t < NT; t += 256) m = fmaxf(m, g_krowmax[h*NT + t]);
    sr[tid] = m; __syncthreads();
    for (int s = 128; s; s >>= 1) { if (tid < s) sr[tid] = fmaxf(sr[tid], sr[tid+s]); __syncthreads(); }
    if (tid == 0) g_kheadmax[h] = sr[0];
}

__global__ void pk_finish_kernel() {
    int idx = blockIdx.x*256 + threadIdx.x;
    if (idx >= NH*NT*NM) return;
    int row = idx / NM;
    int h = row / NT;
    g_pk[idx] = M_RS * (expf((g_pk[idx] - g_kdiag[row]) - g_kheadmax[h]) + 1e-6f);
}

__global__ void pksum_kernel() {
    int h = blockIdx.x, m = threadIdx.x;
    if (m >= NM) return;
    KS s; kinit(s, 0.f);
    for (int t = 0; t < NT; t++) kadd(s, g_pk[((size_t)(h*NT + t))*NM + m]);
    g_pksum[h*NM + m] = kval(s);
}

// kv[h][m][d] = sum_t pk[h][t][m] * vfa[h][t][d]
__global__ void kv_kernel(const float* __restrict__ vfa) {
    int h = blockIdx.z;
    int m0 = blockIdx.x*16, n0 = blockIdx.y*16;
    int tx = threadIdx.x, ty = threadIdx.y;
    int tid = ty*16 + tx;
    __shared__ float As[32][16];
    __shared__ float Bs[32][16];
    KS acc; kinit(acc, 0.f);
    for (int k0 = 0; k0 < NT; k0 += 32) {
        #pragma unroll
        for (int e = tid; e < 512; e += 256) {
            int kk = e >> 4, j = e & 15;
            int m = m0 + j;
            As[kk][j] = (m < NM) ? g_pk[((size_t)(h*NT + k0 + kk))*NM + m] : 0.f;
            Bs[kk][j] = vfa[((size_t)(h*NT + k0 + kk))*NVH + n0 + j];
        }
        __syncthreads();
        #pragma unroll
        for (int kk = 0; kk < 32; kk++) kmac(acc, As[kk][ty], Bs[kk][tx]);
        __syncthreads();
    }
    int m = m0 + ty;
    if (m < NM) g_kv[((size_t)h*NM + m)*NVH + n0 + tx] = kval(acc);
}

// t_perf = (pq @ kv) * z ;  z = 1/(pq . pksum + 1e-8)
__global__ void tperf_kernel() {
    int h = blockIdx.y, t0 = blockIdx.x*8, tid = threadIdx.x; // 192 threads
    __shared__ float pqs[8][NM];
    __shared__ float zs[8];
    for (int e = tid; e < 8*NM; e += 192) {
        int r = e / NM, m = e % NM;
        pqs[r][m] = g_pq[((size_t)(h*NT + t0 + r))*NM + m];
    }
    __syncthreads();
    if (tid < 8) {
        KS dn; kinit(dn, 0.f);
        for (int m = 0; m < NM; m++) kmac(dn, pqs[tid][m], g_pksum[h*NM + m]);
        zs[tid] = (float)(1.0 / ((double)kval(dn) + 1e-8));
    }
    KS acc[8];
    #pragma unroll
    for (int r = 0; r < 8; r++) kinit(acc[r], 0.f);
    for (int m = 0; m < NM; m++) {
        float kvv = g_kv[((size_t)h*NM + m)*NVH + tid];
        #pragma unroll
        for (int r = 0; r < 8; r++) kmac(acc[r], pqs[r][m], kvv);
    }
    __syncthreads();
    #pragma unroll
    for (int r = 0; r < 8; r++)
        g_tperf[((size_t)(h*NT + t0 + r))*NVH + tid] = kval(acc[r]) * zs[r];
}

// ---------------- 2) encoder: Linear(192->128) + LN + exact GELU ----------------
__global__ void enc_kernel(const float* __restrict__ enc_w, const float* __restrict__ enc_b,
                           const float* __restrict__ ln_g, const float* __restrict__ ln_b)
{
    int h = blockIdx.y, t0 = blockIdx.x*8, tid = threadIdx.x; // 128 threads
    __shared__ float tps[8][NVH];
    __shared__ float s4[4];
    for (int e = tid; e < 8*NVH; e += 128) {
        int r = e / NVH, vv = e % NVH;
        tps[r][vv] = g_tperf[((size_t)(h*NT + t0 + r))*NVH + vv];
    }
    __syncthreads();
    KS acc[8];
    #pragma unroll
    for (int r = 0; r < 8; r++) kinit(acc[r], enc_b[tid]);
    for (int vv = 0; vv < NVH; vv++) {
        float w = enc_w[vv*ND2 + tid];
        #pragma unroll
        for (int r = 0; r < 8; r++) kmac(acc[r], tps[r][vv], w);
    }
    float gg = ln_g[tid], bb = ln_b[tid];
    for (int r = 0; r < 8; r++) {
        float av = kval(acc[r]);
        float su = blockSum128(av, s4);
        float mu = su * (1.f/128.f);
        float d = av - mu;
        float s2 = blockSum128(d*d, s4);
        float var = s2 * (1.f/128.f);
        float y = d * (float)(1.0 / sqrt((double)var + 1e-5)) * gg + bb;
        float ge = 0.5f*y*(1.f + erff(y*0.70710678118654752f));
        g_tenc[((size_t)(h*NT + t0 + r))*ND2 + tid] = ge;
    }
}

// ---------------- 3) decoder Linear(128->256) + channel split ----------------
__global__ void dec_kernel(const float* __restrict__ dec_w, const float* __restrict__ dec_b)
{
    int h = blockIdx.y, t0 = blockIdx.x*8, tid = threadIdx.x; // 256 threads
    __shared__ float tes[8][ND2];
    for (int e = tid; e < 8*ND2; e += 256) {
        int r = e >> 7, vv = e & 127;
        tes[r][vv] = g_tenc[((size_t)(h*NT + t0 + r))*ND2 + vv];
    }
    __syncthreads();
    KS acc[8];
    #pragma unroll
    for (int r = 0; r < 8; r++) kinit(acc[r], dec_b[tid]);
    for (int vv = 0; vv < ND2; vv++) {
        float w = dec_w[vv*256 + tid];
        #pragma unroll
        for (int r = 0; r < 8; r++) kmac(acc[r], tes[r][vv], w);
    }
    int g = tid >> 6, wc = tid & 63, c = h*4 + g;
    #pragma unroll
    for (int r = 0; r < 8; r++)
        g_xdec[((size_t)c*NT + (t0 + r))*ND + wc] = kval(acc[r]);
}

// ---------------- 4) CNN stack (compensated) ----------------
__global__ void conv1_kernel(const float* __restrict__ W, const float* __restrict__ B)
{
    int to = blockIdx.x, tid = threadIdx.x; // 256 threads
    int w = tid & 63, cosub = tid >> 6;
    __shared__ float in_s[NC4][3][66];
    __shared__ float w_s[4][NC4][9];
    for (int e = tid; e < NC4*3*66; e += 256) {
        int ci = e / 198, rem = e % 198, dy = rem / 66, col = rem % 66;
        int r = 2*to + dy - 1, ws = col - 1;
        float vv = 0.f;
        if (r >= 0 && r < NT && ws >= 0 && ws < ND) vv = g_xdec[((size_t)ci*NT + r)*ND + ws];
        in_s[ci][dy][col] = vv;
    }
    KS acc[12];
    #pragma unroll
    for (int i = 0; i < 12; i++) kinit(acc[i], B[cosub + 4*i]);
    for (int cc = 0; cc < 12; cc++) {
        __syncthreads();
        for (int e = tid; e < 4*NC4*9; e += 256) {
            int cis = e / 432, rem = e % 432, co = rem / 9, kk = rem % 9;
            w_s[cis][co][kk] = W[((size_t)co*NC4 + (cc*4 + cis))*9 + kk];
        }
        __syncthreads();
        #pragma unroll
        for (int cis = 0; cis < 4; cis++) {
            int ci = cc*4 + cis;
            float i00 = in_s[ci][0][w], i01 = in_s[ci][0][w+1], i02 = in_s[ci][0][w+2];
            float i10 = in_s[ci][1][w], i11 = in_s[ci][1][w+1], i12 = in_s[ci][1][w+2];
            float i20 = in_s[ci][2][w], i21 = in_s[ci][2][w+1], i22 = in_s[ci][2][w+2];
            #pragma unroll
            for (int i = 0; i < 12; i++) {
                const float* wp = w_s[cis][cosub + 4*i];
                kmac(acc[i], i00, wp[0]); kmac(acc[i], i01, wp[1]); kmac(acc[i], i02, wp[2]);
                kmac(acc[i], i10, wp[3]); kmac(acc[i], i11, wp[4]); kmac(acc[i], i12, wp[5]);
                kmac(acc[i], i20, wp[6]); kmac(acc[i], i21, wp[7]); kmac(acc[i], i22, wp[8]);
            }
        }
    }
    #pragma unroll
    for (int i = 0; i < 12; i++) {
        int co = cosub + 4*i;
        g_c1[((size_t)co*NTH + to)*ND + w] = fmaxf(kval(acc[i]), 0.f);
    }
}

__global__ void conv2_kernel(const float* __restrict__ W, const float* __restrict__ B)
{
    int to = blockIdx.x, tid = threadIdx.x;
    int w = tid & 63, cosub = tid >> 6;
    __shared__ float in_s[NC4][3][66];
    __shared__ float w_s[4][NC4][9];
    for (int e = tid; e < NC4*3*66; e += 256) {
        int ci = e / 198, rem = e % 198, dy = rem / 66, col = rem % 66;
        int r = to + dy - 1, ws = col - 1;
        float vv = 0.f;
        if (r >= 0 && r < NTH && ws >= 0 && ws < ND) vv = g_c1[((size_t)ci*NTH + r)*ND + ws];
        in_s[ci][dy][col] = vv;
    }
    KS acc[12];
    #pragma unroll
    for (int i = 0; i < 12; i++) kinit(acc[i], B[cosub + 4*i]);
    for (int cc = 0; cc < 12; cc++) {
        __syncthreads();
        for (int e = tid; e < 4*NC4*9; e += 256) {
            int cis = e / 432, rem = e % 432, co = rem / 9, kk = rem % 9;
            w_s[cis][co][kk] = W[((size_t)co*NC4 + (cc*4 + cis))*9 + kk];
        }
        __syncthreads();
        #pragma unroll
        for (int cis = 0; cis < 4; cis++) {
            int ci = cc*4 + cis;
            float i00 = in_s[ci][0][w], i01 = in_s[ci][0][w+1], i02 = in_s[ci][0][w+2];
            float i10 = in_s[ci][1][w], i11 = in_s[ci][1][w+1], i12 = in_s[ci][1][w+2];
            float i20 = in_s[ci][2][w], i21 = in_s[ci][2][w+1], i22 = in_s[ci][2][w+2];
            #pragma unroll
            for (int i = 0; i < 12; i++) {
                const float* wp = w_s[cis][cosub + 4*i];
                kmac(acc[i], i00, wp[0]); kmac(acc[i], i01, wp[1]); kmac(acc[i], i02, wp[2]);
                kmac(acc[i], i10, wp[3]); kmac(acc[i], i11, wp[4]); kmac(acc[i], i12, wp[5]);
                kmac(acc[i], i20, wp[6]); kmac(acc[i], i21, wp[7]); kmac(acc[i], i22, wp[8]);
            }
        }
    }
    #pragma unroll
    for (int i = 0; i < 12; i++) {
        int co = cosub + 4*i;
        g_c2[((size_t)co*NTH + to)*ND + w] = fmaxf(kval(acc[i]), 0.f);
    }
}

__global__ void conv3_kernel(const float* __restrict__ W, const float* __restrict__ B)
{
    int to = blockIdx.x, tid = threadIdx.x; // 768 threads
    int w = tid & 63, co = tid >> 6;
    __shared__ float in_s[NC4][3][66];
    __shared__ float w_s[8][12][9];
    for (int e = tid; e < NC4*3*66; e += 768) {
        int ci = e / 198, rem = e % 198, dy = rem / 66, col = rem % 66;
        int r = to + dy - 1, ws = col - 1;
        float vv = 0.f;
        if (r >= 0 && r < NT && ws >= 0 && ws < ND) vv = g_c2[((size_t)ci*NTH + (r >> 1))*ND + ws];
        in_s[ci][dy][col] = vv;
    }
    KS acc; kinit(acc, B[co]);
    for (int cc = 0; cc < 6; cc++) {
        __syncthreads();
        for (int e = tid; e < 8*12*9; e += 768) {
            int cis = e / 108, rem = e % 108, c = rem / 9, kk = rem % 9;
            w_s[cis][c][kk] = W[((size_t)c*NC4 + (cc*8 + cis))*9 + kk];
        }
        __syncthreads();
        #pragma unroll
        for (int cis = 0; cis < 8; cis++) {
            int ci = cc*8 + cis;
            const float* wp = w_s[cis][co];
            kmac(acc, in_s[ci][0][w], wp[0]); kmac(acc, in_s[ci][0][w+1], wp[1]); kmac(acc, in_s[ci][0][w+2], wp[2]);
            kmac(acc, in_s[ci][1][w], wp[3]); kmac(acc, in_s[ci][1][w+1], wp[4]); kmac(acc, in_s[ci][1][w+2], wp[5]);
            kmac(acc, in_s[ci][2][w], wp[6]); kmac(acc, in_s[ci][2][w+1], wp[7]); kmac(acc, in_s[ci][2][w+2], wp[8]);
        }
    }
    g_c3[((size_t)co*NT + to)*ND + w] = kval(acc);
}

// ---------------- 5-7) est softmax with XLA-bit-matched rounding -> top-k mask ----------------
// Ref thresholds on f32 est values; f32 TIES at rank 2/3 (P~1.5e-4/row) make the
// ref admit 96 keys instead of 64 on ~4 rows/run. We replicate the rounding:
//   e   = correctly-rounded f32 exp  (== __nv_expf where CR; fast-math-proof)
//   d   = XLA row-reduction order: 128 thr/row, shfl-down tree per warp,
//         cross-warp (p0+p2)+(p1+p3). With est pairs equal, per-warp tree over
//         (d0,d0,...,d15,d15) == 2 * tree16(d) with tree16 = shfl-down 8,4,2,1.
//   est = __fdiv_rn(e, d)   (IEEE f32 division, == XLA's fdiv)
__global__ void mask_kernel()
{
    int t = blockIdx.x, h = blockIdx.y, lane = threadIdx.x; // 32 threads
    const float* row = g_c3 + ((size_t)h*NT + t)*ND;
    float v0 = row[lane], v1 = row[lane + 32];

    float mx = fmaxf(v0, v1);
    #pragma unroll
    for (int o = 16; o; o >>= 1) mx = fmaxf(mx, __shfl_xor_sync(0xffffffffu, mx, o));

    // correctly-rounded f32 exp via double (__nv_exp <=1 ulp double => CR float)
    float e0 = (float)exp((double)(v0 - mx));
    float e1 = (float)exp((double)(v1 - mx));

    // per-16-group tree: groups = lanes [0..15] and [16..31] of each register.
    // tree16: shfl_down 8,4,2,1 (valid at group-relative lane 0 and 16), then exact double.
    float s0 = e0, s1 = e1;
    #pragma unroll
    for (int o = 8; o; o >>= 1) {
        s0 += __shfl_down_sync(0xffffffffu, s0, o);
        s1 += __shfl_down_sync(0xffffffffu, s1, o);
    }
    s0 += s0;  // exact doubling (pair duplication in est row)
    s1 += s1;
    // warp partials: p0 = s0@0, p1 = s0@16, p2 = s1@0, p3 = s1@16
    float p0 = __shfl_sync(0xffffffffu, s0, 0);
    float p1 = __shfl_sync(0xffffffffu, s0, 16);
    float p2 = __shfl_sync(0xffffffffu, s1, 0);
    float p3 = __shfl_sync(0xffffffffu, s1, 16);
    float dsum = (p0 + p2) + (p1 + p3);

    float est0 = __fdiv_rn(e0, dsum);
    float est1 = __fdiv_rn(e1, dsum);

    // warp multiset top-2 of the 64 est values
    float a1 = fmaxf(est0, est1), a2 = fminf(est0, est1);
    #pragma unroll
    for (int o = 16; o; o >>= 1) {
        float b1 = __shfl_xor_sync(0xffffffffu, a1, o);
        float b2 = __shfl_xor_sync(0xffffffffu, a2, o);
        if (b1 > a1) { a2 = fmaxf(a1, b2); a1 = b1; }
        else         { a2 = fmaxf(a2, b1); }
    }
    float thresh = a2;
    int b0 = (est0 >= thresh) ? 1 : 0;
    int b1i = (est1 >= thresh) ? 1 : 0;
    unsigned words[4];
    #pragma unroll
    for (int k2 = 0; k2 < 4; k2++) {
        int wsrc = 16*k2 + (lane >> 1);
        int bv = __shfl_sync(0xffffffffu, (k2 < 2) ? b0 : b1i, wsrc & 31);
        words[k2] = __ballot_sync(0xffffffffu, bv);
    }
    if (lane == 0) {
        unsigned* mp = g_maskbits + ((size_t)h*NT + t)*4;
        mp[0] = words[0]; mp[1] = words[1]; mp[2] = words[2]; mp[3] = words[3];
    }
}

// ---------------- 8) block-sparse masked attention ----------------
__global__ void attn_kernel(const float* __restrict__ q, const float* __restrict__ k,
                            const float* __restrict__ v, float* __restrict__ out)
{
    int t = blockIdx.x, h = blockIdx.y, tid = threadIdx.x; // 128 threads
    __shared__ float qs[ND];
    __shared__ int blk_list[128];
    __shared__ int s_nblk;
    __shared__ float sc[2048];
    __shared__ float s4[4];
    __shared__ unsigned mw[4];
    __shared__ int flags[128];
    __shared__ float part[128];

    if (tid < 4) mw[tid] = g_maskbits[((size_t)h*NT + t)*4 + tid];
    if (tid < ND) qs[tid] = q[((size_t)h*NT + t)*ND + tid];
    __syncthreads();
    flags[tid] = (mw[tid >> 5] >> (tid & 31)) & 1;
    __syncthreads();
    if (tid == 0) {
        int n = 0;
        for (int j = 0; j < 128; j++) if (flags[j]) blk_list[n++] = j;
        s_nblk = n;
    }
    __syncthreads();
    int nk = s_nblk * 16;

    float lmax = -1e30f;
    for (int idx = tid; idx < nk; idx += 128) {
        int ss = blk_list[idx >> 4]*16 + (idx & 15);
        const float4* kr = (const float4*)(k + ((size_t)h*NT + ss)*ND);
        float acc = 0.f;
        #pragma unroll
        for (int u = 0; u < 16; u++) {
            float4 k4 = kr[u];
            acc += k4.x*qs[4*u] + k4.y*qs[4*u+1] + k4.z*qs[4*u+2] + k4.w*qs[4*u+3];
        }
        float scv = acc * 0.125f;
        sc[idx] = scv;
        lmax = fmaxf(lmax, scv);
    }
    #pragma unroll
    for (int o = 16; o; o >>= 1) lmax = fmaxf(lmax, __shfl_down_sync(0xffffffffu, lmax, o));
    if ((tid & 31) == 0) s4[tid >> 5] = lmax;
    __syncthreads();
    float gmax = fmaxf(fmaxf(s4[0], s4[1]), fmaxf(s4[2], s4[3]));

    float lsum = 0.f;
    for (int idx = tid; idx < nk; idx += 128) {
        float p = expf(sc[idx] - gmax);
        sc[idx] = p;
        lsum += p;
    }
    #pragma unroll
    for (int o = 16; o; o >>= 1) lsum += __shfl_down_sync(0xffffffffu, lsum, o);
    __syncthreads();
    if ((tid & 31) == 0) s4[tid >> 5] = lsum;
    __syncthreads();
    float denom = (s4[0] + s4[1]) + (s4[2] + s4[3]);
    float rden = (float)(1.0 / (double)denom);

    int d = tid & 63, half = tid >> 6;
    float acc = 0.f;
    for (int idx = half; idx < nk; idx += 2) {
        int ss = blk_list[idx >> 4]*16 + (idx & 15);
        acc += sc[idx] * v[((size_t)h*NT + ss)*ND + d];
    }
    part[tid] = acc;
    __syncthreads();
    if (tid < 64)
        out[((size_t)h*NT + t)*ND + d] = (part[tid] + part[tid + 64]) * rden;
}

// ---------------- launch ----------------
extern "C" void kernel_launch(void* const* d_in, const int* in_sizes, int n_in,
                              void* d_out, int out_size)
{
    const float* q     = (const float*)d_in[0];
    const float* k     = (const float*)d_in[1];
    const float* v     = (const float*)d_in[2];
    const float* vfa   = (const float*)d_in[3];
    const float* proj  = (const float*)d_in[4];
    const float* enc_w = (const float*)d_in[5];
    const float* enc_b = (const float*)d_in[6];
    const float* ln_g  = (const float*)d_in[7];
    const float* ln_b  = (const float*)d_in[8];
    const float* dec_w = (const float*)d_in[9];
    const float* dec_b = (const float*)d_in[10];
    const float* c1w   = (const float*)d_in[11];
    const float* c1b   = (const float*)d_in[12];
    const float* c2w   = (const float*)d_in[13];
    const float* c2b   = (const float*)d_in[14];
    const float* c3w   = (const float*)d_in[15];
    const float* c3b   = (const float*)d_in[16];
    float* out = (float*)d_out;

    dim3 gTH(NT, NH);

    phi_kernel<1><<<gTH, 128>>>(q, proj);
    phi_kernel<0><<<gTH, 128>>>(k, proj);
    headmax_kernel<<<NH, 256>>>();
    pk_finish_kernel<<<(NH*NT*NM + 255)/256, 256>>>();
    pksum_kernel<<<NH, 288>>>();
    kv_kernel<<<dim3((NM + 15)/16, NVH/16, NH), dim3(16, 16)>>>(vfa);
    tperf_kernel<<<dim3(NT/8, NH), 192>>>();
    enc_kernel<<<dim3(NT/8, NH), 128>>>(enc_w, enc_b, ln_g, ln_b);
    dec_kernel<<<dim3(NT/8, NH), 256>>>(dec_w, dec_b);
    conv1_kernel<<<NTH, 256>>>(c1w, c1b);
    conv2_kernel<<<NTH, 256>>>(c2w, c2b);
    conv3_kernel<<<NT, 768>>>(c3w, c3b);
    mask_kernel<<<gTH, 32>>>();
    attn_kernel<<<gTH, 128>>>(q, k, v, out);
}

// round 10
// speedup vs baseline: 1.6037x; 1.6037x over previous
#include <cuda_runtime.h>
#include <math.h>

// ---------------- problem constants ----------------
#define NH 12      // heads
#define NT 2048    // sequence length
#define ND 64      // head dim
#define NM 266     // performer features
#define NVH 192    // performer value hidden (3D)
#define ND2 128    // 2*D
#define NC4 48     // 4*H conv channels
#define NTH 1024   // T/2

#define DATA_NORM 0.35355339059327373f   // 64^-0.25
#define M_RS      0.06131393394849658f   // 266^-0.5

typedef unsigned long long ull;

// ---------------- scratch (device globals; no allocs allowed) ----------------
__device__ float g_pq[NH*NT*NM];
__device__ float g_pk[NH*NT*NM];
__device__ float g_krowmax[NH*NT];
__device__ float g_kdiag[NH*NT];
__device__ float g_kheadmax[NH];
__device__ float g_kv[NH*NM*NVH];
__device__ float g_pksum[NH*NM];
__device__ float g_tperf[NH*NT*NVH];
__device__ float g_tenc[NH*NT*ND2];
__device__ float g_xdec[NC4*NT*ND];
__device__ float g_c1[NC4*NTH*ND];
__device__ float g_c2[NC4*NTH*ND];
__device__ float g_c3[NH*NT*ND];
__device__ unsigned g_maskbits[NH*NT*4];

// ---------------- packed f32x2 helpers (sm_103a) ----------------
__device__ __forceinline__ ull F2(float a, float b) {
    ull r; asm("mov.b64 %0,{%1,%2};" : "=l"(r) : "f"(a), "f"(b)); return r;
}
__device__ __forceinline__ ull DUP(float a) { return F2(a, a); }
__device__ __forceinline__ void UNF2(ull p, float& a, float& b) {
    asm("mov.b64 {%0,%1},%2;" : "=f"(a), "=f"(b) : "l"(p));
}
__device__ __forceinline__ ull ADD2(ull a, ull b) {
    ull r; asm("add.rn.f32x2 %0,%1,%2;" : "=l"(r) : "l"(a), "l"(b)); return r;
}
__device__ __forceinline__ ull MUL2(ull a, ull b) {
    ull r; asm("mul.rn.f32x2 %0,%1,%2;" : "=l"(r) : "l"(a), "l"(b)); return r;
}
__device__ __forceinline__ ull FMA2(ull a, ull b, ull c) {
    ull r; asm("fma.rn.f32x2 %0,%1,%2,%3;" : "=l"(r) : "l"(a), "l"(b), "l"(c)); return r;
}
#define NEG1X2 0xBF800000BF800000ULL
#define SGNM2  0x8000000080000000ULL
__device__ __forceinline__ ull SUB2(ull a, ull b) { return FMA2(b, NEG1X2, a); } // fl(a-b) exact rounding

// packed compensated accumulator: two independent Neumaier-grade lanes.
// Knuth branchless TwoSum gives the bit-identical exact error as fast-two-sum.
struct KS2 { ull s, c; };
__device__ __forceinline__ void kinit2(KS2& a, ull v) { a.s = v; a.c = 0ULL; }
__device__ __forceinline__ void kmac2(KS2& a, ull x, ull y) {
    ull p  = MUL2(x, y);
    ull ep = FMA2(x, y, p ^ SGNM2);   // exact product error
    ull t  = ADD2(a.s, p);
    ull z  = SUB2(t, a.s);
    ull e1 = SUB2(a.s, SUB2(t, z));
    ull e2 = SUB2(p, z);
    a.c = ADD2(a.c, ADD2(e1, e2));    // exact sum error
    a.c = ADD2(a.c, ep);
    a.s = t;
}
__device__ __forceinline__ void kval2(const KS2& a, float& r0, float& r1) {
    float s0, s1, c0, c1;
    UNF2(a.s, s0, s1); UNF2(a.c, c0, c1);
    r0 = s0 + c0; r1 = s1 + c1;
}

// ---------------- scalar compensated helpers (small paths) ----------------
struct KS { float s, c; };
__device__ __forceinline__ void kinit(KS& a, float v) { a.s = v; a.c = 0.f; }
__device__ __forceinline__ void kadd(KS& a, float v) {
    float t = a.s + v;
    if (fabsf(a.s) >= fabsf(v)) a.c += (a.s - t) + v;
    else                        a.c += (v - t) + a.s;
    a.s = t;
}
__device__ __forceinline__ void kmac(KS& a, float x, float y) {
    float p = x * y;
    float e = fmaf(x, y, -p);
    kadd(a, p);
    a.c += e;
}
__device__ __forceinline__ float kval(const KS& a) { return a.s + a.c; }

__device__ __forceinline__ float blockSum128(float v, float* s4) {
    #pragma unroll
    for (int o = 16; o; o >>= 1) v += __shfl_down_sync(0xffffffffu, v, o);
    int lane = threadIdx.x & 31, wid = threadIdx.x >> 5;
    __syncthreads();
    if (lane == 0) s4[wid] = v;
    __syncthreads();
    return (s4[0] + s4[1]) + (s4[2] + s4[3]);
}

// ---------------- 1) performer feature maps (4 t per block, t-pairs packed) ----------------
template<int IS_Q>
__global__ void phi_kernel(const float* __restrict__ x, const float* __restrict__ proj)
{
    int t0 = blockIdx.x*4, h = blockIdx.y, tid = threadIdx.x; // 128 threads
    __shared__ float xs[4][ND];
    __shared__ float smax[4][4];
    for (int e = tid; e < 4*ND; e += 128) {
        int j = e >> 6, u = e & 63;
        xs[j][u] = x[((size_t)(h*NT + t0 + j))*ND + u] * DATA_NORM;
    }
    __syncthreads();

    KS2 dk01, dk23; kinit2(dk01, 0ULL); kinit2(dk23, 0ULL);
    #pragma unroll 8
    for (int u = 0; u < ND; u++) {
        ull a = F2(xs[0][u], xs[1][u]);
        ull b = F2(xs[2][u], xs[3][u]);
        kmac2(dk01, a, a);
        kmac2(dk23, b, b);
    }
    float dg[4];
    { float q0, q1;
      kval2(dk01, q0, q1); dg[0] = 0.5f*q0; dg[1] = 0.5f*q1;
      kval2(dk23, q0, q1); dg[2] = 0.5f*q0; dg[3] = 0.5f*q1; }

    float xpv[3][4];
    float lmax[4] = {-1e30f, -1e30f, -1e30f, -1e30f};

    // m = tid and m = tid+128 fused (both always < 266)
    {
        const float* p0 = proj + (size_t)tid*ND;
        const float* p1 = proj + (size_t)(tid + 128)*ND;
        KS2 a001, a023, a101, a123;
        kinit2(a001, 0ULL); kinit2(a023, 0ULL); kinit2(a101, 0ULL); kinit2(a123, 0ULL);
        #pragma unroll 4
        for (int u = 0; u < ND; u++) {
            ull x01 = F2(xs[0][u], xs[1][u]);
            ull x23 = F2(xs[2][u], xs[3][u]);
            ull w0 = DUP(p0[u]); ull w1 = DUP(p1[u]);
            kmac2(a001, w0, x01); kmac2(a023, w0, x23);
            kmac2(a101, w1, x01); kmac2(a123, w1, x23);
        }
        kval2(a001, xpv[0][0], xpv[0][1]); kval2(a023, xpv[0][2], xpv[0][3]);
        kval2(a101, xpv[1][0], xpv[1][1]); kval2(a123, xpv[1][2], xpv[1][3]);
        #pragma unroll
        for (int j = 0; j < 4; j++)
            lmax[j] = fmaxf(xpv[0][j], xpv[1][j]);
    }
    int m2 = tid + 256;
    if (m2 < NM) {
        const float* p2 = proj + (size_t)m2*ND;
        KS2 a201, a223; kinit2(a201, 0ULL); kinit2(a223, 0ULL);
        #pragma unroll 4
        for (int u = 0; u < ND; u++) {
            ull w2 = DUP(p2[u]);
            kmac2(a201, w2, F2(xs[0][u], xs[1][u]));
            kmac2(a223, w2, F2(xs[2][u], xs[3][u]));
        }
        kval2(a201, xpv[2][0], xpv[2][1]); kval2(a223, xpv[2][2], xpv[2][3]);
        #pragma unroll
        for (int j = 0; j < 4; j++)
            lmax[j] = fmaxf(lmax[j], xpv[2][j]);
    }

    #pragma unroll
    for (int j = 0; j < 4; j++) {
        float v = lmax[j];
        #pragma unroll
        for (int o = 16; o; o >>= 1) v = fmaxf(v, __shfl_down_sync(0xffffffffu, v, o));
        if ((tid & 31) == 0) smax[j][tid >> 5] = v;
    }
    __syncthreads();
    float gmax[4];
    #pragma unroll
    for (int j = 0; j < 4; j++)
        gmax[j] = fmaxf(fmaxf(smax[j][0], smax[j][1]), fmaxf(smax[j][2], smax[j][3]));

    if (IS_Q) {
        #pragma unroll
        for (int j = 0; j < 4; j++) {
            float* orow = g_pq + ((size_t)(h*NT + t0 + j))*NM;
            orow[tid]       = M_RS * (expf((xpv[0][j] - dg[j]) - gmax[j]) + 1e-6f);
            orow[tid + 128] = M_RS * (expf((xpv[1][j] - dg[j]) - gmax[j]) + 1e-6f);
            if (m2 < NM)
                orow[m2]    = M_RS * (expf((xpv[2][j] - dg[j]) - gmax[j]) + 1e-6f);
        }
    } else {
        #pragma unroll
        for (int j = 0; j < 4; j++) {
            float* orow = g_pk + ((size_t)(h*NT + t0 + j))*NM;
            orow[tid]       = xpv[0][j];
            orow[tid + 128] = xpv[1][j];
            if (m2 < NM) orow[m2] = xpv[2][j];
        }
        if (tid == 0) {
            #pragma unroll
            for (int j = 0; j < 4; j++) {
                g_krowmax[h*NT + t0 + j] = gmax[j];
                g_kdiag[h*NT + t0 + j]   = dg[j];
            }
        }
    }
}

__global__ void headmax_kernel() {
    int h = blockIdx.x, tid = threadIdx.x;
    __shared__ float sr[256];
    float m = -1e30f;
    for (int t = tid; t < NT; t += 256) m = fmaxf(m, g_krowmax[h*NT + t]);
    sr[tid] = m; __syncthreads();
    for (int s = 128; s; s >>= 1) { if (tid < s) sr[tid] = fmaxf(sr[tid], sr[tid+s]); __syncthreads(); }
    if (tid == 0) g_kheadmax[h] = sr[0];
}

__global__ void pk_finish_kernel() {
    int idx = blockIdx.x*256 + threadIdx.x;
    if (idx >= NH*NT*NM) return;
    int row = idx / NM;
    int h = row / NT;
    g_pk[idx] = M_RS * (expf((g_pk[idx] - g_kdiag[row]) - g_kheadmax[h]) + 1e-6f);
}

__global__ void pksum_kernel() {
    int h = blockIdx.x, m = threadIdx.x;
    if (m >= NM) return;
    KS s; kinit(s, 0.f);
    for (int t = 0; t < NT; t++) kadd(s, g_pk[((size_t)(h*NT + t))*NM + m]);
    g_pksum[h*NM + m] = kval(s);
}

// kv[h][m][d] = sum_t pk[h][t][m] * vfa[h][t][d]   (n-pairs packed)
__global__ void kv_kernel(const float* __restrict__ vfa) {
    int h = blockIdx.z;
    int m0 = blockIdx.x*16, n0 = blockIdx.y*16;
    int tx = threadIdx.x;   // 0..7
    int ty = threadIdx.y;   // 0..15
    int tid = ty*8 + tx;    // 128 threads
    __shared__ float As[32][16];
    __shared__ float Bs[32][16];
    KS2 acc; kinit2(acc, 0ULL);
    for (int k0 = 0; k0 < NT; k0 += 32) {
        #pragma unroll
        for (int e = tid; e < 512; e += 128) {
            int kk = e >> 4, j = e & 15;
            int m = m0 + j;
            As[kk][j] = (m < NM) ? g_pk[((size_t)(h*NT + k0 + kk))*NM + m] : 0.f;
            Bs[kk][j] = vfa[((size_t)(h*NT + k0 + kk))*NVH + n0 + j];
        }
        __syncthreads();
        #pragma unroll
        for (int kk = 0; kk < 32; kk++)
            kmac2(acc, DUP(As[kk][ty]), F2(Bs[kk][tx], Bs[kk][tx+8]));
        __syncthreads();
    }
    int m = m0 + ty;
    if (m < NM) {
        float r0, r1; kval2(acc, r0, r1);
        g_kv[((size_t)h*NM + m)*NVH + n0 + tx]     = r0;
        g_kv[((size_t)h*NM + m)*NVH + n0 + tx + 8] = r1;
    }
}

// t_perf = (pq @ kv) * z ;  z = 1/(pq . pksum + 1e-8)  (row-pairs packed)
__global__ void tperf_kernel() {
    int h = blockIdx.y, t0 = blockIdx.x*8, tid = threadIdx.x; // 192 threads
    __shared__ float pqs[8][NM];
    __shared__ float zs[8];
    for (int e = tid; e < 8*NM; e += 192) {
        int r = e / NM, m = e % NM;
        pqs[r][m] = g_pq[((size_t)(h*NT + t0 + r))*NM + m];
    }
    __syncthreads();
    if (tid < 8) {
        KS dn; kinit(dn, 0.f);
        for (int m = 0; m < NM; m++) kmac(dn, pqs[tid][m], g_pksum[h*NM + m]);
        zs[tid] = (float)(1.0 / ((double)kval(dn) + 1e-8));
    }
    KS2 acc2[4];
    #pragma unroll
    for (int j = 0; j < 4; j++) kinit2(acc2[j], 0ULL);
    for (int m = 0; m < NM; m++) {
        ull kv2 = DUP(g_kv[((size_t)h*NM + m)*NVH + tid]);
        #pragma unroll
        for (int j = 0; j < 4; j++)
            kmac2(acc2[j], F2(pqs[2*j][m], pqs[2*j+1][m]), kv2);
    }
    __syncthreads();
    #pragma unroll
    for (int j = 0; j < 4; j++) {
        float r0, r1; kval2(acc2[j], r0, r1);
        g_tperf[((size_t)(h*NT + t0 + 2*j))*NVH + tid]     = r0 * zs[2*j];
        g_tperf[((size_t)(h*NT + t0 + 2*j + 1))*NVH + tid] = r1 * zs[2*j+1];
    }
}

// ---------------- 2) encoder: Linear(192->128) + LN + exact GELU ----------------
__global__ void enc_kernel(const float* __restrict__ enc_w, const float* __restrict__ enc_b,
                           const float* __restrict__ ln_g, const float* __restrict__ ln_b)
{
    int h = blockIdx.y, t0 = blockIdx.x*8, tid = threadIdx.x; // 128 threads
    __shared__ float tps[8][NVH];
    __shared__ float s4[4];
    for (int e = tid; e < 8*NVH; e += 128) {
        int r = e / NVH, vv = e % NVH;
        tps[r][vv] = g_tperf[((size_t)(h*NT + t0 + r))*NVH + vv];
    }
    __syncthreads();
    KS2 acc2[4];
    #pragma unroll
    for (int j = 0; j < 4; j++) kinit2(acc2[j], DUP(enc_b[tid]));
    for (int vv = 0; vv < NVH; vv++) {
        ull w2 = DUP(enc_w[vv*ND2 + tid]);
        #pragma unroll
        for (int j = 0; j < 4; j++)
            kmac2(acc2[j], F2(tps[2*j][vv], tps[2*j+1][vv]), w2);
    }
    float av[8];
    #pragma unroll
    for (int j = 0; j < 4; j++) kval2(acc2[j], av[2*j], av[2*j+1]);

    float gg = ln_g[tid], bb = ln_b[tid];
    for (int r = 0; r < 8; r++) {
        float su = blockSum128(av[r], s4);
        float mu = su * (1.f/128.f);
        float d = av[r] - mu;
        float s2 = blockSum128(d*d, s4);
        float var = s2 * (1.f/128.f);
        float y = d * (float)(1.0 / sqrt((double)var + 1e-5)) * gg + bb;
        float ge = 0.5f*y*(1.f + erff(y*0.70710678118654752f));
        g_tenc[((size_t)(h*NT + t0 + r))*ND2 + tid] = ge;
    }
}

// ---------------- 3) decoder Linear(128->256) + channel split ----------------
__global__ void dec_kernel(const float* __restrict__ dec_w, const float* __restrict__ dec_b)
{
    int h = blockIdx.y, t0 = blockIdx.x*8, tid = threadIdx.x; // 256 threads
    __shared__ float tes[8][ND2];
    for (int e = tid; e < 8*ND2; e += 256) {
        int r = e >> 7, vv = e & 127;
        tes[r][vv] = g_tenc[((size_t)(h*NT + t0 + r))*ND2 + vv];
    }
    __syncthreads();
    KS2 acc2[4];
    #pragma unroll
    for (int j = 0; j < 4; j++) kinit2(acc2[j], DUP(dec_b[tid]));
    for (int vv = 0; vv < ND2; vv++) {
        ull w2 = DUP(dec_w[vv*256 + tid]);
        #pragma unroll
        for (int j = 0; j < 4; j++)
            kmac2(acc2[j], F2(tes[2*j][vv], tes[2*j+1][vv]), w2);
    }
    int g = tid >> 6, wc = tid & 63, c = h*4 + g;
    #pragma unroll
    for (int j = 0; j < 4; j++) {
        float r0, r1; kval2(acc2[j], r0, r1);
        g_xdec[((size_t)c*NT + (t0 + 2*j))*ND + wc]     = r0;
        g_xdec[((size_t)c*NT + (t0 + 2*j + 1))*ND + wc] = r1;
    }
}

// ---------------- 4) CNN stack (channel-pairs packed) ----------------
__global__ void conv1_kernel(const float* __restrict__ W, const float* __restrict__ B)
{
    int to = blockIdx.x, tid = threadIdx.x; // 256 threads
    int w = tid & 63, cosub = tid >> 6;
    __shared__ float in_s[NC4][3][66];
    __shared__ ull w_u[4][24][9];
    for (int e = tid; e < NC4*3*66; e += 256) {
        int ci = e / 198, rem = e % 198, dy = rem / 66, col = rem % 66;
        int r = 2*to + dy - 1, ws = col - 1;
        float vv = 0.f;
        if (r >= 0 && r < NT && ws >= 0 && ws < ND) vv = g_xdec[((size_t)ci*NT + r)*ND + ws];
        in_s[ci][dy][col] = vv;
    }
    KS2 acc2[6];
    #pragma unroll
    for (int i = 0; i < 6; i++)
        kinit2(acc2[i], F2(B[cosub + 4*i], B[cosub + 4*i + 24]));
    for (int cc = 0; cc < 12; cc++) {
        __syncthreads();
        for (int e = tid; e < 4*24*9; e += 256) {
            int cis = e / 216, rem = e % 216, co = rem / 9, kk = rem % 9;
            int cin = cc*4 + cis;
            w_u[cis][co][kk] = F2(W[((size_t)co*NC4 + cin)*9 + kk],
                                  W[((size_t)(co + 24)*NC4 + cin)*9 + kk]);
        }
        __syncthreads();
        #pragma unroll
        for (int cis = 0; cis < 4; cis++) {
            int ci = cc*4 + cis;
            ull d0 = DUP(in_s[ci][0][w]), d1 = DUP(in_s[ci][0][w+1]), d2 = DUP(in_s[ci][0][w+2]);
            ull d3 = DUP(in_s[ci][1][w]), d4 = DUP(in_s[ci][1][w+1]), d5 = DUP(in_s[ci][1][w+2]);
            ull d6 = DUP(in_s[ci][2][w]), d7 = DUP(in_s[ci][2][w+1]), d8 = DUP(in_s[ci][2][w+2]);
            #pragma unroll
            for (int i = 0; i < 6; i++) {
                const ull* wp = w_u[cis][cosub + 4*i];
                kmac2(acc2[i], d0, wp[0]); kmac2(acc2[i], d1, wp[1]); kmac2(acc2[i], d2, wp[2]);
                kmac2(acc2[i], d3, wp[3]); kmac2(acc2[i], d4, wp[4]); kmac2(acc2[i], d5, wp[5]);
                kmac2(acc2[i], d6, wp[6]); kmac2(acc2[i], d7, wp[7]); kmac2(acc2[i], d8, wp[8]);
            }
        }
    }
    #pragma unroll
    for (int i = 0; i < 6; i++) {
        float r0, r1; kval2(acc2[i], r0, r1);
        int co = cosub + 4*i;
        g_c1[((size_t)co*NTH + to)*ND + w]        = fmaxf(r0, 0.f);
        g_c1[((size_t)(co + 24)*NTH + to)*ND + w] = fmaxf(r1, 0.f);
    }
}

__global__ void conv2_kernel(const float* __restrict__ W, const float* __restrict__ B)
{
    int to = blockIdx.x, tid = threadIdx.x;
    int w = tid & 63, cosub = tid >> 6;
    __shared__ float in_s[NC4][3][66];
    __shared__ ull w_u[4][24][9];
    for (int e = tid; e < NC4*3*66; e += 256) {
        int ci = e / 198, rem = e % 198, dy = rem / 66, col = rem % 66;
        int r = to + dy - 1, ws = col - 1;
        float vv = 0.f;
        if (r >= 0 && r < NTH && ws >= 0 && ws < ND) vv = g_c1[((size_t)ci*NTH + r)*ND + ws];
        in_s[ci][dy][col] = vv;
    }
    KS2 acc2[6];
    #pragma unroll
    for (int i = 0; i < 6; i++)
        kinit2(acc2[i], F2(B[cosub + 4*i], B[cosub + 4*i + 24]));
    for (int cc = 0; cc < 12; cc++) {
        __syncthreads();
        for (int e = tid; e < 4*24*9; e += 256) {
            int cis = e / 216, rem = e % 216, co = rem / 9, kk = rem % 9;
            int cin = cc*4 + cis;
            w_u[cis][co][kk] = F2(W[((size_t)co*NC4 + cin)*9 + kk],
                                  W[((size_t)(co + 24)*NC4 + cin)*9 + kk]);
        }
        __syncthreads();
        #pragma unroll
        for (int cis = 0; cis < 4; cis++) {
            int ci = cc*4 + cis;
            ull d0 = DUP(in_s[ci][0][w]), d1 = DUP(in_s[ci][0][w+1]), d2 = DUP(in_s[ci][0][w+2]);
            ull d3 = DUP(in_s[ci][1][w]), d4 = DUP(in_s[ci][1][w+1]), d5 = DUP(in_s[ci][1][w+2]);
            ull d6 = DUP(in_s[ci][2][w]), d7 = DUP(in_s[ci][2][w+1]), d8 = DUP(in_s[ci][2][w+2]);
            #pragma unroll
            for (int i = 0; i < 6; i++) {
                const ull* wp = w_u[cis][cosub + 4*i];
                kmac2(acc2[i], d0, wp[0]); kmac2(acc2[i], d1, wp[1]); kmac2(acc2[i], d2, wp[2]);
                kmac2(acc2[i], d3, wp[3]); kmac2(acc2[i], d4, wp[4]); kmac2(acc2[i], d5, wp[5]);
                kmac2(acc2[i], d6, wp[6]); kmac2(acc2[i], d7, wp[7]); kmac2(acc2[i], d8, wp[8]);
            }
        }
    }
    #pragma unroll
    for (int i = 0; i < 6; i++) {
        float r0, r1; kval2(acc2[i], r0, r1);
        int co = cosub + 4*i;
        g_c2[((size_t)co*NTH + to)*ND + w]        = fmaxf(r0, 0.f);
        g_c2[((size_t)(co + 24)*NTH + to)*ND + w] = fmaxf(r1, 0.f);
    }
}

// conv3: nearest-upsample rows fused; output-channel pairs packed; 384 threads
__global__ void conv3_kernel(const float* __restrict__ W, const float* __restrict__ B)
{
    int to = blockIdx.x, tid = threadIdx.x; // 384 threads: w = tid&63, cop = tid>>6 (0..5)
    int w = tid & 63, cop = tid >> 6;
    __shared__ float in_s[NC4][3][66];
    __shared__ ull w_u[8][6][9];
    for (int e = tid; e < NC4*3*66; e += 384) {
        int ci = e / 198, rem = e % 198, dy = rem / 66, col = rem % 66;
        int r = to + dy - 1, ws = col - 1;
        float vv = 0.f;
        if (r >= 0 && r < NT && ws >= 0 && ws < ND) vv = g_c2[((size_t)ci*NTH + (r >> 1))*ND + ws];
        in_s[ci][dy][col] = vv;
    }
    KS2 acc; kinit2(acc, F2(B[cop], B[cop + 6]));
    for (int cc = 0; cc < 6; cc++) {
        __syncthreads();
        for (int e = tid; e < 8*6*9; e += 384) {
            int cis = e / 54, rem = e % 54, c = rem / 9, kk = rem % 9;
            int cin = cc*8 + cis;
            w_u[cis][c][kk] = F2(W[((size_t)c*NC4 + cin)*9 + kk],
                                 W[((size_t)(c + 6)*NC4 + cin)*9 + kk]);
        }
        __syncthreads();
        #pragma unroll
        for (int cis = 0; cis < 8; cis++) {
            int ci = cc*8 + cis;
            const ull* wp = w_u[cis][cop];
            kmac2(acc, DUP(in_s[ci][0][w]),   wp[0]);
            kmac2(acc, DUP(in_s[ci][0][w+1]), wp[1]);
            kmac2(acc, DUP(in_s[ci][0][w+2]), wp[2]);
            kmac2(acc, DUP(in_s[ci][1][w]),   wp[3]);
            kmac2(acc, DUP(in_s[ci][1][w+1]), wp[4]);
            kmac2(acc, DUP(in_s[ci][1][w+2]), wp[5]);
            kmac2(acc, DUP(in_s[ci][2][w]),   wp[6]);
            kmac2(acc, DUP(in_s[ci][2][w+1]), wp[7]);
            kmac2(acc, DUP(in_s[ci][2][w+2]), wp[8]);
        }
    }
    float r0, r1; kval2(acc, r0, r1);
    g_c3[((size_t)cop*NT + to)*ND + w]       = r0;
    g_c3[((size_t)(cop + 6)*NT + to)*ND + w] = r1;
}

// ---------------- 5-7) est softmax with XLA-bit-matched rounding -> top-k mask ----------------
// (UNCHANGED from passing R7 kernel — mask-critical)
__global__ void mask_kernel()
{
    int t = blockIdx.x, h = blockIdx.y, lane = threadIdx.x; // 32 threads
    const float* row = g_c3 + ((size_t)h*NT + t)*ND;
    float v0 = row[lane], v1 = row[lane + 32];

    float mx = fmaxf(v0, v1);
    #pragma unroll
    for (int o = 16; o; o >>= 1) mx = fmaxf(mx, __shfl_xor_sync(0xffffffffu, mx, o));

    float e0 = (float)exp((double)(v0 - mx));
    float e1 = (float)exp((double)(v1 - mx));

    float s0 = e0, s1 = e1;
    #pragma unroll
    for (int o = 8; o; o >>= 1) {
        s0 += __shfl_down_sync(0xffffffffu, s0, o);
        s1 += __shfl_down_sync(0xffffffffu, s1, o);
    }
    s0 += s0;
    s1 += s1;
    float p0 = __shfl_sync(0xffffffffu, s0, 0);
    float p1 = __shfl_sync(0xffffffffu, s0, 16);
    float p2 = __shfl_sync(0xffffffffu, s1, 0);
    float p3 = __shfl_sync(0xffffffffu, s1, 16);
    float dsum = (p0 + p2) + (p1 + p3);

    float est0 = __fdiv_rn(e0, dsum);
    float est1 = __fdiv_rn(e1, dsum);

    float a1 = fmaxf(est0, est1), a2 = fminf(est0, est1);
    #pragma unroll
    for (int o = 16; o; o >>= 1) {
        float b1 = __shfl_xor_sync(0xffffffffu, a1, o);
        float b2 = __shfl_xor_sync(0xffffffffu, a2, o);
        if (b1 > a1) { a2 = fmaxf(a1, b2); a1 = b1; }
        else         { a2 = fmaxf(a2, b1); }
    }
    float thresh = a2;
    int b0 = (est0 >= thresh) ? 1 : 0;
    int b1i = (est1 >= thresh) ? 1 : 0;
    unsigned words[4];
    #pragma unroll
    for (int k2 = 0; k2 < 4; k2++) {
        int wsrc = 16*k2 + (lane >> 1);
        int bv = __shfl_sync(0xffffffffu, (k2 < 2) ? b0 : b1i, wsrc & 31);
        words[k2] = __ballot_sync(0xffffffffu, bv);
    }
    if (lane == 0) {
        unsigned* mp = g_maskbits + ((size_t)h*NT + t)*4;
        mp[0] = words[0]; mp[1] = words[1]; mp[2] = words[2]; mp[3] = words[3];
    }
}

// ---------------- 8) block-sparse masked attention ----------------
__global__ void attn_kernel(const float* __restrict__ q, const float* __restrict__ k,
                            const float* __restrict__ v, float* __restrict__ out)
{
    int t = blockIdx.x, h = blockIdx.y, tid = threadIdx.x; // 128 threads
    __shared__ float qs[ND];
    __shared__ int blk_list[128];
    __shared__ int s_nblk;
    __shared__ float sc[2048];
    __shared__ float s4[4];
    __shared__ unsigned mw[4];
    __shared__ int flags[128];
    __shared__ float part[128];

    if (tid < 4) mw[tid] = g_maskbits[((size_t)h*NT + t)*4 + tid];
    if (tid < ND) qs[tid] = q[((size_t)h*NT + t)*ND + tid];
    __syncthreads();
    flags[tid] = (mw[tid >> 5] >> (tid & 31)) & 1;
    __syncthreads();
    if (tid == 0) {
        int n = 0;
        for (int j = 0; j < 128; j++) if (flags[j]) blk_list[n++] = j;
        s_nblk = n;
    }
    __syncthreads();
    int nk = s_nblk * 16;

    float lmax = -1e30f;
    for (int idx = tid; idx < nk; idx += 128) {
        int ss = blk_list[idx >> 4]*16 + (idx & 15);
        const float4* kr = (const float4*)(k + ((size_t)h*NT + ss)*ND);
        float acc = 0.f;
        #pragma unroll
        for (int u = 0; u < 16; u++) {
            float4 k4 = kr[u];
            acc += k4.x*qs[4*u] + k4.y*qs[4*u+1] + k4.z*qs[4*u+2] + k4.w*qs[4*u+3];
        }
        float scv = acc * 0.125f;
        sc[idx] = scv;
        lmax = fmaxf(lmax, scv);
    }
    #pragma unroll
    for (int o = 16; o; o >>= 1) lmax = fmaxf(lmax, __shfl_down_sync(0xffffffffu, lmax, o));
    if ((tid & 31) == 0) s4[tid >> 5] = lmax;
    __syncthreads();
    float gmax = fmaxf(fmaxf(s4[0], s4[1]), fmaxf(s4[2], s4[3]));

    float lsum = 0.f;
    for (int idx = tid; idx < nk; idx += 128) {
        float p = expf(sc[idx] - gmax);
        sc[idx] = p;
        lsum += p;
    }
    #pragma unroll
    for (int o = 16; o; o >>= 1) lsum += __shfl_down_sync(0xffffffffu, lsum, o);
    __syncthreads();
    if ((tid & 31) == 0) s4[tid >> 5] = lsum;
    __syncthreads();
    float denom = (s4[0] + s4[1]) + (s4[2] + s4[3]);
    float rden = (float)(1.0 / (double)denom);

    int d = tid & 63, half = tid >> 6;
    float acc = 0.f;
    for (int idx = half; idx < nk; idx += 2) {
        int ss = blk_list[idx >> 4]*16 + (idx & 15);
        acc += sc[idx] * v[((size_t)h*NT + ss)*ND + d];
    }
    part[tid] = acc;
    __syncthreads();
    if (tid < 64)
        out[((size_t)h*NT + t)*ND + d] = (part[tid] + part[tid + 64]) * rden;
}

// ---------------- launch ----------------
extern "C" void kernel_launch(void* const* d_in, const int* in_sizes, int n_in,
                              void* d_out, int out_size)
{
    const float* q     = (const float*)d_in[0];
    const float* k     = (const float*)d_in[1];
    const float* v     = (const float*)d_in[2];
    const float* vfa   = (const float*)d_in[3];
    const float* proj  = (const float*)d_in[4];
    const float* enc_w = (const float*)d_in[5];
    const float* enc_b = (const float*)d_in[6];
    const float* ln_g  = (const float*)d_in[7];
    const float* ln_b  = (const float*)d_in[8];
    const float* dec_w = (const float*)d_in[9];
    const float* dec_b = (const float*)d_in[10];
    const float* c1w   = (const float*)d_in[11];
    const float* c1b   = (const float*)d_in[12];
    const float* c2w   = (const float*)d_in[13];
    const float* c2b   = (const float*)d_in[14];
    const float* c3w   = (const float*)d_in[15];
    const float* c3b   = (const float*)d_in[16];
    float* out = (float*)d_out;

    dim3 gTH(NT, NH);

    phi_kernel<1><<<dim3(NT/4, NH), 128>>>(q, proj);
    phi_kernel<0><<<dim3(NT/4, NH), 128>>>(k, proj);
    headmax_kernel<<<NH, 256>>>();
    pk_finish_kernel<<<(NH*NT*NM + 255)/256, 256>>>();
    pksum_kernel<<<NH, 288>>>();
    kv_kernel<<<dim3((NM + 15)/16, NVH/16, NH), dim3(8, 16)>>>(vfa);
    tperf_kernel<<<dim3(NT/8, NH), 192>>>();
    enc_kernel<<<dim3(NT/8, NH), 128>>>(enc_w, enc_b, ln_g, ln_b);
    dec_kernel<<<dim3(NT/8, NH), 256>>>(dec_w, dec_b);
    conv1_kernel<<<NTH, 256>>>(c1w, c1b);
    conv2_kernel<<<NTH, 256>>>(c2w, c2b);
    conv3_kernel<<<NT, 384>>>(c3w, c3b);
    mask_kernel<<<gTH, 32>>>();
    attn_kernel<<<gTH, 128>>>(q, k, v, out);
}

// round 11
// speedup vs baseline: 1.8756x; 1.1696x over previous
#include <cuda_runtime.h>
#include <math.h>

// ---------------- problem constants ----------------
#define NH 12      // heads
#define NT 2048    // sequence length
#define ND 64      // head dim
#define NM 266     // performer features
#define NVH 192    // performer value hidden (3D)
#define ND2 128    // 2*D
#define NC4 48     // 4*H conv channels
#define NTH 1024   // T/2

#define DATA_NORM 0.35355339059327373f   // 64^-0.25
#define M_RS      0.06131393394849658f   // 266^-0.5

typedef unsigned long long ull;

// ---------------- scratch (device globals; no allocs allowed) ----------------
__device__ float g_pq[NH*NT*NM];
__device__ float g_pk[NH*NT*NM];
__device__ float g_krowmax[NH*NT];
__device__ float g_kdiag[NH*NT];
__device__ float g_kheadmax[NH];
__device__ float g_kv[NH*NM*NVH];
__device__ float g_pksum[NH*NM];
__device__ float g_tperf[NH*NT*NVH];
__device__ float g_tenc[NH*NT*ND2];
__device__ float g_xdec[NC4*NT*ND];
__device__ float g_c1[NC4*NTH*ND];
__device__ float g_c2[NC4*NTH*ND];
__device__ float g_c3[NH*NT*ND];
__device__ unsigned g_maskbits[NH*NT*4];

// ---------------- packed f32x2 helpers (sm_103a) ----------------
__device__ __forceinline__ ull F2(float a, float b) {
    ull r; asm("mov.b64 %0,{%1,%2};" : "=l"(r) : "f"(a), "f"(b)); return r;
}
__device__ __forceinline__ ull DUP(float a) { return F2(a, a); }
__device__ __forceinline__ void UNF2(ull p, float& a, float& b) {
    asm("mov.b64 {%0,%1},%2;" : "=f"(a), "=f"(b) : "l"(p));
}
__device__ __forceinline__ ull ADD2(ull a, ull b) {
    ull r; asm("add.rn.f32x2 %0,%1,%2;" : "=l"(r) : "l"(a), "l"(b)); return r;
}
__device__ __forceinline__ ull MUL2(ull a, ull b) {
    ull r; asm("mul.rn.f32x2 %0,%1,%2;" : "=l"(r) : "l"(a), "l"(b)); return r;
}
__device__ __forceinline__ ull FMA2(ull a, ull b, ull c) {
    ull r; asm("fma.rn.f32x2 %0,%1,%2,%3;" : "=l"(r) : "l"(a), "l"(b), "l"(c)); return r;
}
#define NEG1X2 0xBF800000BF800000ULL
#define SGNM2  0x8000000080000000ULL
__device__ __forceinline__ ull SUB2(ull a, ull b) { return FMA2(b, NEG1X2, a); } // fl(a-b)

// packed compensated accumulator: two independent Kahan lanes with exact
// product-error folding.  7 fma-pipe ops per 2 MACs.
// Convention: true sum ~= s - c   (c carries the pending negative correction)
struct KS2 { ull s, c; };
__device__ __forceinline__ void kinit2(KS2& a, ull v) { a.s = v; a.c = 0ULL; }
__device__ __forceinline__ void kmac2(KS2& a, ull x, ull y) {
    ull p  = MUL2(x, y);
    ull ep = FMA2(x, y, p ^ SGNM2);   // exact product error: xy - p
    ull yy = SUB2(p, a.c);            // apply pending correction
    ull t  = ADD2(a.s, yy);
    ull d  = SUB2(t, a.s);
    a.c    = SUB2(SUB2(d, yy), ep);   // lost low bits of yy, minus product error
    a.s    = t;
}
__device__ __forceinline__ void kval2(const KS2& a, float& r0, float& r1) {
    float s0, s1, c0, c1;
    UNF2(a.s, s0, s1); UNF2(a.c, c0, c1);
    r0 = s0 - c0; r1 = s1 - c1;
}

// ---------------- scalar compensated helpers (small paths) ----------------
struct KS { float s, c; };
__device__ __forceinline__ void kinit(KS& a, float v) { a.s = v; a.c = 0.f; }
__device__ __forceinline__ void kadd(KS& a, float v) {
    float t = a.s + v;
    if (fabsf(a.s) >= fabsf(v)) a.c += (a.s - t) + v;
    else                        a.c += (v - t) + a.s;
    a.s = t;
}
__device__ __forceinline__ void kmac(KS& a, float x, float y) {
    float p = x * y;
    float e = fmaf(x, y, -p);
    kadd(a, p);
    a.c += e;
}
__device__ __forceinline__ float kval(const KS& a) { return a.s + a.c; }

__device__ __forceinline__ float blockSum128(float v, float* s4) {
    #pragma unroll
    for (int o = 16; o; o >>= 1) v += __shfl_down_sync(0xffffffffu, v, o);
    int lane = threadIdx.x & 31, wid = threadIdx.x >> 5;
    __syncthreads();
    if (lane == 0) s4[wid] = v;
    __syncthreads();
    return (s4[0] + s4[1]) + (s4[2] + s4[3]);
}

// ---------------- 1) performer feature maps (4 t per block, t-pairs packed) ----------------
template<int IS_Q>
__global__ void phi_kernel(const float* __restrict__ x, const float* __restrict__ proj)
{
    int t0 = blockIdx.x*4, h = blockIdx.y, tid = threadIdx.x; // 128 threads
    __shared__ float xs[4][ND];
    __shared__ float smax[4][4];
    for (int e = tid; e < 4*ND; e += 128) {
        int j = e >> 6, u = e & 63;
        xs[j][u] = x[((size_t)(h*NT + t0 + j))*ND + u] * DATA_NORM;
    }
    __syncthreads();

    KS2 dk01, dk23; kinit2(dk01, 0ULL); kinit2(dk23, 0ULL);
    #pragma unroll 8
    for (int u = 0; u < ND; u++) {
        ull a = F2(xs[0][u], xs[1][u]);
        ull b = F2(xs[2][u], xs[3][u]);
        kmac2(dk01, a, a);
        kmac2(dk23, b, b);
    }
    float dg[4];
    { float q0, q1;
      kval2(dk01, q0, q1); dg[0] = 0.5f*q0; dg[1] = 0.5f*q1;
      kval2(dk23, q0, q1); dg[2] = 0.5f*q0; dg[3] = 0.5f*q1; }

    float xpv[3][4];
    float lmax[4] = {-1e30f, -1e30f, -1e30f, -1e30f};

    {
        const float* p0 = proj + (size_t)tid*ND;
        const float* p1 = proj + (size_t)(tid + 128)*ND;
        KS2 a001, a023, a101, a123;
        kinit2(a001, 0ULL); kinit2(a023, 0ULL); kinit2(a101, 0ULL); kinit2(a123, 0ULL);
        #pragma unroll 4
        for (int u = 0; u < ND; u++) {
            ull x01 = F2(xs[0][u], xs[1][u]);
            ull x23 = F2(xs[2][u], xs[3][u]);
            ull w0 = DUP(p0[u]); ull w1 = DUP(p1[u]);
            kmac2(a001, w0, x01); kmac2(a023, w0, x23);
            kmac2(a101, w1, x01); kmac2(a123, w1, x23);
        }
        kval2(a001, xpv[0][0], xpv[0][1]); kval2(a023, xpv[0][2], xpv[0][3]);
        kval2(a101, xpv[1][0], xpv[1][1]); kval2(a123, xpv[1][2], xpv[1][3]);
        #pragma unroll
        for (int j = 0; j < 4; j++)
            lmax[j] = fmaxf(xpv[0][j], xpv[1][j]);
    }
    int m2 = tid + 256;
    if (m2 < NM) {
        const float* p2 = proj + (size_t)m2*ND;
        KS2 a201, a223; kinit2(a201, 0ULL); kinit2(a223, 0ULL);
        #pragma unroll 4
        for (int u = 0; u < ND; u++) {
            ull w2 = DUP(p2[u]);
            kmac2(a201, w2, F2(xs[0][u], xs[1][u]));
            kmac2(a223, w2, F2(xs[2][u], xs[3][u]));
        }
        kval2(a201, xpv[2][0], xpv[2][1]); kval2(a223, xpv[2][2], xpv[2][3]);
        #pragma unroll
        for (int j = 0; j < 4; j++)
            lmax[j] = fmaxf(lmax[j], xpv[2][j]);
    }

    #pragma unroll
    for (int j = 0; j < 4; j++) {
        float v = lmax[j];
        #pragma unroll
        for (int o = 16; o; o >>= 1) v = fmaxf(v, __shfl_down_sync(0xffffffffu, v, o));
        if ((tid & 31) == 0) smax[j][tid >> 5] = v;
    }
    __syncthreads();
    float gmax[4];
    #pragma unroll
    for (int j = 0; j < 4; j++)
        gmax[j] = fmaxf(fmaxf(smax[j][0], smax[j][1]), fmaxf(smax[j][2], smax[j][3]));

    if (IS_Q) {
        #pragma unroll
        for (int j = 0; j < 4; j++) {
            float* orow = g_pq + ((size_t)(h*NT + t0 + j))*NM;
            orow[tid]       = M_RS * (expf((xpv[0][j] - dg[j]) - gmax[j]) + 1e-6f);
            orow[tid + 128] = M_RS * (expf((xpv[1][j] - dg[j]) - gmax[j]) + 1e-6f);
            if (m2 < NM)
                orow[m2]    = M_RS * (expf((xpv[2][j] - dg[j]) - gmax[j]) + 1e-6f);
        }
    } else {
        #pragma unroll
        for (int j = 0; j < 4; j++) {
            float* orow = g_pk + ((size_t)(h*NT + t0 + j))*NM;
            orow[tid]       = xpv[0][j];
            orow[tid + 128] = xpv[1][j];
            if (m2 < NM) orow[m2] = xpv[2][j];
        }
        if (tid == 0) {
            #pragma unroll
            for (int j = 0; j < 4; j++) {
                g_krowmax[h*NT + t0 + j] = gmax[j];
                g_kdiag[h*NT + t0 + j]   = dg[j];
            }
        }
    }
}

__global__ void headmax_kernel() {
    int h = blockIdx.x, tid = threadIdx.x;
    __shared__ float sr[256];
    float m = -1e30f;
    for (int t = tid; t < NT; t += 256) m = fmaxf(m, g_krowmax[h*NT + t]);
    sr[tid] = m; __syncthreads();
    for (int s = 128; s; s >>= 1) { if (tid < s) sr[tid] = fmaxf(sr[tid], sr[tid+s]); __syncthreads(); }
    if (tid == 0) g_kheadmax[h] = sr[0];
}

__global__ void pk_finish_kernel() {
    int idx = blockIdx.x*256 + threadIdx.x;
    if (idx >= NH*NT*NM) return;
    int row = idx / NM;
    int h = row / NT;
    g_pk[idx] = M_RS * (expf((g_pk[idx] - g_kdiag[row]) - g_kheadmax[h]) + 1e-6f);
}

__global__ void pksum_kernel() {
    int h = blockIdx.x, m = threadIdx.x;
    if (m >= NM) return;
    KS s; kinit(s, 0.f);
    for (int t = 0; t < NT; t++) kadd(s, g_pk[((size_t)(h*NT + t))*NM + m]);
    g_pksum[h*NM + m] = kval(s);
}

// kv[h][m][d] = sum_t pk[h][t][m] * vfa[h][t][d]   (n-pairs packed)
__global__ void kv_kernel(const float* __restrict__ vfa) {
    int h = blockIdx.z;
    int m0 = blockIdx.x*16, n0 = blockIdx.y*16;
    int tx = threadIdx.x;   // 0..7
    int ty = threadIdx.y;   // 0..15
    int tid = ty*8 + tx;    // 128 threads
    __shared__ float As[32][16];
    __shared__ float Bs[32][16];
    KS2 acc; kinit2(acc, 0ULL);
    for (int k0 = 0; k0 < NT; k0 += 32) {
        #pragma unroll
        for (int e = tid; e < 512; e += 128) {
            int kk = e >> 4, j = e & 15;
            int m = m0 + j;
            As[kk][j] = (m < NM) ? g_pk[((size_t)(h*NT + k0 + kk))*NM + m] : 0.f;
            Bs[kk][j] = vfa[((size_t)(h*NT + k0 + kk))*NVH + n0 + j];
        }
        __syncthreads();
        #pragma unroll
        for (int kk = 0; kk < 32; kk++)
            kmac2(acc, DUP(As[kk][ty]), F2(Bs[kk][tx], Bs[kk][tx+8]));
        __syncthreads();
    }
    int m = m0 + ty;
    if (m < NM) {
        float r0, r1; kval2(acc, r0, r1);
        g_kv[((size_t)h*NM + m)*NVH + n0 + tx]     = r0;
        g_kv[((size_t)h*NM + m)*NVH + n0 + tx + 8] = r1;
    }
}

// t_perf = (pq @ kv) * z ;  z = 1/(pq . pksum + 1e-8)  (row-pairs packed)
__global__ void tperf_kernel() {
    int h = blockIdx.y, t0 = blockIdx.x*8, tid = threadIdx.x; // 192 threads
    __shared__ float pqs[8][NM];
    __shared__ float zs[8];
    for (int e = tid; e < 8*NM; e += 192) {
        int r = e / NM, m = e % NM;
        pqs[r][m] = g_pq[((size_t)(h*NT + t0 + r))*NM + m];
    }
    __syncthreads();
    if (tid < 8) {
        KS dn; kinit(dn, 0.f);
        for (int m = 0; m < NM; m++) kmac(dn, pqs[tid][m], g_pksum[h*NM + m]);
        zs[tid] = (float)(1.0 / ((double)kval(dn) + 1e-8));
    }
    KS2 acc2[4];
    #pragma unroll
    for (int j = 0; j < 4; j++) kinit2(acc2[j], 0ULL);
    for (int m = 0; m < NM; m++) {
        ull kv2 = DUP(g_kv[((size_t)h*NM + m)*NVH + tid]);
        #pragma unroll
        for (int j = 0; j < 4; j++)
            kmac2(acc2[j], F2(pqs[2*j][m], pqs[2*j+1][m]), kv2);
    }
    __syncthreads();
    #pragma unroll
    for (int j = 0; j < 4; j++) {
        float r0, r1; kval2(acc2[j], r0, r1);
        g_tperf[((size_t)(h*NT + t0 + 2*j))*NVH + tid]     = r0 * zs[2*j];
        g_tperf[((size_t)(h*NT + t0 + 2*j + 1))*NVH + tid] = r1 * zs[2*j+1];
    }
}

// ---------------- 2) encoder: Linear(192->128) + LN + exact GELU ----------------
__global__ void enc_kernel(const float* __restrict__ enc_w, const float* __restrict__ enc_b,
                           const float* __restrict__ ln_g, const float* __restrict__ ln_b)
{
    int h = blockIdx.y, t0 = blockIdx.x*8, tid = threadIdx.x; // 128 threads
    __shared__ float tps[8][NVH];
    __shared__ float s4[4];
    for (int e = tid; e < 8*NVH; e += 128) {
        int r = e / NVH, vv = e % NVH;
        tps[r][vv] = g_tperf[((size_t)(h*NT + t0 + r))*NVH + vv];
    }
    __syncthreads();
    KS2 acc2[4];
    #pragma unroll
    for (int j = 0; j < 4; j++) kinit2(acc2[j], DUP(enc_b[tid]));
    for (int vv = 0; vv < NVH; vv++) {
        ull w2 = DUP(enc_w[vv*ND2 + tid]);
        #pragma unroll
        for (int j = 0; j < 4; j++)
            kmac2(acc2[j], F2(tps[2*j][vv], tps[2*j+1][vv]), w2);
    }
    float av[8];
    #pragma unroll
    for (int j = 0; j < 4; j++) kval2(acc2[j], av[2*j], av[2*j+1]);

    float gg = ln_g[tid], bb = ln_b[tid];
    for (int r = 0; r < 8; r++) {
        float su = blockSum128(av[r], s4);
        float mu = su * (1.f/128.f);
        float d = av[r] - mu;
        float s2 = blockSum128(d*d, s4);
        float var = s2 * (1.f/128.f);
        float y = d * (float)(1.0 / sqrt((double)var + 1e-5)) * gg + bb;
        float ge = 0.5f*y*(1.f + erff(y*0.70710678118654752f));
        g_tenc[((size_t)(h*NT + t0 + r))*ND2 + tid] = ge;
    }
}

// ---------------- 3) decoder Linear(128->256) + channel split ----------------
__global__ void dec_kernel(const float* __restrict__ dec_w, const float* __restrict__ dec_b)
{
    int h = blockIdx.y, t0 = blockIdx.x*8, tid = threadIdx.x; // 256 threads
    __shared__ float tes[8][ND2];
    for (int e = tid; e < 8*ND2; e += 256) {
        int r = e >> 7, vv = e & 127;
        tes[r][vv] = g_tenc[((size_t)(h*NT + t0 + r))*ND2 + vv];
    }
    __syncthreads();
    KS2 acc2[4];
    #pragma unroll
    for (int j = 0; j < 4; j++) kinit2(acc2[j], DUP(dec_b[tid]));
    for (int vv = 0; vv < ND2; vv++) {
        ull w2 = DUP(dec_w[vv*256 + tid]);
        #pragma unroll
        for (int j = 0; j < 4; j++)
            kmac2(acc2[j], F2(tes[2*j][vv], tes[2*j+1][vv]), w2);
    }
    int g = tid >> 6, wc = tid & 63, c = h*4 + g;
    #pragma unroll
    for (int j = 0; j < 4; j++) {
        float r0, r1; kval2(acc2[j], r0, r1);
        g_xdec[((size_t)c*NT + (t0 + 2*j))*ND + wc]     = r0;
        g_xdec[((size_t)c*NT + (t0 + 2*j + 1))*ND + wc] = r1;
    }
}

// ---------------- 4) CNN stack (channel-pairs packed) ----------------
__global__ void conv1_kernel(const float* __restrict__ W, const float* __restrict__ B)
{
    int to = blockIdx.x, tid = threadIdx.x; // 256 threads
    int w = tid & 63, cosub = tid >> 6;
    __shared__ float in_s[NC4][3][66];
    __shared__ ull w_u[4][24][9];
    for (int e = tid; e < NC4*3*66; e += 256) {
        int ci = e / 198, rem = e % 198, dy = rem / 66, col = rem % 66;
        int r = 2*to + dy - 1, ws = col - 1;
        float vv = 0.f;
        if (r >= 0 && r < NT && ws >= 0 && ws < ND) vv = g_xdec[((size_t)ci*NT + r)*ND + ws];
        in_s[ci][dy][col] = vv;
    }
    KS2 acc2[6];
    #pragma unroll
    for (int i = 0; i < 6; i++)
        kinit2(acc2[i], F2(B[cosub + 4*i], B[cosub + 4*i + 24]));
    for (int cc = 0; cc < 12; cc++) {
        __syncthreads();
        for (int e = tid; e < 4*24*9; e += 256) {
            int cis = e / 216, rem = e % 216, co = rem / 9, kk = rem % 9;
            int cin = cc*4 + cis;
            w_u[cis][co][kk] = F2(W[((size_t)co*NC4 + cin)*9 + kk],
                                  W[((size_t)(co + 24)*NC4 + cin)*9 + kk]);
        }
        __syncthreads();
        #pragma unroll
        for (int cis = 0; cis < 4; cis++) {
            int ci = cc*4 + cis;
            ull d0 = DUP(in_s[ci][0][w]), d1 = DUP(in_s[ci][0][w+1]), d2 = DUP(in_s[ci][0][w+2]);
            ull d3 = DUP(in_s[ci][1][w]), d4 = DUP(in_s[ci][1][w+1]), d5 = DUP(in_s[ci][1][w+2]);
            ull d6 = DUP(in_s[ci][2][w]), d7 = DUP(in_s[ci][2][w+1]), d8 = DUP(in_s[ci][2][w+2]);
            #pragma unroll
            for (int i = 0; i < 6; i++) {
                const ull* wp = w_u[cis][cosub + 4*i];
                kmac2(acc2[i], d0, wp[0]); kmac2(acc2[i], d1, wp[1]); kmac2(acc2[i], d2, wp[2]);
                kmac2(acc2[i], d3, wp[3]); kmac2(acc2[i], d4, wp[4]); kmac2(acc2[i], d5, wp[5]);
                kmac2(acc2[i], d6, wp[6]); kmac2(acc2[i], d7, wp[7]); kmac2(acc2[i], d8, wp[8]);
            }
        }
    }
    #pragma unroll
    for (int i = 0; i < 6; i++) {
        float r0, r1; kval2(acc2[i], r0, r1);
        int co = cosub + 4*i;
        g_c1[((size_t)co*NTH + to)*ND + w]        = fmaxf(r0, 0.f);
        g_c1[((size_t)(co + 24)*NTH + to)*ND + w] = fmaxf(r1, 0.f);
    }
}

__global__ void conv2_kernel(const float* __restrict__ W, const float* __restrict__ B)
{
    int to = blockIdx.x, tid = threadIdx.x;
    int w = tid & 63, cosub = tid >> 6;
    __shared__ float in_s[NC4][3][66];
    __shared__ ull w_u[4][24][9];
    for (int e = tid; e < NC4*3*66; e += 256) {
        int ci = e / 198, rem = e % 198, dy = rem / 66, col = rem % 66;
        int r = to + dy - 1, ws = col - 1;
        float vv = 0.f;
        if (r >= 0 && r < NTH && ws >= 0 && ws < ND) vv = g_c1[((size_t)ci*NTH + r)*ND + ws];
        in_s[ci][dy][col] = vv;
    }
    KS2 acc2[6];
    #pragma unroll
    for (int i = 0; i < 6; i++)
        kinit2(acc2[i], F2(B[cosub + 4*i], B[cosub + 4*i + 24]));
    for (int cc = 0; cc < 12; cc++) {
        __syncthreads();
        for (int e = tid; e < 4*24*9; e += 256) {
            int cis = e / 216, rem = e % 216, co = rem / 9, kk = rem % 9;
            int cin = cc*4 + cis;
            w_u[cis][co][kk] = F2(W[((size_t)co*NC4 + cin)*9 + kk],
                                  W[((size_t)(co + 24)*NC4 + cin)*9 + kk]);
        }
        __syncthreads();
        #pragma unroll
        for (int cis = 0; cis < 4; cis++) {
            int ci = cc*4 + cis;
            ull d0 = DUP(in_s[ci][0][w]), d1 = DUP(in_s[ci][0][w+1]), d2 = DUP(in_s[ci][0][w+2]);
            ull d3 = DUP(in_s[ci][1][w]), d4 = DUP(in_s[ci][1][w+1]), d5 = DUP(in_s[ci][1][w+2]);
            ull d6 = DUP(in_s[ci][2][w]), d7 = DUP(in_s[ci][2][w+1]), d8 = DUP(in_s[ci][2][w+2]);
            #pragma unroll
            for (int i = 0; i < 6; i++) {
                const ull* wp = w_u[cis][cosub + 4*i];
                kmac2(acc2[i], d0, wp[0]); kmac2(acc2[i], d1, wp[1]); kmac2(acc2[i], d2, wp[2]);
                kmac2(acc2[i], d3, wp[3]); kmac2(acc2[i], d4, wp[4]); kmac2(acc2[i], d5, wp[5]);
                kmac2(acc2[i], d6, wp[6]); kmac2(acc2[i], d7, wp[7]); kmac2(acc2[i], d8, wp[8]);
            }
        }
    }
    #pragma unroll
    for (int i = 0; i < 6; i++) {
        float r0, r1; kval2(acc2[i], r0, r1);
        int co = cosub + 4*i;
        g_c2[((size_t)co*NTH + to)*ND + w]        = fmaxf(r0, 0.f);
        g_c2[((size_t)(co + 24)*NTH + to)*ND + w] = fmaxf(r1, 0.f);
    }
}

// conv3: nearest-upsample rows fused; output-channel pairs packed; 384 threads
__global__ void conv3_kernel(const float* __restrict__ W, const float* __restrict__ B)
{
    int to = blockIdx.x, tid = threadIdx.x; // 384 threads: w = tid&63, cop = tid>>6 (0..5)
    int w = tid & 63, cop = tid >> 6;
    __shared__ float in_s[NC4][3][66];
    __shared__ ull w_u[8][6][9];
    for (int e = tid; e < NC4*3*66; e += 384) {
        int ci = e / 198, rem = e % 198, dy = rem / 66, col = rem % 66;
        int r = to + dy - 1, ws = col - 1;
        float vv = 0.f;
        if (r >= 0 && r < NT && ws >= 0 && ws < ND) vv = g_c2[((size_t)ci*NTH + (r >> 1))*ND + ws];
        in_s[ci][dy][col] = vv;
    }
    KS2 acc; kinit2(acc, F2(B[cop], B[cop + 6]));
    for (int cc = 0; cc < 6; cc++) {
        __syncthreads();
        for (int e = tid; e < 8*6*9; e += 384) {
            int cis = e / 54, rem = e % 54, c = rem / 9, kk = rem % 9;
            int cin = cc*8 + cis;
            w_u[cis][c][kk] = F2(W[((size_t)c*NC4 + cin)*9 + kk],
                                 W[((size_t)(c + 6)*NC4 + cin)*9 + kk]);
        }
        __syncthreads();
        #pragma unroll
        for (int cis = 0; cis < 8; cis++) {
            int ci = cc*8 + cis;
            const ull* wp = w_u[cis][cop];
            kmac2(acc, DUP(in_s[ci][0][w]),   wp[0]);
            kmac2(acc, DUP(in_s[ci][0][w+1]), wp[1]);
            kmac2(acc, DUP(in_s[ci][0][w+2]), wp[2]);
            kmac2(acc, DUP(in_s[ci][1][w]),   wp[3]);
            kmac2(acc, DUP(in_s[ci][1][w+1]), wp[4]);
            kmac2(acc, DUP(in_s[ci][1][w+2]), wp[5]);
            kmac2(acc, DUP(in_s[ci][2][w]),   wp[6]);
            kmac2(acc, DUP(in_s[ci][2][w+1]), wp[7]);
            kmac2(acc, DUP(in_s[ci][2][w+2]), wp[8]);
        }
    }
    float r0, r1; kval2(acc, r0, r1);
    g_c3[((size_t)cop*NT + to)*ND + w]       = r0;
    g_c3[((size_t)(cop + 6)*NT + to)*ND + w] = r1;
}

// ---------------- 5-7) est softmax with XLA-bit-matched rounding -> top-k mask ----------------
// (UNCHANGED — mask-critical)
__global__ void mask_kernel()
{
    int t = blockIdx.x, h = blockIdx.y, lane = threadIdx.x; // 32 threads
    const float* row = g_c3 + ((size_t)h*NT + t)*ND;
    float v0 = row[lane], v1 = row[lane + 32];

    float mx = fmaxf(v0, v1);
    #pragma unroll
    for (int o = 16; o; o >>= 1) mx = fmaxf(mx, __shfl_xor_sync(0xffffffffu, mx, o));

    float e0 = (float)exp((double)(v0 - mx));
    float e1 = (float)exp((double)(v1 - mx));

    float s0 = e0, s1 = e1;
    #pragma unroll
    for (int o = 8; o; o >>= 1) {
        s0 += __shfl_down_sync(0xffffffffu, s0, o);
        s1 += __shfl_down_sync(0xffffffffu, s1, o);
    }
    s0 += s0;
    s1 += s1;
    float p0 = __shfl_sync(0xffffffffu, s0, 0);
    float p1 = __shfl_sync(0xffffffffu, s0, 16);
    float p2 = __shfl_sync(0xffffffffu, s1, 0);
    float p3 = __shfl_sync(0xffffffffu, s1, 16);
    float dsum = (p0 + p2) + (p1 + p3);

    float est0 = __fdiv_rn(e0, dsum);
    float est1 = __fdiv_rn(e1, dsum);

    float a1 = fmaxf(est0, est1), a2 = fminf(est0, est1);
    #pragma unroll
    for (int o = 16; o; o >>= 1) {
        float b1 = __shfl_xor_sync(0xffffffffu, a1, o);
        float b2 = __shfl_xor_sync(0xffffffffu, a2, o);
        if (b1 > a1) { a2 = fmaxf(a1, b2); a1 = b1; }
        else         { a2 = fmaxf(a2, b1); }
    }
    float thresh = a2;
    int b0 = (est0 >= thresh) ? 1 : 0;
    int b1i = (est1 >= thresh) ? 1 : 0;
    unsigned words[4];
    #pragma unroll
    for (int k2 = 0; k2 < 4; k2++) {
        int wsrc = 16*k2 + (lane >> 1);
        int bv = __shfl_sync(0xffffffffu, (k2 < 2) ? b0 : b1i, wsrc & 31);
        words[k2] = __ballot_sync(0xffffffffu, bv);
    }
    if (lane == 0) {
        unsigned* mp = g_maskbits + ((size_t)h*NT + t)*4;
        mp[0] = words[0]; mp[1] = words[1]; mp[2] = words[2]; mp[3] = words[3];
    }
}

// ---------------- 8) block-sparse masked attention ----------------
__global__ void attn_kernel(const float* __restrict__ q, const float* __restrict__ k,
                            const float* __restrict__ v, float* __restrict__ out)
{
    int t = blockIdx.x, h = blockIdx.y, tid = threadIdx.x; // 128 threads
    __shared__ float qs[ND];
    __shared__ int blk_list[128];
    __shared__ int s_nblk;
    __shared__ float sc[2048];
    __shared__ float s4[4];
    __shared__ unsigned mw[4];
    __shared__ int flags[128];
    __shared__ float part[128];

    if (tid < 4) mw[tid] = g_maskbits[((size_t)h*NT + t)*4 + tid];
    if (tid < ND) qs[tid] = q[((size_t)h*NT + t)*ND + tid];
    __syncthreads();
    flags[tid] = (mw[tid >> 5] >> (tid & 31)) & 1;
    __syncthreads();
    if (tid == 0) {
        int n = 0;
        for (int j = 0; j < 128; j++) if (flags[j]) blk_list[n++] = j;
        s_nblk = n;
    }
    __syncthreads();
    int nk = s_nblk * 16;

    float lmax = -1e30f;
    for (int idx = tid; idx < nk; idx += 128) {
        int ss = blk_list[idx >> 4]*16 + (idx & 15);
        const float4* kr = (const float4*)(k + ((size_t)h*NT + ss)*ND);
        float acc = 0.f;
        #pragma unroll
        for (int u = 0; u < 16; u++) {
            float4 k4 = kr[u];
            acc += k4.x*qs[4*u] + k4.y*qs[4*u+1] + k4.z*qs[4*u+2] + k4.w*qs[4*u+3];
        }
        float scv = acc * 0.125f;
        sc[idx] = scv;
        lmax = fmaxf(lmax, scv);
    }
    #pragma unroll
    for (int o = 16; o; o >>= 1) lmax = fmaxf(lmax, __shfl_down_sync(0xffffffffu, lmax, o));
    if ((tid & 31) == 0) s4[tid >> 5] = lmax;
    __syncthreads();
    float gmax = fmaxf(fmaxf(s4[0], s4[1]), fmaxf(s4[2], s4[3]));

    float lsum = 0.f;
    for (int idx = tid; idx < nk; idx += 128) {
        float p = expf(sc[idx] - gmax);
        sc[idx] = p;
        lsum += p;
    }
    #pragma unroll
    for (int o = 16; o; o >>= 1) lsum += __shfl_down_sync(0xffffffffu, lsum, o);
    __syncthreads();
    if ((tid & 31) == 0) s4[tid >> 5] = lsum;
    __syncthreads();
    float denom = (s4[0] + s4[1]) + (s4[2] + s4[3]);
    float rden = (float)(1.0 / (double)denom);

    int d = tid & 63, half = tid >> 6;
    float acc = 0.f;
    for (int idx = half; idx < nk; idx += 2) {
        int ss = blk_list[idx >> 4]*16 + (idx & 15);
        acc += sc[idx] * v[((size_t)h*NT + ss)*ND + d];
    }
    part[tid] = acc;
    __syncthreads();
    if (tid < 64)
        out[((size_t)h*NT + t)*ND + d] = (part[tid] + part[tid + 64]) * rden;
}

// ---------------- launch ----------------
extern "C" void kernel_launch(void* const* d_in, const int* in_sizes, int n_in,
                              void* d_out, int out_size)
{
    const float* q     = (const float*)d_in[0];
    const float* k     = (const float*)d_in[1];
    const float* v     = (const float*)d_in[2];
    const float* vfa   = (const float*)d_in[3];
    const float* proj  = (const float*)d_in[4];
    const float* enc_w = (const float*)d_in[5];
    const float* enc_b = (const float*)d_in[6];
    const float* ln_g  = (const float*)d_in[7];
    const float* ln_b  = (const float*)d_in[8];
    const float* dec_w = (const float*)d_in[9];
    const float* dec_b = (const float*)d_in[10];
    const float* c1w   = (const float*)d_in[11];
    const float* c1b   = (const float*)d_in[12];
    const float* c2w   = (const float*)d_in[13];
    const float* c2b   = (const float*)d_in[14];
    const float* c3w   = (const float*)d_in[15];
    const float* c3b   = (const float*)d_in[16];
    float* out = (float*)d_out;

    dim3 gTH(NT, NH);

    phi_kernel<1><<<dim3(NT/4, NH), 128>>>(q, proj);
    phi_kernel<0><<<dim3(NT/4, NH), 128>>>(k, proj);
    headmax_kernel<<<NH, 256>>>();
    pk_finish_kernel<<<(NH*NT*NM + 255)/256, 256>>>();
    pksum_kernel<<<NH, 288>>>();
    kv_kernel<<<dim3((NM + 15)/16, NVH/16, NH), dim3(8, 16)>>>(vfa);
    tperf_kernel<<<dim3(NT/8, NH), 192>>>();
    enc_kernel<<<dim3(NT/8, NH), 128>>>(enc_w, enc_b, ln_g, ln_b);
    dec_kernel<<<dim3(NT/8, NH), 256>>>(dec_w, dec_b);
    conv1_kernel<<<NTH, 256>>>(c1w, c1b);
    conv2_kernel<<<NTH, 256>>>(c2w, c2b);
    conv3_kernel<<<NT, 384>>>(c3w, c3b);
    mask_kernel<<<gTH, 32>>>();
    attn_kernel<<<gTH, 128>>>(q, k, v, out);
}

// round 12
// speedup vs baseline: 1.9296x; 1.0288x over previous
#include <cuda_runtime.h>
#include <math.h>

// ---------------- problem constants ----------------
#define NH 12      // heads
#define NT 2048    // sequence length
#define ND 64      // head dim
#define NM 266     // performer features
#define NVH 192    // performer value hidden (3D)
#define ND2 128    // 2*D
#define NC4 48     // 4*H conv channels
#define NTH 1024   // T/2

#define DATA_NORM 0.35355339059327373f   // 64^-0.25
#define M_RS      0.06131393394849658f   // 266^-0.5

typedef unsigned long long ull;

// ---------------- scratch (device globals; no allocs allowed) ----------------
__device__ float g_pq[NH*NT*NM];
__device__ float g_pk[NH*NT*NM];
__device__ float g_krowmax[NH*NT];
__device__ float g_kdiag[NH*NT];
__device__ float g_kheadmax[NH];
__device__ float g_kv[NH*NM*NVH];
__device__ float g_pksum[NH*NM];
__device__ float g_tperf[NH*NT*NVH];
__device__ float g_tenc[NH*NT*ND2];
__device__ float g_xdec[NC4*NT*ND];
__device__ float g_c1[NC4*NTH*ND];
__device__ float g_c2[NC4*NTH*ND];
__device__ float g_c3[NH*NT*ND];
__device__ unsigned g_maskbits[NH*NT*4];

// ---------------- packed f32x2 helpers (sm_103a) ----------------
__device__ __forceinline__ ull F2(float a, float b) {
    ull r; asm("mov.b64 %0,{%1,%2};" : "=l"(r) : "f"(a), "f"(b)); return r;
}
__device__ __forceinline__ ull DUP(float a) { return F2(a, a); }
__device__ __forceinline__ void UNF2(ull p, float& a, float& b) {
    asm("mov.b64 {%0,%1},%2;" : "=f"(a), "=f"(b) : "l"(p));
}
__device__ __forceinline__ ull ADD2(ull a, ull b) {
    ull r; asm("add.rn.f32x2 %0,%1,%2;" : "=l"(r) : "l"(a), "l"(b)); return r;
}
__device__ __forceinline__ ull MUL2(ull a, ull b) {
    ull r; asm("mul.rn.f32x2 %0,%1,%2;" : "=l"(r) : "l"(a), "l"(b)); return r;
}
__device__ __forceinline__ ull FMA2(ull a, ull b, ull c) {
    ull r; asm("fma.rn.f32x2 %0,%1,%2,%3;" : "=l"(r) : "l"(a), "l"(b), "l"(c)); return r;
}
// native packed subtract: FADD2 with operand-negate modifier -> 2 distinct
// 64-bit operands (rt=2) instead of the 3-operand FMA2 form (rt=3 via RF banking).
// IEEE: a-b == a+(-b) exactly -> bit-identical to the previous FMA2(b,-1,a).
__device__ __forceinline__ ull SUB2(ull a, ull b) {
    ull r; asm("sub.rn.f32x2 %0,%1,%2;" : "=l"(r) : "l"(a), "l"(b)); return r;
}
__device__ __forceinline__ ull LDS64(const float* p) { return *(const ull*)p; }
#define SGNM2  0x8000000080000000ULL

// packed compensated accumulator: two independent Kahan lanes with exact
// product-error folding. Convention: true sum ~= s - c.
struct KS2 { ull s, c; };
__device__ __forceinline__ void kinit2(KS2& a, ull v) { a.s = v; a.c = 0ULL; }
__device__ __forceinline__ void kmac2(KS2& a, ull x, ull y) {
    ull p  = MUL2(x, y);
    ull ep = FMA2(x, y, p ^ SGNM2);   // exact product error: xy - p
    ull yy = SUB2(p, a.c);            // apply pending correction
    ull t  = ADD2(a.s, yy);
    ull d  = SUB2(t, a.s);
    a.c    = SUB2(SUB2(d, yy), ep);   // lost low bits of yy, minus product error
    a.s    = t;
}
__device__ __forceinline__ void kval2(const KS2& a, float& r0, float& r1) {
    float s0, s1, c0, c1;
    UNF2(a.s, s0, s1); UNF2(a.c, c0, c1);
    r0 = s0 - c0; r1 = s1 - c1;
}

// ---------------- scalar compensated helpers (small paths) ----------------
struct KS { float s, c; };
__device__ __forceinline__ void kinit(KS& a, float v) { a.s = v; a.c = 0.f; }
__device__ __forceinline__ void kadd(KS& a, float v) {
    float t = a.s + v;
    if (fabsf(a.s) >= fabsf(v)) a.c += (a.s - t) + v;
    else                        a.c += (v - t) + a.s;
    a.s = t;
}
__device__ __forceinline__ void kmac(KS& a, float x, float y) {
    float p = x * y;
    float e = fmaf(x, y, -p);
    kadd(a, p);
    a.c += e;
}
__device__ __forceinline__ float kval(const KS& a) { return a.s + a.c; }

__device__ __forceinline__ float blockSum128(float v, float* s4) {
    #pragma unroll
    for (int o = 16; o; o >>= 1) v += __shfl_down_sync(0xffffffffu, v, o);
    int lane = threadIdx.x & 31, wid = threadIdx.x >> 5;
    __syncthreads();
    if (lane == 0) s4[wid] = v;
    __syncthreads();
    return (s4[0] + s4[1]) + (s4[2] + s4[3]);
}

// ---------------- 1) performer feature maps (4 t per block, t-pairs packed) ----------------
template<int IS_Q>
__global__ void phi_kernel(const float* __restrict__ x, const float* __restrict__ proj)
{
    int t0 = blockIdx.x*4, h = blockIdx.y, tid = threadIdx.x; // 128 threads
    __shared__ float xs[4][ND];
    __shared__ ull xs01_u[ND], xs23_u[ND];
    __shared__ float smax[4][4];
    for (int e = tid; e < 4*ND; e += 128) {
        int j = e >> 6, u = e & 63;
        xs[j][u] = x[((size_t)(h*NT + t0 + j))*ND + u] * DATA_NORM;
    }
    __syncthreads();
    if (tid < 64)       xs01_u[tid]      = F2(xs[0][tid], xs[1][tid]);
    else                xs23_u[tid - 64] = F2(xs[2][tid - 64], xs[3][tid - 64]);
    __syncthreads();

    KS2 dk01, dk23; kinit2(dk01, 0ULL); kinit2(dk23, 0ULL);
    #pragma unroll 8
    for (int u = 0; u < ND; u++) {
        ull a = xs01_u[u];
        ull b = xs23_u[u];
        kmac2(dk01, a, a);
        kmac2(dk23, b, b);
    }
    float dg[4];
    { float q0, q1;
      kval2(dk01, q0, q1); dg[0] = 0.5f*q0; dg[1] = 0.5f*q1;
      kval2(dk23, q0, q1); dg[2] = 0.5f*q0; dg[3] = 0.5f*q1; }

    float xpv[3][4];
    float lmax[4] = {-1e30f, -1e30f, -1e30f, -1e30f};

    {
        const float* p0 = proj + (size_t)tid*ND;
        const float* p1 = proj + (size_t)(tid + 128)*ND;
        KS2 a001, a023, a101, a123;
        kinit2(a001, 0ULL); kinit2(a023, 0ULL); kinit2(a101, 0ULL); kinit2(a123, 0ULL);
        #pragma unroll 4
        for (int u = 0; u < ND; u++) {
            ull x01 = xs01_u[u];
            ull x23 = xs23_u[u];
            ull w0 = DUP(p0[u]); ull w1 = DUP(p1[u]);
            kmac2(a001, w0, x01); kmac2(a023, w0, x23);
            kmac2(a101, w1, x01); kmac2(a123, w1, x23);
        }
        kval2(a001, xpv[0][0], xpv[0][1]); kval2(a023, xpv[0][2], xpv[0][3]);
        kval2(a101, xpv[1][0], xpv[1][1]); kval2(a123, xpv[1][2], xpv[1][3]);
        #pragma unroll
        for (int j = 0; j < 4; j++)
            lmax[j] = fmaxf(xpv[0][j], xpv[1][j]);
    }
    int m2 = tid + 256;
    if (m2 < NM) {
        const float* p2 = proj + (size_t)m2*ND;
        KS2 a201, a223; kinit2(a201, 0ULL); kinit2(a223, 0ULL);
        #pragma unroll 4
        for (int u = 0; u < ND; u++) {
            ull w2 = DUP(p2[u]);
            kmac2(a201, w2, xs01_u[u]);
            kmac2(a223, w2, xs23_u[u]);
        }
        kval2(a201, xpv[2][0], xpv[2][1]); kval2(a223, xpv[2][2], xpv[2][3]);
        #pragma unroll
        for (int j = 0; j < 4; j++)
            lmax[j] = fmaxf(lmax[j], xpv[2][j]);
    }

    #pragma unroll
    for (int j = 0; j < 4; j++) {
        float v = lmax[j];
        #pragma unroll
        for (int o = 16; o; o >>= 1) v = fmaxf(v, __shfl_down_sync(0xffffffffu, v, o));
        if ((tid & 31) == 0) smax[j][tid >> 5] = v;
    }
    __syncthreads();
    float gmax[4];
    #pragma unroll
    for (int j = 0; j < 4; j++)
        gmax[j] = fmaxf(fmaxf(smax[j][0], smax[j][1]), fmaxf(smax[j][2], smax[j][3]));

    if (IS_Q) {
        #pragma unroll
        for (int j = 0; j < 4; j++) {
            float* orow = g_pq + ((size_t)(h*NT + t0 + j))*NM;
            orow[tid]       = M_RS * (expf((xpv[0][j] - dg[j]) - gmax[j]) + 1e-6f);
            orow[tid + 128] = M_RS * (expf((xpv[1][j] - dg[j]) - gmax[j]) + 1e-6f);
            if (m2 < NM)
                orow[m2]    = M_RS * (expf((xpv[2][j] - dg[j]) - gmax[j]) + 1e-6f);
        }
    } else {
        #pragma unroll
        for (int j = 0; j < 4; j++) {
            float* orow = g_pk + ((size_t)(h*NT + t0 + j))*NM;
            orow[tid]       = xpv[0][j];
            orow[tid + 128] = xpv[1][j];
            if (m2 < NM) orow[m2] = xpv[2][j];
        }
        if (tid == 0) {
            #pragma unroll
            for (int j = 0; j < 4; j++) {
                g_krowmax[h*NT + t0 + j] = gmax[j];
                g_kdiag[h*NT + t0 + j]   = dg[j];
            }
        }
    }
}

__global__ void headmax_kernel() {
    int h = blockIdx.x, tid = threadIdx.x;
    __shared__ float sr[256];
    float m = -1e30f;
    for (int t = tid; t < NT; t += 256) m = fmaxf(m, g_krowmax[h*NT + t]);
    sr[tid] = m; __syncthreads();
    for (int s = 128; s; s >>= 1) { if (tid < s) sr[tid] = fmaxf(sr[tid], sr[tid+s]); __syncthreads(); }
    if (tid == 0) g_kheadmax[h] = sr[0];
}

__global__ void pk_finish_kernel() {
    int idx = blockIdx.x*256 + threadIdx.x;
    if (idx >= NH*NT*NM) return;
    int row = idx / NM;
    int h = row / NT;
    g_pk[idx] = M_RS * (expf((g_pk[idx] - g_kdiag[row]) - g_kheadmax[h]) + 1e-6f);
}

__global__ void pksum_kernel() {
    int h = blockIdx.x, m = threadIdx.x;
    if (m >= NM) return;
    KS s; kinit(s, 0.f);
    for (int t = 0; t < NT; t++) kadd(s, g_pk[((size_t)(h*NT + t))*NM + m]);
    g_pksum[h*NM + m] = kval(s);
}

// kv[h][m][d] = sum_t pk[h][t][m] * vfa[h][t][d]   (n-pairs packed, Bs pre-packed)
__global__ void kv_kernel(const float* __restrict__ vfa) {
    int h = blockIdx.z;
    int m0 = blockIdx.x*16, n0 = blockIdx.y*16;
    int tx = threadIdx.x;   // 0..7
    int ty = threadIdx.y;   // 0..15
    int tid = ty*8 + tx;    // 128 threads
    __shared__ float As[32][16];
    __shared__ ull Bs_u[32][8];
    KS2 acc; kinit2(acc, 0ULL);
    for (int k0 = 0; k0 < NT; k0 += 32) {
        #pragma unroll
        for (int e = tid; e < 512; e += 128) {
            int kk = e >> 4, j = e & 15;
            int m = m0 + j;
            As[kk][j] = (m < NM) ? g_pk[((size_t)(h*NT + k0 + kk))*NM + m] : 0.f;
        }
        #pragma unroll
        for (int e = tid; e < 256; e += 128) {
            int kk = e >> 3, j8 = e & 7;
            const float* vr = vfa + ((size_t)(h*NT + k0 + kk))*NVH + n0;
            Bs_u[kk][j8] = F2(vr[j8], vr[j8 + 8]);
        }
        __syncthreads();
        #pragma unroll
        for (int kk = 0; kk < 32; kk++)
            kmac2(acc, DUP(As[kk][ty]), Bs_u[kk][tx]);
        __syncthreads();
    }
    int m = m0 + ty;
    if (m < NM) {
        float r0, r1; kval2(acc, r0, r1);
        g_kv[((size_t)h*NM + m)*NVH + n0 + tx]     = r0;
        g_kv[((size_t)h*NM + m)*NVH + n0 + tx + 8] = r1;
    }
}

// t_perf = (pq @ kv) * z ; 16 rows/block, row-pairs pre-packed in shared
__global__ void tperf_kernel() {
    int h = blockIdx.y, t0 = blockIdx.x*16, tid = threadIdx.x; // 192 threads
    __shared__ __align__(8) float pqs_f[NM][18];   // [m][row], padded
    __shared__ float zs[16];
    for (int e = tid; e < 16*NM; e += 192) {
        int r = e / NM, m = e % NM;
        pqs_f[m][r] = g_pq[((size_t)(h*NT + t0 + r))*NM + m];
    }
    __syncthreads();
    if (tid < 16) {
        KS dn; kinit(dn, 0.f);
        for (int m = 0; m < NM; m++) kmac(dn, pqs_f[m][tid], g_pksum[h*NM + m]);
        zs[tid] = (float)(1.0 / ((double)kval(dn) + 1e-8));
    }
    KS2 acc2[8];
    #pragma unroll
    for (int j = 0; j < 8; j++) kinit2(acc2[j], 0ULL);
    for (int m = 0; m < NM; m++) {
        ull kv2 = DUP(g_kv[((size_t)h*NM + m)*NVH + tid]);
        const float* pr = pqs_f[m];
        #pragma unroll
        for (int j = 0; j < 8; j++)
            kmac2(acc2[j], LDS64(pr + 2*j), kv2);
    }
    __syncthreads();
    #pragma unroll
    for (int j = 0; j < 8; j++) {
        float r0, r1; kval2(acc2[j], r0, r1);
        g_tperf[((size_t)(h*NT + t0 + 2*j))*NVH + tid]     = r0 * zs[2*j];
        g_tperf[((size_t)(h*NT + t0 + 2*j + 1))*NVH + tid] = r1 * zs[2*j+1];
    }
}

// ---------------- 2) encoder: Linear(192->128) + LN + exact GELU, 16 rows ----------------
__global__ void enc_kernel(const float* __restrict__ enc_w, const float* __restrict__ enc_b,
                           const float* __restrict__ ln_g, const float* __restrict__ ln_b)
{
    int h = blockIdx.y, t0 = blockIdx.x*16, tid = threadIdx.x; // 128 threads
    __shared__ __align__(8) float tps_f[NVH][18];
    __shared__ float s4[4];
    for (int e = tid; e < 16*NVH; e += 128) {
        int r = e / NVH, vv = e % NVH;
        tps_f[vv][r] = g_tperf[((size_t)(h*NT + t0 + r))*NVH + vv];
    }
    __syncthreads();
    KS2 acc2[8];
    #pragma unroll
    for (int j = 0; j < 8; j++) kinit2(acc2[j], DUP(enc_b[tid]));
    for (int vv = 0; vv < NVH; vv++) {
        ull w2 = DUP(enc_w[vv*ND2 + tid]);
        const float* pr = tps_f[vv];
        #pragma unroll
        for (int j = 0; j < 8; j++)
            kmac2(acc2[j], LDS64(pr + 2*j), w2);
    }
    float av[16];
    #pragma unroll
    for (int j = 0; j < 8; j++) kval2(acc2[j], av[2*j], av[2*j+1]);

    float gg = ln_g[tid], bb = ln_b[tid];
    for (int r = 0; r < 16; r++) {
        float su = blockSum128(av[r], s4);
        float mu = su * (1.f/128.f);
        float d = av[r] - mu;
        float s2 = blockSum128(d*d, s4);
        float var = s2 * (1.f/128.f);
        float y = d * (float)(1.0 / sqrt((double)var + 1e-5)) * gg + bb;
        float ge = 0.5f*y*(1.f + erff(y*0.70710678118654752f));
        g_tenc[((size_t)(h*NT + t0 + r))*ND2 + tid] = ge;
    }
}

// ---------------- 3) decoder Linear(128->256) + channel split, 16 rows ----------------
__global__ void dec_kernel(const float* __restrict__ dec_w, const float* __restrict__ dec_b)
{
    int h = blockIdx.y, t0 = blockIdx.x*16, tid = threadIdx.x; // 256 threads
    __shared__ __align__(8) float tes_f[ND2][18];
    for (int e = tid; e < 16*ND2; e += 256) {
        int r = e >> 7, vv = e & 127;
        tes_f[vv][r] = g_tenc[((size_t)(h*NT + t0 + r))*ND2 + vv];
    }
    __syncthreads();
    KS2 acc2[8];
    #pragma unroll
    for (int j = 0; j < 8; j++) kinit2(acc2[j], DUP(dec_b[tid]));
    for (int vv = 0; vv < ND2; vv++) {
        ull w2 = DUP(dec_w[vv*256 + tid]);
        const float* pr = tes_f[vv];
        #pragma unroll
        for (int j = 0; j < 8; j++)
            kmac2(acc2[j], LDS64(pr + 2*j), w2);
    }
    int g = tid >> 6, wc = tid & 63, c = h*4 + g;
    #pragma unroll
    for (int j = 0; j < 8; j++) {
        float r0, r1; kval2(acc2[j], r0, r1);
        g_xdec[((size_t)c*NT + (t0 + 2*j))*ND + wc]     = r0;
        g_xdec[((size_t)c*NT + (t0 + 2*j + 1))*ND + wc] = r1;
    }
}

// ---------------- 4) CNN stack (channel-pairs packed) ----------------
__global__ void conv1_kernel(const float* __restrict__ W, const float* __restrict__ B)
{
    int to = blockIdx.x, tid = threadIdx.x; // 256 threads
    int w = tid & 63, cosub = tid >> 6;
    __shared__ float in_s[NC4][3][66];
    __shared__ ull w_u[4][24][9];
    for (int e = tid; e < NC4*3*66; e += 256) {
        int ci = e / 198, rem = e % 198, dy = rem / 66, col = rem % 66;
        int r = 2*to + dy - 1, ws = col - 1;
        float vv = 0.f;
        if (r >= 0 && r < NT && ws >= 0 && ws < ND) vv = g_xdec[((size_t)ci*NT + r)*ND + ws];
        in_s[ci][dy][col] = vv;
    }
    KS2 acc2[6];
    #pragma unroll
    for (int i = 0; i < 6; i++)
        kinit2(acc2[i], F2(B[cosub + 4*i], B[cosub + 4*i + 24]));
    for (int cc = 0; cc < 12; cc++) {
        __syncthreads();
        for (int e = tid; e < 4*24*9; e += 256) {
            int cis = e / 216, rem = e % 216, co = rem / 9, kk = rem % 9;
            int cin = cc*4 + cis;
            w_u[cis][co][kk] = F2(W[((size_t)co*NC4 + cin)*9 + kk],
                                  W[((size_t)(co + 24)*NC4 + cin)*9 + kk]);
        }
        __syncthreads();
        #pragma unroll
        for (int cis = 0; cis < 4; cis++) {
            int ci = cc*4 + cis;
            ull d0 = DUP(in_s[ci][0][w]), d1 = DUP(in_s[ci][0][w+1]), d2 = DUP(in_s[ci][0][w+2]);
            ull d3 = DUP(in_s[ci][1][w]), d4 = DUP(in_s[ci][1][w+1]), d5 = DUP(in_s[ci][1][w+2]);
            ull d6 = DUP(in_s[ci][2][w]), d7 = DUP(in_s[ci][2][w+1]), d8 = DUP(in_s[ci][2][w+2]);
            #pragma unroll
            for (int i = 0; i < 6; i++) {
                const ull* wp = w_u[cis][cosub + 4*i];
                kmac2(acc2[i], d0, wp[0]); kmac2(acc2[i], d1, wp[1]); kmac2(acc2[i], d2, wp[2]);
                kmac2(acc2[i], d3, wp[3]); kmac2(acc2[i], d4, wp[4]); kmac2(acc2[i], d5, wp[5]);
                kmac2(acc2[i], d6, wp[6]); kmac2(acc2[i], d7, wp[7]); kmac2(acc2[i], d8, wp[8]);
            }
        }
    }
    #pragma unroll
    for (int i = 0; i < 6; i++) {
        float r0, r1; kval2(acc2[i], r0, r1);
        int co = cosub + 4*i;
        g_c1[((size_t)co*NTH + to)*ND + w]        = fmaxf(r0, 0.f);
        g_c1[((size_t)(co + 24)*NTH + to)*ND + w] = fmaxf(r1, 0.f);
    }
}

__global__ void conv2_kernel(const float* __restrict__ W, const float* __restrict__ B)
{
    int to = blockIdx.x, tid = threadIdx.x;
    int w = tid & 63, cosub = tid >> 6;
    __shared__ float in_s[NC4][3][66];
    __shared__ ull w_u[4][24][9];
    for (int e = tid; e < NC4*3*66; e += 256) {
        int ci = e / 198, rem = e % 198, dy = rem / 66, col = rem % 66;
        int r = to + dy - 1, ws = col - 1;
        float vv = 0.f;
        if (r >= 0 && r < NTH && ws >= 0 && ws < ND) vv = g_c1[((size_t)ci*NTH + r)*ND + ws];
        in_s[ci][dy][col] = vv;
    }
    KS2 acc2[6];
    #pragma unroll
    for (int i = 0; i < 6; i++)
        kinit2(acc2[i], F2(B[cosub + 4*i], B[cosub + 4*i + 24]));
    for (int cc = 0; cc < 12; cc++) {
        __syncthreads();
        for (int e = tid; e < 4*24*9; e += 256) {
            int cis = e / 216, rem = e % 216, co = rem / 9, kk = rem % 9;
            int cin = cc*4 + cis;
            w_u[cis][co][kk] = F2(W[((size_t)co*NC4 + cin)*9 + kk],
                                  W[((size_t)(co + 24)*NC4 + cin)*9 + kk]);
        }
        __syncthreads();
        #pragma unroll
        for (int cis = 0; cis < 4; cis++) {
            int ci = cc*4 + cis;
            ull d0 = DUP(in_s[ci][0][w]), d1 = DUP(in_s[ci][0][w+1]), d2 = DUP(in_s[ci][0][w+2]);
            ull d3 = DUP(in_s[ci][1][w]), d4 = DUP(in_s[ci][1][w+1]), d5 = DUP(in_s[ci][1][w+2]);
            ull d6 = DUP(in_s[ci][2][w]), d7 = DUP(in_s[ci][2][w+1]), d8 = DUP(in_s[ci][2][w+2]);
            #pragma unroll
            for (int i = 0; i < 6; i++) {
                const ull* wp = w_u[cis][cosub + 4*i];
                kmac2(acc2[i], d0, wp[0]); kmac2(acc2[i], d1, wp[1]); kmac2(acc2[i], d2, wp[2]);
                kmac2(acc2[i], d3, wp[3]); kmac2(acc2[i], d4, wp[4]); kmac2(acc2[i], d5, wp[5]);
                kmac2(acc2[i], d6, wp[6]); kmac2(acc2[i], d7, wp[7]); kmac2(acc2[i], d8, wp[8]);
            }
        }
    }
    #pragma unroll
    for (int i = 0; i < 6; i++) {
        float r0, r1; kval2(acc2[i], r0, r1);
        int co = cosub + 4*i;
        g_c2[((size_t)co*NTH + to)*ND + w]        = fmaxf(r0, 0.f);
        g_c2[((size_t)(co + 24)*NTH + to)*ND + w] = fmaxf(r1, 0.f);
    }
}

// conv3: nearest-upsample rows fused; output-channel pairs packed; 384 threads
__global__ void conv3_kernel(const float* __restrict__ W, const float* __restrict__ B)
{
    int to = blockIdx.x, tid = threadIdx.x; // 384 threads: w = tid&63, cop = tid>>6 (0..5)
    int w = tid & 63, cop = tid >> 6;
    __shared__ float in_s[NC4][3][66];
    __shared__ ull w_u[8][6][9];
    for (int e = tid; e < NC4*3*66; e += 384) {
        int ci = e / 198, rem = e % 198, dy = rem / 66, col = rem % 66;
        int r = to + dy - 1, ws = col - 1;
        float vv = 0.f;
        if (r >= 0 && r < NT && ws >= 0 && ws < ND) vv = g_c2[((size_t)ci*NTH + (r >> 1))*ND + ws];
        in_s[ci][dy][col] = vv;
    }
    KS2 acc; kinit2(acc, F2(B[cop], B[cop + 6]));
    for (int cc = 0; cc < 6; cc++) {
        __syncthreads();
        for (int e = tid; e < 8*6*9; e += 384) {
            int cis = e / 54, rem = e % 54, c = rem / 9, kk = rem % 9;
            int cin = cc*8 + cis;
            w_u[cis][c][kk] = F2(W[((size_t)c*NC4 + cin)*9 + kk],
                                 W[((size_t)(c + 6)*NC4 + cin)*9 + kk]);
        }
        __syncthreads();
        #pragma unroll
        for (int cis = 0; cis < 8; cis++) {
            int ci = cc*8 + cis;
            const ull* wp = w_u[cis][cop];
            kmac2(acc, DUP(in_s[ci][0][w]),   wp[0]);
            kmac2(acc, DUP(in_s[ci][0][w+1]), wp[1]);
            kmac2(acc, DUP(in_s[ci][0][w+2]), wp[2]);
            kmac2(acc, DUP(in_s[ci][1][w]),   wp[3]);
            kmac2(acc, DUP(in_s[ci][1][w+1]), wp[4]);
            kmac2(acc, DUP(in_s[ci][1][w+2]), wp[5]);
            kmac2(acc, DUP(in_s[ci][2][w]),   wp[6]);
            kmac2(acc, DUP(in_s[ci][2][w+1]), wp[7]);
            kmac2(acc, DUP(in_s[ci][2][w+2]), wp[8]);
        }
    }
    float r0, r1; kval2(acc, r0, r1);
    g_c3[((size_t)cop*NT + to)*ND + w]       = r0;
    g_c3[((size_t)(cop + 6)*NT + to)*ND + w] = r1;
}

// ---------------- 5-7) est softmax with XLA-bit-matched rounding -> top-k mask ----------------
// (UNCHANGED — mask-critical)
__global__ void mask_kernel()
{
    int t = blockIdx.x, h = blockIdx.y, lane = threadIdx.x; // 32 threads
    const float* row = g_c3 + ((size_t)h*NT + t)*ND;
    float v0 = row[lane], v1 = row[lane + 32];

    float mx = fmaxf(v0, v1);
    #pragma unroll
    for (int o = 16; o; o >>= 1) mx = fmaxf(mx, __shfl_xor_sync(0xffffffffu, mx, o));

    float e0 = (float)exp((double)(v0 - mx));
    float e1 = (float)exp((double)(v1 - mx));

    float s0 = e0, s1 = e1;
    #pragma unroll
    for (int o = 8; o; o >>= 1) {
        s0 += __shfl_down_sync(0xffffffffu, s0, o);
        s1 += __shfl_down_sync(0xffffffffu, s1, o);
    }
    s0 += s0;
    s1 += s1;
    float p0 = __shfl_sync(0xffffffffu, s0, 0);
    float p1 = __shfl_sync(0xffffffffu, s0, 16);
    float p2 = __shfl_sync(0xffffffffu, s1, 0);
    float p3 = __shfl_sync(0xffffffffu, s1, 16);
    float dsum = (p0 + p2) + (p1 + p3);

    float est0 = __fdiv_rn(e0, dsum);
    float est1 = __fdiv_rn(e1, dsum);

    float a1 = fmaxf(est0, est1), a2 = fminf(est0, est1);
    #pragma unroll
    for (int o = 16; o; o >>= 1) {
        float b1 = __shfl_xor_sync(0xffffffffu, a1, o);
        float b2 = __shfl_xor_sync(0xffffffffu, a2, o);
        if (b1 > a1) { a2 = fmaxf(a1, b2); a1 = b1; }
        else         { a2 = fmaxf(a2, b1); }
    }
    float thresh = a2;
    int b0 = (est0 >= thresh) ? 1 : 0;
    int b1i = (est1 >= thresh) ? 1 : 0;
    unsigned words[4];
    #pragma unroll
    for (int k2 = 0; k2 < 4; k2++) {
        int wsrc = 16*k2 + (lane >> 1);
        int bv = __shfl_sync(0xffffffffu, (k2 < 2) ? b0 : b1i, wsrc & 31);
        words[k2] = __ballot_sync(0xffffffffu, bv);
    }
    if (lane == 0) {
        unsigned* mp = g_maskbits + ((size_t)h*NT + t)*4;
        mp[0] = words[0]; mp[1] = words[1]; mp[2] = words[2]; mp[3] = words[3];
    }
}

// ---------------- 8) block-sparse masked attention ----------------
__global__ void attn_kernel(const float* __restrict__ q, const float* __restrict__ k,
                            const float* __restrict__ v, float* __restrict__ out)
{
    int t = blockIdx.x, h = blockIdx.y, tid = threadIdx.x; // 128 threads
    __shared__ float qs[ND];
    __shared__ int blk_list[128];
    __shared__ int s_nblk;
    __shared__ float sc[2048];
    __shared__ float s4[4];
    __shared__ unsigned mw[4];
    __shared__ int flags[128];
    __shared__ float part[128];

    if (tid < 4) mw[tid] = g_maskbits[((size_t)h*NT + t)*4 + tid];
    if (tid < ND) qs[tid] = q[((size_t)h*NT + t)*ND + tid];
    __syncthreads();
    flags[tid] = (mw[tid >> 5] >> (tid & 31)) & 1;
    __syncthreads();
    if (tid == 0) {
        int n = 0;
        for (int j = 0; j < 128; j++) if (flags[j]) blk_list[n++] = j;
        s_nblk = n;
    }
    __syncthreads();
    int nk = s_nblk * 16;

    float lmax = -1e30f;
    for (int idx = tid; idx < nk; idx += 128) {
        int ss = blk_list[idx >> 4]*16 + (idx & 15);
        const float4* kr = (const float4*)(k + ((size_t)h*NT + ss)*ND);
        float acc = 0.f;
        #pragma unroll
        for (int u = 0; u < 16; u++) {
            float4 k4 = kr[u];
            acc += k4.x*qs[4*u] + k4.y*qs[4*u+1] + k4.z*qs[4*u+2] + k4.w*qs[4*u+3];
        }
        float scv = acc * 0.125f;
        sc[idx] = scv;
        lmax = fmaxf(lmax, scv);
    }
    #pragma unroll
    for (int o = 16; o; o >>= 1) lmax = fmaxf(lmax, __shfl_down_sync(0xffffffffu, lmax, o));
    if ((tid & 31) == 0) s4[tid >> 5] = lmax;
    __syncthreads();
    float gmax = fmaxf(fmaxf(s4[0], s4[1]), fmaxf(s4[2], s4[3]));

    float lsum = 0.f;
    for (int idx = tid; idx < nk; idx += 128) {
        float p = expf(sc[idx] - gmax);
        sc[idx] = p;
        lsum += p;
    }
    #pragma unroll
    for (int o = 16; o; o >>= 1) lsum += __shfl_down_sync(0xffffffffu, lsum, o);
    __syncthreads();
    if ((tid & 31) == 0) s4[tid >> 5] = lsum;
    __syncthreads();
    float denom = (s4[0] + s4[1]) + (s4[2] + s4[3]);
    float rden = (float)(1.0 / (double)denom);

    int d = tid & 63, half = tid >> 6;
    float acc = 0.f;
    for (int idx = half; idx < nk; idx += 2) {
        int ss = blk_list[idx >> 4]*16 + (idx & 15);
        acc += sc[idx] * v[((size_t)h*NT + ss)*ND + d];
    }
    part[tid] = acc;
    __syncthreads();
    if (tid < 64)
        out[((size_t)h*NT + t)*ND + d] = (part[tid] + part[tid + 64]) * rden;
}

// ---------------- launch ----------------
extern "C" void kernel_launch(void* const* d_in, const int* in_sizes, int n_in,
                              void* d_out, int out_size)
{
    const float* q     = (const float*)d_in[0];
    const float* k     = (const float*)d_in[1];
    const float* v     = (const float*)d_in[2];
    const float* vfa   = (const float*)d_in[3];
    const float* proj  = (const float*)d_in[4];
    const float* enc_w = (const float*)d_in[5];
    const float* enc_b = (const float*)d_in[6];
    const float* ln_g  = (const float*)d_in[7];
    const float* ln_b  = (const float*)d_in[8];
    const float* dec_w = (const float*)d_in[9];
    const float* dec_b = (const float*)d_in[10];
    const float* c1w   = (const float*)d_in[11];
    const float* c1b   = (const float*)d_in[12];
    const float* c2w   = (const float*)d_in[13];
    const float* c2b   = (const float*)d_in[14];
    const float* c3w   = (const float*)d_in[15];
    const float* c3b   = (const float*)d_in[16];
    float* out = (float*)d_out;

    dim3 gTH(NT, NH);

    phi_kernel<1><<<dim3(NT/4, NH), 128>>>(q, proj);
    phi_kernel<0><<<dim3(NT/4, NH), 128>>>(k, proj);
    headmax_kernel<<<NH, 256>>>();
    pk_finish_kernel<<<(NH*NT*NM + 255)/256, 256>>>();
    pksum_kernel<<<NH, 288>>>();
    kv_kernel<<<dim3((NM + 15)/16, NVH/16, NH), dim3(8, 16)>>>(vfa);
    tperf_kernel<<<dim3(NT/16, NH), 192>>>();
    enc_kernel<<<dim3(NT/16, NH), 128>>>(enc_w, enc_b, ln_g, ln_b);
    dec_kernel<<<dim3(NT/16, NH), 256>>>(dec_w, dec_b);
    conv1_kernel<<<NTH, 256>>>(c1w, c1b);
    conv2_kernel<<<NTH, 256>>>(c2w, c2b);
    conv3_kernel<<<NT, 384>>>(c3w, c3b);
    mask_kernel<<<gTH, 32>>>();
    attn_kernel<<<gTH, 128>>>(q, k, v, out);
}

// round 14
// speedup vs baseline: 2.5074x; 1.2995x over previous
#include <cuda_runtime.h>
#include <math.h>

// ---------------- problem constants ----------------
#define NH 12      // heads
#define NT 2048    // sequence length
#define ND 64      // head dim
#define NM 266     // performer features
#define NVH 192    // performer value hidden (3D)
#define ND2 128    // 2*D
#define NC4 48     // 4*H conv channels
#define NTH 1024   // T/2

#define DATA_NORM 0.35355339059327373f   // 64^-0.25
#define M_RS      0.06131393394849658f   // 266^-0.5

typedef unsigned long long ull;

// ---------------- scratch (device globals; no allocs allowed) ----------------
__device__ float g_pq[NH*NT*NM];
__device__ float g_pk[NH*NT*NM];
__device__ float g_krowmax[NH*NT];
__device__ float g_kdiag[NH*NT];
__device__ float g_kheadmax[NH];
__device__ float g_kv[NH*NM*NVH];
__device__ float g_kv2[NH*NM*ND2];
__device__ float g_pksum[NH*NM];
__device__ float g_tenc[NH*NT*ND2];
__device__ float g_xdec[NC4*NT*ND];
__device__ float g_c1[NC4*NTH*ND];
__device__ float g_c2[NC4*NTH*ND];
__device__ float g_c3[NH*NT*ND];
__device__ unsigned g_maskbits[NH*NT*4];

// ---------------- packed f32x2 helpers (sm_103a) ----------------
__device__ __forceinline__ ull F2(float a, float b) {
    ull r; asm("mov.b64 %0,{%1,%2};" : "=l"(r) : "f"(a), "f"(b)); return r;
}
__device__ __forceinline__ ull DUP(float a) { return F2(a, a); }
__device__ __forceinline__ void UNF2(ull p, float& a, float& b) {
    asm("mov.b64 {%0,%1},%2;" : "=f"(a), "=f"(b) : "l"(p));
}
__device__ __forceinline__ ull ADD2(ull a, ull b) {
    ull r; asm("add.rn.f32x2 %0,%1,%2;" : "=l"(r) : "l"(a), "l"(b)); return r;
}
__device__ __forceinline__ ull FMA2(ull a, ull b, ull c) {
    ull r; asm("fma.rn.f32x2 %0,%1,%2,%3;" : "=l"(r) : "l"(a), "l"(b), "l"(c)); return r;
}
__device__ __forceinline__ ull SUB2(ull a, ull b) {
    ull r; asm("sub.rn.f32x2 %0,%1,%2;" : "=l"(r) : "l"(a), "l"(b)); return r;
}
__device__ __forceinline__ ull LDS64(const float* p) { return *(const ull*)p; }

// packed Kahan-FMA accumulator: two independent lanes, 4 fma-pipe ops per
// 2 MACs. c holds the pending correction with convention true ~= s + c.
//   yy = fl(x*y + c)   (product folded into correction apply; its rounding
//                       ~0.29*eps*|xy| per step is the accepted noise)
//   t  = s + yy ;  c = yy - (t - s) ;  s = t      (Fast2Sum error capture)
struct KS2 { ull s, c; };
__device__ __forceinline__ void kinit2(KS2& a, ull v) { a.s = v; a.c = 0ULL; }
__device__ __forceinline__ void kmac2(KS2& a, ull x, ull y) {
    ull yy = FMA2(x, y, a.c);
    ull t  = ADD2(a.s, yy);
    ull d  = SUB2(t, a.s);
    a.c    = SUB2(yy, d);
    a.s    = t;
}
__device__ __forceinline__ void kval2(const KS2& a, float& r0, float& r1) {
    float s0, s1, c0, c1;
    UNF2(a.s, s0, s1); UNF2(a.c, c0, c1);
    r0 = s0 + c0; r1 = s1 + c1;
}

// ---------------- scalar compensated helpers (small paths) ----------------
struct KS { float s, c; };
__device__ __forceinline__ void kinit(KS& a, float v) { a.s = v; a.c = 0.f; }
__device__ __forceinline__ void kadd(KS& a, float v) {
    float t = a.s + v;
    if (fabsf(a.s) >= fabsf(v)) a.c += (a.s - t) + v;
    else                        a.c += (v - t) + a.s;
    a.s = t;
}
__device__ __forceinline__ void kmac(KS& a, float x, float y) {
    float p = x * y;
    float e = fmaf(x, y, -p);
    kadd(a, p);
    a.c += e;
}
__device__ __forceinline__ float kval(const KS& a) { return a.s + a.c; }

__device__ __forceinline__ float blockSum128(float v, float* s4) {
    #pragma unroll
    for (int o = 16; o; o >>= 1) v += __shfl_down_sync(0xffffffffu, v, o);
    int lane = threadIdx.x & 31, wid = threadIdx.x >> 5;
    __syncthreads();
    if (lane == 0) s4[wid] = v;
    __syncthreads();
    return (s4[0] + s4[1]) + (s4[2] + s4[3]);
}

// ---------------- 1) performer feature maps (4 t per block, t-pairs packed) ----------------
template<int IS_Q>
__global__ void phi_kernel(const float* __restrict__ x, const float* __restrict__ proj)
{
    int t0 = blockIdx.x*4, h = blockIdx.y, tid = threadIdx.x; // 128 threads
    __shared__ float xs[4][ND];
    __shared__ ull xs01_u[ND], xs23_u[ND];
    __shared__ float smax[4][4];
    for (int e = tid; e < 4*ND; e += 128) {
        int j = e >> 6, u = e & 63;
        xs[j][u] = x[((size_t)(h*NT + t0 + j))*ND + u] * DATA_NORM;
    }
    __syncthreads();
    if (tid < 64)       xs01_u[tid]      = F2(xs[0][tid], xs[1][tid]);
    else                xs23_u[tid - 64] = F2(xs[2][tid - 64], xs[3][tid - 64]);
    __syncthreads();

    KS2 dk01, dk23; kinit2(dk01, 0ULL); kinit2(dk23, 0ULL);
    #pragma unroll 8
    for (int u = 0; u < ND; u++) {
        ull a = xs01_u[u];
        ull b = xs23_u[u];
        kmac2(dk01, a, a);
        kmac2(dk23, b, b);
    }
    float dg[4];
    { float q0, q1;
      kval2(dk01, q0, q1); dg[0] = 0.5f*q0; dg[1] = 0.5f*q1;
      kval2(dk23, q0, q1); dg[2] = 0.5f*q0; dg[3] = 0.5f*q1; }

    float xpv[3][4];
    float lmax[4] = {-1e30f, -1e30f, -1e30f, -1e30f};

    {
        const float* p0 = proj + (size_t)tid*ND;
        const float* p1 = proj + (size_t)(tid + 128)*ND;
        KS2 a001, a023, a101, a123;
        kinit2(a001, 0ULL); kinit2(a023, 0ULL); kinit2(a101, 0ULL); kinit2(a123, 0ULL);
        #pragma unroll 4
        for (int u = 0; u < ND; u++) {
            ull x01 = xs01_u[u];
            ull x23 = xs23_u[u];
            ull w0 = DUP(p0[u]); ull w1 = DUP(p1[u]);
            kmac2(a001, w0, x01); kmac2(a023, w0, x23);
            kmac2(a101, w1, x01); kmac2(a123, w1, x23);
        }
        kval2(a001, xpv[0][0], xpv[0][1]); kval2(a023, xpv[0][2], xpv[0][3]);
        kval2(a101, xpv[1][0], xpv[1][1]); kval2(a123, xpv[1][2], xpv[1][3]);
        #pragma unroll
        for (int j = 0; j < 4; j++)
            lmax[j] = fmaxf(xpv[0][j], xpv[1][j]);
    }
    int m2 = tid + 256;
    if (m2 < NM) {
        const float* p2 = proj + (size_t)m2*ND;
        KS2 a201, a223; kinit2(a201, 0ULL); kinit2(a223, 0ULL);
        #pragma unroll 4
        for (int u = 0; u < ND; u++) {
            ull w2 = DUP(p2[u]);
            kmac2(a201, w2, xs01_u[u]);
            kmac2(a223, w2, xs23_u[u]);
        }
        kval2(a201, xpv[2][0], xpv[2][1]); kval2(a223, xpv[2][2], xpv[2][3]);
        #pragma unroll
        for (int j = 0; j < 4; j++)
            lmax[j] = fmaxf(lmax[j], xpv[2][j]);
    }

    #pragma unroll
    for (int j = 0; j < 4; j++) {
        float v = lmax[j];
        #pragma unroll
        for (int o = 16; o; o >>= 1) v = fmaxf(v, __shfl_down_sync(0xffffffffu, v, o));
        if ((tid & 31) == 0) smax[j][tid >> 5] = v;
    }
    __syncthreads();
    float gmax[4];
    #pragma unroll
    for (int j = 0; j < 4; j++)
        gmax[j] = fmaxf(fmaxf(smax[j][0], smax[j][1]), fmaxf(smax[j][2], smax[j][3]));

    if (IS_Q) {
        #pragma unroll
        for (int j = 0; j < 4; j++) {
            float* orow = g_pq + ((size_t)(h*NT + t0 + j))*NM;
            orow[tid]       = M_RS * (expf((xpv[0][j] - dg[j]) - gmax[j]) + 1e-6f);
            orow[tid + 128] = M_RS * (expf((xpv[1][j] - dg[j]) - gmax[j]) + 1e-6f);
            if (m2 < NM)
                orow[m2]    = M_RS * (expf((xpv[2][j] - dg[j]) - gmax[j]) + 1e-6f);
        }
    } else {
        #pragma unroll
        for (int j = 0; j < 4; j++) {
            float* orow = g_pk + ((size_t)(h*NT + t0 + j))*NM;
            orow[tid]       = xpv[0][j];
            orow[tid + 128] = xpv[1][j];
            if (m2 < NM) orow[m2] = xpv[2][j];
        }
        if (tid == 0) {
            #pragma unroll
            for (int j = 0; j < 4; j++) {
                g_krowmax[h*NT + t0 + j] = gmax[j];
                g_kdiag[h*NT + t0 + j]   = dg[j];
            }
        }
    }
}

__global__ void headmax_kernel() {
    int h = blockIdx.x, tid = threadIdx.x;
    __shared__ float sr[256];
    float m = -1e30f;
    for (int t = tid; t < NT; t += 256) m = fmaxf(m, g_krowmax[h*NT + t]);
    sr[tid] = m; __syncthreads();
    for (int s = 128; s; s >>= 1) { if (tid < s) sr[tid] = fmaxf(sr[tid], sr[tid+s]); __syncthreads(); }
    if (tid == 0) g_kheadmax[h] = sr[0];
}

__global__ void pk_finish_kernel() {
    int idx = blockIdx.x*256 + threadIdx.x;
    if (idx >= NH*NT*NM) return;
    int row = idx / NM;
    int h = row / NT;
    g_pk[idx] = M_RS * (expf((g_pk[idx] - g_kdiag[row]) - g_kheadmax[h]) + 1e-6f);
}

__global__ void pksum_kernel() {
    int h = blockIdx.x, m = threadIdx.x;
    if (m >= NM) return;
    KS s; kinit(s, 0.f);
    for (int t = 0; t < NT; t++) kadd(s, g_pk[((size_t)(h*NT + t))*NM + m]);
    g_pksum[h*NM + m] = kval(s);
}

// kv[h][m][d] = sum_t pk[h][t][m] * vfa[h][t][d]   (n-pairs packed, Bs pre-packed)
__global__ void kv_kernel(const float* __restrict__ vfa) {
    int h = blockIdx.z;
    int m0 = blockIdx.x*16, n0 = blockIdx.y*16;
    int tx = threadIdx.x;   // 0..7
    int ty = threadIdx.y;   // 0..15
    int tid = ty*8 + tx;    // 128 threads
    __shared__ float As[32][16];
    __shared__ ull Bs_u[32][8];
    KS2 acc; kinit2(acc, 0ULL);
    for (int k0 = 0; k0 < NT; k0 += 32) {
        #pragma unroll
        for (int e = tid; e < 512; e += 128) {
            int kk = e >> 4, j = e & 15;
            int m = m0 + j;
            As[kk][j] = (m < NM) ? g_pk[((size_t)(h*NT + k0 + kk))*NM + m] : 0.f;
        }
        #pragma unroll
        for (int e = tid; e < 256; e += 128) {
            int kk = e >> 3, j8 = e & 7;
            const float* vr = vfa + ((size_t)(h*NT + k0 + kk))*NVH + n0;
            Bs_u[kk][j8] = F2(vr[j8], vr[j8 + 8]);
        }
        __syncthreads();
        #pragma unroll
        for (int kk = 0; kk < 32; kk++)
            kmac2(acc, DUP(As[kk][ty]), Bs_u[kk][tx]);
        __syncthreads();
    }
    int m = m0 + ty;
    if (m < NM) {
        float r0, r1; kval2(acc, r0, r1);
        g_kv[((size_t)h*NM + m)*NVH + n0 + tx]     = r0;
        g_kv[((size_t)h*NM + m)*NVH + n0 + tx + 8] = r1;
    }
}

// kv2[h][m][d2] = sum_v kv[h][m][v] * enc_w[v][d2]   (tiny fused-path GEMM)
__global__ void kv2_kernel(const float* __restrict__ enc_w) {
    int m = blockIdx.x, h = blockIdx.y, tid = threadIdx.x; // 128 threads
    __shared__ float kvrow[NVH];
    for (int e = tid; e < NVH; e += 128)
        kvrow[e] = g_kv[((size_t)h*NM + m)*NVH + e];
    __syncthreads();
    KS a; kinit(a, 0.f);
    for (int v = 0; v < NVH; v++)
        kmac(a, kvrow[v], enc_w[v*ND2 + tid]);
    g_kv2[((size_t)h*NM + m)*ND2 + tid] = kval(a);
}

// ---------------- 2) FUSED t_perf + encoder ----------------
// t_enc = GELU(LN( z * (pq @ kv2) + enc_b ))  with kv2 = kv @ enc_w
// (algebraic fusion: ((pq@kv)*z) @ enc_w == z * (pq @ (kv@enc_w)); z is a row
//  scalar. Both paths compensated -> both ~exact; safe for the mask.)
__global__ void tperf_enc_kernel(const float* __restrict__ enc_b,
                                 const float* __restrict__ ln_g, const float* __restrict__ ln_b)
{
    int h = blockIdx.y, t0 = blockIdx.x*16, tid = threadIdx.x; // 128 threads
    __shared__ __align__(8) float pqs_f[NM][18];   // [m][row], padded
    __shared__ float zs[16];
    __shared__ float s4[4];
    for (int e = tid; e < 16*NM; e += 128) {
        int r = e / NM, m = e % NM;
        pqs_f[m][r] = g_pq[((size_t)(h*NT + t0 + r))*NM + m];
    }
    __syncthreads();
    if (tid < 16) {
        KS dn; kinit(dn, 0.f);
        for (int m = 0; m < NM; m++) kmac(dn, pqs_f[m][tid], g_pksum[h*NM + m]);
        zs[tid] = (float)(1.0 / ((double)kval(dn) + 1e-8));
    }
    KS2 acc2[8];
    #pragma unroll
    for (int j = 0; j < 8; j++) kinit2(acc2[j], 0ULL);
    __syncthreads();
    for (int m = 0; m < NM; m++) {
        ull kv2v = DUP(g_kv2[((size_t)h*NM + m)*ND2 + tid]);
        const float* pr = pqs_f[m];
        #pragma unroll
        for (int j = 0; j < 8; j++)
            kmac2(acc2[j], LDS64(pr + 2*j), kv2v);
    }
    float encb = enc_b[tid];
    float av[16];
    #pragma unroll
    for (int j = 0; j < 8; j++) {
        float g0, g1; kval2(acc2[j], g0, g1);
        av[2*j]   = fmaf(zs[2*j],   g0, encb);
        av[2*j+1] = fmaf(zs[2*j+1], g1, encb);
    }

    float gg = ln_g[tid], bb = ln_b[tid];
    for (int r = 0; r < 16; r++) {
        float su = blockSum128(av[r], s4);
        float mu = su * (1.f/128.f);
        float d = av[r] - mu;
        float s2 = blockSum128(d*d, s4);
        float var = s2 * (1.f/128.f);
        float y = d * (float)(1.0 / sqrt((double)var + 1e-5)) * gg + bb;
        float ge = 0.5f*y*(1.f + erff(y*0.70710678118654752f));
        g_tenc[((size_t)(h*NT + t0 + r))*ND2 + tid] = ge;
    }
}

// ---------------- 3) decoder Linear(128->256) + channel split, 16 rows ----------------
__global__ void dec_kernel(const float* __restrict__ dec_w, const float* __restrict__ dec_b)
{
    int h = blockIdx.y, t0 = blockIdx.x*16, tid = threadIdx.x; // 256 threads
    __shared__ __align__(8) float tes_f[ND2][18];
    for (int e = tid; e < 16*ND2; e += 256) {
        int r = e >> 7, vv = e & 127;
        tes_f[vv][r] = g_tenc[((size_t)(h*NT + t0 + r))*ND2 + vv];
    }
    __syncthreads();
    KS2 acc2[8];
    #pragma unroll
    for (int j = 0; j < 8; j++) kinit2(acc2[j], DUP(dec_b[tid]));
    for (int vv = 0; vv < ND2; vv++) {
        ull w2 = DUP(dec_w[vv*256 + tid]);
        const float* pr = tes_f[vv];
        #pragma unroll
        for (int j = 0; j < 8; j++)
            kmac2(acc2[j], LDS64(pr + 2*j), w2);
    }
    int g = tid >> 6, wc = tid & 63, c = h*4 + g;
    #pragma unroll
    for (int j = 0; j < 8; j++) {
        float r0, r1; kval2(acc2[j], r0, r1);
        g_xdec[((size_t)c*NT + (t0 + 2*j))*ND + wc]     = r0;
        g_xdec[((size_t)c*NT + (t0 + 2*j + 1))*ND + wc] = r1;
    }
}

// ---------------- 4) CNN stack (channel-pairs packed) ----------------
__global__ void conv1_kernel(const float* __restrict__ W, const float* __restrict__ B)
{
    int to = blockIdx.x, tid = threadIdx.x; // 256 threads
    int w = tid & 63, cosub = tid >> 6;
    __shared__ float in_s[NC4][3][66];
    __shared__ ull w_u[4][24][9];
    for (int e = tid; e < NC4*3*66; e += 256) {
        int ci = e / 198, rem = e % 198, dy = rem / 66, col = rem % 66;
        int r = 2*to + dy - 1, ws = col - 1;
        float vv = 0.f;
        if (r >= 0 && r < NT && ws >= 0 && ws < ND) vv = g_xdec[((size_t)ci*NT + r)*ND + ws];
        in_s[ci][dy][col] = vv;
    }
    KS2 acc2[6];
    #pragma unroll
    for (int i = 0; i < 6; i++)
        kinit2(acc2[i], F2(B[cosub + 4*i], B[cosub + 4*i + 24]));
    for (int cc = 0; cc < 12; cc++) {
        __syncthreads();
        for (int e = tid; e < 4*24*9; e += 256) {
            int cis = e / 216, rem = e % 216, co = rem / 9, kk = rem % 9;
            int cin = cc*4 + cis;
            w_u[cis][co][kk] = F2(W[((size_t)co*NC4 + cin)*9 + kk],
                                  W[((size_t)(co + 24)*NC4 + cin)*9 + kk]);
        }
        __syncthreads();
        #pragma unroll
        for (int cis = 0; cis < 4; cis++) {
            int ci = cc*4 + cis;
            ull d0 = DUP(in_s[ci][0][w]), d1 = DUP(in_s[ci][0][w+1]), d2 = DUP(in_s[ci][0][w+2]);
            ull d3 = DUP(in_s[ci][1][w]), d4 = DUP(in_s[ci][1][w+1]), d5 = DUP(in_s[ci][1][w+2]);
            ull d6 = DUP(in_s[ci][2][w]), d7 = DUP(in_s[ci][2][w+1]), d8 = DUP(in_s[ci][2][w+2]);
            #pragma unroll
            for (int i = 0; i < 6; i++) {
                const ull* wp = w_u[cis][cosub + 4*i];
                kmac2(acc2[i], d0, wp[0]); kmac2(acc2[i], d1, wp[1]); kmac2(acc2[i], d2, wp[2]);
                kmac2(acc2[i], d3, wp[3]); kmac2(acc2[i], d4, wp[4]); kmac2(acc2[i], d5, wp[5]);
                kmac2(acc2[i], d6, wp[6]); kmac2(acc2[i], d7, wp[7]); kmac2(acc2[i], d8, wp[8]);
            }
        }
    }
    #pragma unroll
    for (int i = 0; i < 6; i++) {
        float r0, r1; kval2(acc2[i], r0, r1);
        int co = cosub + 4*i;
        g_c1[((size_t)co*NTH + to)*ND + w]        = fmaxf(r0, 0.f);
        g_c1[((size_t)(co + 24)*NTH + to)*ND + w] = fmaxf(r1, 0.f);
    }
}

__global__ void conv2_kernel(const float* __restrict__ W, const float* __restrict__ B)
{
    int to = blockIdx.x, tid = threadIdx.x;
    int w = tid & 63, cosub = tid >> 6;
    __shared__ float in_s[NC4][3][66];
    __shared__ ull w_u[4][24][9];
    for (int e = tid; e < NC4*3*66; e += 256) {
        int ci = e / 198, rem = e % 198, dy = rem / 66, col = rem % 66;
        int r = to + dy - 1, ws = col - 1;
        float vv = 0.f;
        if (r >= 0 && r < NTH && ws >= 0 && ws < ND) vv = g_c1[((size_t)ci*NTH + r)*ND + ws];
        in_s[ci][dy][col] = vv;
    }
    KS2 acc2[6];
    #pragma unroll
    for (int i = 0; i < 6; i++)
        kinit2(acc2[i], F2(B[cosub + 4*i], B[cosub + 4*i + 24]));
    for (int cc = 0; cc < 12; cc++) {
        __syncthreads();
        for (int e = tid; e < 4*24*9; e += 256) {
            int cis = e / 216, rem = e % 216, co = rem / 9, kk = rem % 9;
            int cin = cc*4 + cis;
            w_u[cis][co][kk] = F2(W[((size_t)co*NC4 + cin)*9 + kk],
                                  W[((size_t)(co + 24)*NC4 + cin)*9 + kk]);
        }
        __syncthreads();
        #pragma unroll
        for (int cis = 0; cis < 4; cis++) {
            int ci = cc*4 + cis;
            ull d0 = DUP(in_s[ci][0][w]), d1 = DUP(in_s[ci][0][w+1]), d2 = DUP(in_s[ci][0][w+2]);
            ull d3 = DUP(in_s[ci][1][w]), d4 = DUP(in_s[ci][1][w+1]), d5 = DUP(in_s[ci][1][w+2]);
            ull d6 = DUP(in_s[ci][2][w]), d7 = DUP(in_s[ci][2][w+1]), d8 = DUP(in_s[ci][2][w+2]);
            #pragma unroll
            for (int i = 0; i < 6; i++) {
                const ull* wp = w_u[cis][cosub + 4*i];
                kmac2(acc2[i], d0, wp[0]); kmac2(acc2[i], d1, wp[1]); kmac2(acc2[i], d2, wp[2]);
                kmac2(acc2[i], d3, wp[3]); kmac2(acc2[i], d4, wp[4]); kmac2(acc2[i], d5, wp[5]);
                kmac2(acc2[i], d6, wp[6]); kmac2(acc2[i], d7, wp[7]); kmac2(acc2[i], d8, wp[8]);
            }
        }
    }
    #pragma unroll
    for (int i = 0; i < 6; i++) {
        float r0, r1; kval2(acc2[i], r0, r1);
        int co = cosub + 4*i;
        g_c2[((size_t)co*NTH + to)*ND + w]        = fmaxf(r0, 0.f);
        g_c2[((size_t)(co + 24)*NTH + to)*ND + w] = fmaxf(r1, 0.f);
    }
}

// conv3: nearest-upsample rows fused; output-channel pairs packed; 384 threads
__global__ void conv3_kernel(const float* __restrict__ W, const float* __restrict__ B)
{
    int to = blockIdx.x, tid = threadIdx.x; // 384 threads: w = tid&63, cop = tid>>6 (0..5)
    int w = tid & 63, cop = tid >> 6;
    __shared__ float in_s[NC4][3][66];
    __shared__ ull w_u[8][6][9];
    for (int e = tid; e < NC4*3*66; e += 384) {
        int ci = e / 198, rem = e % 198, dy = rem / 66, col = rem % 66;
        int r = to + dy - 1, ws = col - 1;
        float vv = 0.f;
        if (r >= 0 && r < NT && ws >= 0 && ws < ND) vv = g_c2[((size_t)ci*NTH + (r >> 1))*ND + ws];
        in_s[ci][dy][col] = vv;
    }
    KS2 acc; kinit2(acc, F2(B[cop], B[cop + 6]));
    for (int cc = 0; cc < 6; cc++) {
        __syncthreads();
        for (int e = tid; e < 8*6*9; e += 384) {
            int cis = e / 54, rem = e % 54, c = rem / 9, kk = rem % 9;
            int cin = cc*8 + cis;
            w_u[cis][c][kk] = F2(W[((size_t)c*NC4 + cin)*9 + kk],
                                 W[((size_t)(c + 6)*NC4 + cin)*9 + kk]);
        }
        __syncthreads();
        #pragma unroll
        for (int cis = 0; cis < 8; cis++) {
            int ci = cc*8 + cis;
            const ull* wp = w_u[cis][cop];
            kmac2(acc, DUP(in_s[ci][0][w]),   wp[0]);
            kmac2(acc, DUP(in_s[ci][0][w+1]), wp[1]);
            kmac2(acc, DUP(in_s[ci][0][w+2]), wp[2]);
            kmac2(acc, DUP(in_s[ci][1][w]),   wp[3]);
            kmac2(acc, DUP(in_s[ci][1][w+1]), wp[4]);
            kmac2(acc, DUP(in_s[ci][1][w+2]), wp[5]);
            kmac2(acc, DUP(in_s[ci][2][w]),   wp[6]);
            kmac2(acc, DUP(in_s[ci][2][w+1]), wp[7]);
            kmac2(acc, DUP(in_s[ci][2][w+2]), wp[8]);
        }
    }
    float r0, r1; kval2(acc, r0, r1);
    g_c3[((size_t)cop*NT + to)*ND + w]       = r0;
    g_c3[((size_t)(cop + 6)*NT + to)*ND + w] = r1;
}

// ---------------- 5-7) est softmax with XLA-bit-matched rounding -> top-k mask ----------------
// (UNCHANGED — mask-critical)
__global__ void mask_kernel()
{
    int t = blockIdx.x, h = blockIdx.y, lane = threadIdx.x; // 32 threads
    const float* row = g_c3 + ((size_t)h*NT + t)*ND;
    float v0 = row[lane], v1 = row[lane + 32];

    float mx = fmaxf(v0, v1);
    #pragma unroll
    for (int o = 16; o; o >>= 1) mx = fmaxf(mx, __shfl_xor_sync(0xffffffffu, mx, o));

    float e0 = (float)exp((double)(v0 - mx));
    float e1 = (float)exp((double)(v1 - mx));

    float s0 = e0, s1 = e1;
    #pragma unroll
    for (int o = 8; o; o >>= 1) {
        s0 += __shfl_down_sync(0xffffffffu, s0, o);
        s1 += __shfl_down_sync(0xffffffffu, s1, o);
    }
    s0 += s0;
    s1 += s1;
    float p0 = __shfl_sync(0xffffffffu, s0, 0);
    float p1 = __shfl_sync(0xffffffffu, s0, 16);
    float p2 = __shfl_sync(0xffffffffu, s1, 0);
    float p3 = __shfl_sync(0xffffffffu, s1, 16);
    float dsum = (p0 + p2) + (p1 + p3);

    float est0 = __fdiv_rn(e0, dsum);
    float est1 = __fdiv_rn(e1, dsum);

    float a1 = fmaxf(est0, est1), a2 = fminf(est0, est1);
    #pragma unroll
    for (int o = 16; o; o >>= 1) {
        float b1 = __shfl_xor_sync(0xffffffffu, a1, o);
        float b2 = __shfl_xor_sync(0xffffffffu, a2, o);
        if (b1 > a1) { a2 = fmaxf(a1, b2); a1 = b1; }
        else         { a2 = fmaxf(a2, b1); }
    }
    float thresh = a2;
    int b0 = (est0 >= thresh) ? 1 : 0;
    int b1i = (est1 >= thresh) ? 1 : 0;
    unsigned words[4];
    #pragma unroll
    for (int k2 = 0; k2 < 4; k2++) {
        int wsrc = 16*k2 + (lane >> 1);
        int bv = __shfl_sync(0xffffffffu, (k2 < 2) ? b0 : b1i, wsrc & 31);
        words[k2] = __ballot_sync(0xffffffffu, bv);
    }
    if (lane == 0) {
        unsigned* mp = g_maskbits + ((size_t)h*NT + t)*4;
        mp[0] = words[0]; mp[1] = words[1]; mp[2] = words[2]; mp[3] = words[3];
    }
}

// ---------------- 8) block-sparse masked attention ----------------
__global__ void attn_kernel(const float* __restrict__ q, const float* __restrict__ k,
                            const float* __restrict__ v, float* __restrict__ out)
{
    int t = blockIdx.x, h = blockIdx.y, tid = threadIdx.x; // 128 threads
    __shared__ float qs[ND];
    __shared__ int blk_list[128];
    __shared__ int s_nblk;
    __shared__ float sc[2048];
    __shared__ float s4[4];
    __shared__ unsigned mw[4];
    __shared__ int flags[128];
    __shared__ float part[128];

    if (tid < 4) mw[tid] = g_maskbits[((size_t)h*NT + t)*4 + tid];
    if (tid < ND) qs[tid] = q[((size_t)h*NT + t)*ND + tid];
    __syncthreads();
    flags[tid] = (mw[tid >> 5] >> (tid & 31)) & 1;
    __syncthreads();
    if (tid == 0) {
        int n = 0;
        for (int j = 0; j < 128; j++) if (flags[j]) blk_list[n++] = j;
        s_nblk = n;
    }
    __syncthreads();
    int nk = s_nblk * 16;

    float lmax = -1e30f;
    for (int idx = tid; idx < nk; idx += 128) {
        int ss = blk_list[idx >> 4]*16 + (idx & 15);
        const float4* kr = (const float4*)(k + ((size_t)h*NT + ss)*ND);
        float acc = 0.f;
        #pragma unroll
        for (int u = 0; u < 16; u++) {
            float4 k4 = kr[u];
            acc += k4.x*qs[4*u] + k4.y*qs[4*u+1] + k4.z*qs[4*u+2] + k4.w*qs[4*u+3];
        }
        float scv = acc * 0.125f;
        sc[idx] = scv;
        lmax = fmaxf(lmax, scv);
    }
    #pragma unroll
    for (int o = 16; o; o >>= 1) lmax = fmaxf(lmax, __shfl_down_sync(0xffffffffu, lmax, o));
    if ((tid & 31) == 0) s4[tid >> 5] = lmax;
    __syncthreads();
    float gmax = fmaxf(fmaxf(s4[0], s4[1]), fmaxf(s4[2], s4[3]));

    float lsum = 0.f;
    for (int idx = tid; idx < nk; idx += 128) {
        float p = expf(sc[idx] - gmax);
        sc[idx] = p;
        lsum += p;
    }
    #pragma unroll
    for (int o = 16; o; o >>= 1) lsum += __shfl_down_sync(0xffffffffu, lsum, o);
    __syncthreads();
    if ((tid & 31) == 0) s4[tid >> 5] = lsum;
    __syncthreads();
    float denom = (s4[0] + s4[1]) + (s4[2] + s4[3]);
    float rden = (float)(1.0 / (double)denom);

    int d = tid & 63, half = tid >> 6;
    float acc = 0.f;
    for (int idx = half; idx < nk; idx += 2) {
        int ss = blk_list[idx >> 4]*16 + (idx & 15);
        acc += sc[idx] * v[((size_t)h*NT + ss)*ND + d];
    }
    part[tid] = acc;
    __syncthreads();
    if (tid < 64)
        out[((size_t)h*NT + t)*ND + d] = (part[tid] + part[tid + 64]) * rden;
}

// ---------------- launch ----------------
extern "C" void kernel_launch(void* const* d_in, const int* in_sizes, int n_in,
                              void* d_out, int out_size)
{
    const float* q     = (const float*)d_in[0];
    const float* k     = (const float*)d_in[1];
    const float* v     = (const float*)d_in[2];
    const float* vfa   = (const float*)d_in[3];
    const float* proj  = (const float*)d_in[4];
    const float* enc_w = (const float*)d_in[5];
    const float* enc_b = (const float*)d_in[6];
    const float* ln_g  = (const float*)d_in[7];
    const float* ln_b  = (const float*)d_in[8];
    const float* dec_w = (const float*)d_in[9];
    const float* dec_b = (const float*)d_in[10];
    const float* c1w   = (const float*)d_in[11];
    const float* c1b   = (const float*)d_in[12];
    const float* c2w   = (const float*)d_in[13];
    const float* c2b   = (const float*)d_in[14];
    const float* c3w   = (const float*)d_in[15];
    const float* c3b   = (const float*)d_in[16];
    float* out = (float*)d_out;

    dim3 gTH(NT, NH);

    phi_kernel<1><<<dim3(NT/4, NH), 128>>>(q, proj);
    phi_kernel<0><<<dim3(NT/4, NH), 128>>>(k, proj);
    headmax_kernel<<<NH, 256>>>();
    pk_finish_kernel<<<(NH*NT*NM + 255)/256, 256>>>();
    pksum_kernel<<<NH, 288>>>();
    kv_kernel<<<dim3((NM + 15)/16, NVH/16, NH), dim3(8, 16)>>>(vfa);
    kv2_kernel<<<dim3(NM, NH), 128>>>(enc_w);
    tperf_enc_kernel<<<dim3(NT/16, NH), 128>>>(enc_b, ln_g, ln_b);
    dec_kernel<<<dim3(NT/16, NH), 256>>>(dec_w, dec_b);
    conv1_kernel<<<NTH, 256>>>(c1w, c1b);
    conv2_kernel<<<NTH, 256>>>(c2w, c2b);
    conv3_kernel<<<NT, 384>>>(c3w, c3b);
    mask_kernel<<<gTH, 32>>>();
    attn_kernel<<<gTH, 128>>>(q, k, v, out);
}

// round 15
// speedup vs baseline: 2.7090x; 1.0804x over previous
#include <cuda_runtime.h>
#include <math.h>

// ---------------- problem constants ----------------
#define NH 12      // heads
#define NT 2048    // sequence length
#define ND 64      // head dim
#define NM 266     // performer features
#define NVH 192    // performer value hidden (3D)
#define ND2 128    // 2*D
#define NC4 48     // 4*H conv channels
#define NTH 1024   // T/2

#define DATA_NORM 0.35355339059327373f   // 64^-0.25
#define M_RS      0.06131393394849658f   // 266^-0.5

typedef unsigned long long ull;

// ---------------- scratch (device globals; no allocs allowed) ----------------
__device__ float g_pq[NH*NT*NM];
__device__ float g_pk[NH*NT*NM];
__device__ float g_krowmax[NH*NT];
__device__ float g_kdiag[NH*NT];
__device__ float g_kheadmax[NH];
__device__ float g_kv[NH*NM*NVH];
__device__ float g_kv2[NH*NM*ND2];
__device__ float g_pksum[NH*NM];
__device__ float g_tenc[NH*NT*ND2];
__device__ float g_xdec[NC4*NT*ND];
__device__ float g_c1[NC4*NTH*ND];
__device__ float g_c2[NC4*NTH*ND];
__device__ float g_c3[NH*NT*ND];
__device__ unsigned g_maskbits[NH*NT*4];

// ---------------- packed f32x2 helpers (sm_103a) ----------------
__device__ __forceinline__ ull F2(float a, float b) {
    ull r; asm("mov.b64 %0,{%1,%2};" : "=l"(r) : "f"(a), "f"(b)); return r;
}
__device__ __forceinline__ ull DUP(float a) { return F2(a, a); }
__device__ __forceinline__ void UNF2(ull p, float& a, float& b) {
    asm("mov.b64 {%0,%1},%2;" : "=f"(a), "=f"(b) : "l"(p));
}
__device__ __forceinline__ ull ADD2(ull a, ull b) {
    ull r; asm("add.rn.f32x2 %0,%1,%2;" : "=l"(r) : "l"(a), "l"(b)); return r;
}
__device__ __forceinline__ ull MUL2(ull a, ull b) {
    ull r; asm("mul.rn.f32x2 %0,%1,%2;" : "=l"(r) : "l"(a), "l"(b)); return r;
}
__device__ __forceinline__ ull FMA2(ull a, ull b, ull c) {
    ull r; asm("fma.rn.f32x2 %0,%1,%2,%3;" : "=l"(r) : "l"(a), "l"(b), "l"(c)); return r;
}
__device__ __forceinline__ ull SUB2(ull a, ull b) {
    ull r; asm("sub.rn.f32x2 %0,%1,%2;" : "=l"(r) : "l"(a), "l"(b)); return r;
}
__device__ __forceinline__ ull LDS64(const float* p) { return *(const ull*)p; }

// packed Kahan-FMA accumulator: two independent lanes, 4 fma-pipe ops per
// 2 MACs. c holds the pending correction with convention true ~= s + c.
struct KS2 { ull s, c; };
__device__ __forceinline__ void kinit2(KS2& a, ull v) { a.s = v; a.c = 0ULL; }
__device__ __forceinline__ void kmac2(KS2& a, ull x, ull y) {
    ull yy = FMA2(x, y, a.c);
    ull t  = ADD2(a.s, yy);
    ull d  = SUB2(t, a.s);
    a.c    = SUB2(yy, d);
    a.s    = t;
}
// fold a pre-accumulated chunk value into the Kahan pair (4 ops)
__device__ __forceinline__ void kfold2(KS2& a, ull chunk) {
    ull yy = ADD2(chunk, a.c);
    ull t  = ADD2(a.s, yy);
    ull d  = SUB2(t, a.s);
    a.c    = SUB2(yy, d);
    a.s    = t;
}
__device__ __forceinline__ void kval2(const KS2& a, float& r0, float& r1) {
    float s0, s1, c0, c1;
    UNF2(a.s, s0, s1); UNF2(a.c, c0, c1);
    r0 = s0 + c0; r1 = s1 + c1;
}

// ---------------- scalar compensated helpers (small paths) ----------------
struct KS { float s, c; };
__device__ __forceinline__ void kinit(KS& a, float v) { a.s = v; a.c = 0.f; }
__device__ __forceinline__ void kadd(KS& a, float v) {
    float t = a.s + v;
    if (fabsf(a.s) >= fabsf(v)) a.c += (a.s - t) + v;
    else                        a.c += (v - t) + a.s;
    a.s = t;
}
__device__ __forceinline__ void kmac(KS& a, float x, float y) {
    float p = x * y;
    float e = fmaf(x, y, -p);
    kadd(a, p);
    a.c += e;
}
__device__ __forceinline__ float kval(const KS& a) { return a.s + a.c; }

__device__ __forceinline__ float blockSum128(float v, float* s4) {
    #pragma unroll
    for (int o = 16; o; o >>= 1) v += __shfl_down_sync(0xffffffffu, v, o);
    int lane = threadIdx.x & 31, wid = threadIdx.x >> 5;
    __syncthreads();
    if (lane == 0) s4[wid] = v;
    __syncthreads();
    return (s4[0] + s4[1]) + (s4[2] + s4[3]);
}

// ---------------- 1) performer feature maps (4 t per block, t-pairs packed) ----------------
template<int IS_Q>
__global__ void phi_kernel(const float* __restrict__ x, const float* __restrict__ proj)
{
    int t0 = blockIdx.x*4, h = blockIdx.y, tid = threadIdx.x; // 128 threads
    __shared__ float xs[4][ND];
    __shared__ ull xs01_u[ND], xs23_u[ND];
    __shared__ float smax[4][4];
    for (int e = tid; e < 4*ND; e += 128) {
        int j = e >> 6, u = e & 63;
        xs[j][u] = x[((size_t)(h*NT + t0 + j))*ND + u] * DATA_NORM;
    }
    __syncthreads();
    if (tid < 64)       xs01_u[tid]      = F2(xs[0][tid], xs[1][tid]);
    else                xs23_u[tid - 64] = F2(xs[2][tid - 64], xs[3][tid - 64]);
    __syncthreads();

    KS2 dk01, dk23; kinit2(dk01, 0ULL); kinit2(dk23, 0ULL);
    #pragma unroll 8
    for (int u = 0; u < ND; u++) {
        ull a = xs01_u[u];
        ull b = xs23_u[u];
        kmac2(dk01, a, a);
        kmac2(dk23, b, b);
    }
    float dg[4];
    { float q0, q1;
      kval2(dk01, q0, q1); dg[0] = 0.5f*q0; dg[1] = 0.5f*q1;
      kval2(dk23, q0, q1); dg[2] = 0.5f*q0; dg[3] = 0.5f*q1; }

    float xpv[3][4];
    float lmax[4] = {-1e30f, -1e30f, -1e30f, -1e30f};

    {
        const float* p0 = proj + (size_t)tid*ND;
        const float* p1 = proj + (size_t)(tid + 128)*ND;
        KS2 a001, a023, a101, a123;
        kinit2(a001, 0ULL); kinit2(a023, 0ULL); kinit2(a101, 0ULL); kinit2(a123, 0ULL);
        #pragma unroll 4
        for (int u = 0; u < ND; u++) {
            ull x01 = xs01_u[u];
            ull x23 = xs23_u[u];
            ull w0 = DUP(p0[u]); ull w1 = DUP(p1[u]);
            kmac2(a001, w0, x01); kmac2(a023, w0, x23);
            kmac2(a101, w1, x01); kmac2(a123, w1, x23);
        }
        kval2(a001, xpv[0][0], xpv[0][1]); kval2(a023, xpv[0][2], xpv[0][3]);
        kval2(a101, xpv[1][0], xpv[1][1]); kval2(a123, xpv[1][2], xpv[1][3]);
        #pragma unroll
        for (int j = 0; j < 4; j++)
            lmax[j] = fmaxf(xpv[0][j], xpv[1][j]);
    }
    int m2 = tid + 256;
    if (m2 < NM) {
        const float* p2 = proj + (size_t)m2*ND;
        KS2 a201, a223; kinit2(a201, 0ULL); kinit2(a223, 0ULL);
        #pragma unroll 4
        for (int u = 0; u < ND; u++) {
            ull w2 = DUP(p2[u]);
            kmac2(a201, w2, xs01_u[u]);
            kmac2(a223, w2, xs23_u[u]);
        }
        kval2(a201, xpv[2][0], xpv[2][1]); kval2(a223, xpv[2][2], xpv[2][3]);
        #pragma unroll
        for (int j = 0; j < 4; j++)
            lmax[j] = fmaxf(lmax[j], xpv[2][j]);
    }

    #pragma unroll
    for (int j = 0; j < 4; j++) {
        float v = lmax[j];
        #pragma unroll
        for (int o = 16; o; o >>= 1) v = fmaxf(v, __shfl_down_sync(0xffffffffu, v, o));
        if ((tid & 31) == 0) smax[j][tid >> 5] = v;
    }
    __syncthreads();
    float gmax[4];
    #pragma unroll
    for (int j = 0; j < 4; j++)
        gmax[j] = fmaxf(fmaxf(smax[j][0], smax[j][1]), fmaxf(smax[j][2], smax[j][3]));

    if (IS_Q) {
        #pragma unroll
        for (int j = 0; j < 4; j++) {
            float* orow = g_pq + ((size_t)(h*NT + t0 + j))*NM;
            orow[tid]       = M_RS * (expf((xpv[0][j] - dg[j]) - gmax[j]) + 1e-6f);
            orow[tid + 128] = M_RS * (expf((xpv[1][j] - dg[j]) - gmax[j]) + 1e-6f);
            if (m2 < NM)
                orow[m2]    = M_RS * (expf((xpv[2][j] - dg[j]) - gmax[j]) + 1e-6f);
        }
    } else {
        #pragma unroll
        for (int j = 0; j < 4; j++) {
            float* orow = g_pk + ((size_t)(h*NT + t0 + j))*NM;
            orow[tid]       = xpv[0][j];
            orow[tid + 128] = xpv[1][j];
            if (m2 < NM) orow[m2] = xpv[2][j];
        }
        if (tid == 0) {
            #pragma unroll
            for (int j = 0; j < 4; j++) {
                g_krowmax[h*NT + t0 + j] = gmax[j];
                g_kdiag[h*NT + t0 + j]   = dg[j];
            }
        }
    }
}

__global__ void headmax_kernel() {
    int h = blockIdx.x, tid = threadIdx.x;
    __shared__ float sr[256];
    float m = -1e30f;
    for (int t = tid; t < NT; t += 256) m = fmaxf(m, g_krowmax[h*NT + t]);
    sr[tid] = m; __syncthreads();
    for (int s = 128; s; s >>= 1) { if (tid < s) sr[tid] = fmaxf(sr[tid], sr[tid+s]); __syncthreads(); }
    if (tid == 0) g_kheadmax[h] = sr[0];
}

__global__ void pk_finish_kernel() {
    int idx = blockIdx.x*256 + threadIdx.x;
    if (idx >= NH*NT*NM) return;
    int row = idx / NM;
    int h = row / NT;
    g_pk[idx] = M_RS * (expf((g_pk[idx] - g_kdiag[row]) - g_kheadmax[h]) + 1e-6f);
}

__global__ void pksum_kernel() {
    int h = blockIdx.x, m = threadIdx.x;
    if (m >= NM) return;
    KS s; kinit(s, 0.f);
    for (int t = 0; t < NT; t++) kadd(s, g_pk[((size_t)(h*NT + t))*NM + m]);
    g_pksum[h*NM + m] = kval(s);
}

// kv[h][m][d] = sum_t pk[h][t][m] * vfa[h][t][d]
// K-tile 64 (was 32): halves barrier count; per-thread k-order unchanged.
__global__ void kv_kernel(const float* __restrict__ vfa) {
    int h = blockIdx.z;
    int m0 = blockIdx.x*16, n0 = blockIdx.y*16;
    int tx = threadIdx.x;   // 0..7
    int ty = threadIdx.y;   // 0..15
    int tid = ty*8 + tx;    // 128 threads
    __shared__ float As[64][16];
    __shared__ ull Bs_u[64][8];
    KS2 acc; kinit2(acc, 0ULL);
    for (int k0 = 0; k0 < NT; k0 += 64) {
        #pragma unroll
        for (int e = tid; e < 1024; e += 128) {
            int kk = e >> 4, j = e & 15;
            int m = m0 + j;
            As[kk][j] = (m < NM) ? g_pk[((size_t)(h*NT + k0 + kk))*NM + m] : 0.f;
        }
        #pragma unroll
        for (int e = tid; e < 512; e += 128) {
            int kk = e >> 3, j8 = e & 7;
            const float* vr = vfa + ((size_t)(h*NT + k0 + kk))*NVH + n0;
            Bs_u[kk][j8] = F2(vr[j8], vr[j8 + 8]);
        }
        __syncthreads();
        #pragma unroll
        for (int kk = 0; kk < 64; kk++)
            kmac2(acc, DUP(As[kk][ty]), Bs_u[kk][tx]);
        __syncthreads();
    }
    int m = m0 + ty;
    if (m < NM) {
        float r0, r1; kval2(acc, r0, r1);
        g_kv[((size_t)h*NM + m)*NVH + n0 + tx]     = r0;
        g_kv[((size_t)h*NM + m)*NVH + n0 + tx + 8] = r1;
    }
}

// kv2[h][m][d2] = sum_v kv[h][m][v] * enc_w[v][d2]   (tiny fused-path GEMM)
__global__ void kv2_kernel(const float* __restrict__ enc_w) {
    int m = blockIdx.x, h = blockIdx.y, tid = threadIdx.x; // 128 threads
    __shared__ float kvrow[NVH];
    for (int e = tid; e < NVH; e += 128)
        kvrow[e] = g_kv[((size_t)h*NM + m)*NVH + e];
    __syncthreads();
    KS a; kinit(a, 0.f);
    for (int v = 0; v < NVH; v++)
        kmac(a, kvrow[v], enc_w[v*ND2 + tid]);
    g_kv2[((size_t)h*NM + m)*ND2 + tid] = kval(a);
}

// ---------------- 2) FUSED t_perf + encoder ----------------
__global__ void tperf_enc_kernel(const float* __restrict__ enc_b,
                                 const float* __restrict__ ln_g, const float* __restrict__ ln_b)
{
    int h = blockIdx.y, t0 = blockIdx.x*16, tid = threadIdx.x; // 128 threads
    __shared__ __align__(8) float pqs_f[NM][18];   // [m][row], padded
    __shared__ float zs[16];
    __shared__ float s4[4];
    for (int e = tid; e < 16*NM; e += 128) {
        int r = e / NM, m = e % NM;
        pqs_f[m][r] = g_pq[((size_t)(h*NT + t0 + r))*NM + m];
    }
    __syncthreads();
    if (tid < 16) {
        KS dn; kinit(dn, 0.f);
        for (int m = 0; m < NM; m++) kmac(dn, pqs_f[m][tid], g_pksum[h*NM + m]);
        zs[tid] = (float)(1.0 / ((double)kval(dn) + 1e-8));
    }
    KS2 acc2[8];
    #pragma unroll
    for (int j = 0; j < 8; j++) kinit2(acc2[j], 0ULL);
    __syncthreads();
    for (int m = 0; m < NM; m++) {
        ull kv2v = DUP(g_kv2[((size_t)h*NM + m)*ND2 + tid]);
        const float* pr = pqs_f[m];
        #pragma unroll
        for (int j = 0; j < 8; j++)
            kmac2(acc2[j], LDS64(pr + 2*j), kv2v);
    }
    float encb = enc_b[tid];
    float av[16];
    #pragma unroll
    for (int j = 0; j < 8; j++) {
        float g0, g1; kval2(acc2[j], g0, g1);
        av[2*j]   = fmaf(zs[2*j],   g0, encb);
        av[2*j+1] = fmaf(zs[2*j+1], g1, encb);
    }

    float gg = ln_g[tid], bb = ln_b[tid];
    for (int r = 0; r < 16; r++) {
        float su = blockSum128(av[r], s4);
        float mu = su * (1.f/128.f);
        float d = av[r] - mu;
        float s2 = blockSum128(d*d, s4);
        float var = s2 * (1.f/128.f);
        float y = d * (float)(1.0 / sqrt((double)var + 1e-5)) * gg + bb;
        float ge = 0.5f*y*(1.f + erff(y*0.70710678118654752f));
        g_tenc[((size_t)(h*NT + t0 + r))*ND2 + tid] = ge;
    }
}

// ---------------- 3) decoder Linear(128->256) + channel split, 16 rows ----------------
__global__ void dec_kernel(const float* __restrict__ dec_w, const float* __restrict__ dec_b)
{
    int h = blockIdx.y, t0 = blockIdx.x*16, tid = threadIdx.x; // 256 threads
    __shared__ __align__(8) float tes_f[ND2][18];
    for (int e = tid; e < 16*ND2; e += 256) {
        int r = e >> 7, vv = e & 127;
        tes_f[vv][r] = g_tenc[((size_t)(h*NT + t0 + r))*ND2 + vv];
    }
    __syncthreads();
    KS2 acc2[8];
    #pragma unroll
    for (int j = 0; j < 8; j++) kinit2(acc2[j], DUP(dec_b[tid]));
    for (int vv = 0; vv < ND2; vv++) {
        ull w2 = DUP(dec_w[vv*256 + tid]);
        const float* pr = tes_f[vv];
        #pragma unroll
        for (int j = 0; j < 8; j++)
            kmac2(acc2[j], LDS64(pr + 2*j), w2);
    }
    int g = tid >> 6, wc = tid & 63, c = h*4 + g;
    #pragma unroll
    for (int j = 0; j < 8; j++) {
        float r0, r1; kval2(acc2[j], r0, r1);
        g_xdec[((size_t)c*NT + (t0 + 2*j))*ND + wc]     = r0;
        g_xdec[((size_t)c*NT + (t0 + 2*j + 1))*ND + wc] = r1;
    }
}

// ---------------- 4) CNN stack ----------------
// conv1/conv2: per-input-channel 9-tap chunk accumulated with plain FMA2
// cascade (same term order), folded into the Kahan pair with one Fast2Sum.
// 13 ops / 9 MACs. Chunk noise (~2.2x kmac2) is damped by the downstream
// conv gain (~0.42/layer) before reaching conv3's x -> mask-safe margin kept.
__global__ void conv1_kernel(const float* __restrict__ W, const float* __restrict__ B)
{
    int to = blockIdx.x, tid = threadIdx.x; // 256 threads
    int w = tid & 63, cosub = tid >> 6;
    __shared__ float in_s[NC4][3][66];
    __shared__ ull w_u[4][24][9];
    for (int e = tid; e < NC4*3*66; e += 256) {
        int ci = e / 198, rem = e % 198, dy = rem / 66, col = rem % 66;
        int r = 2*to + dy - 1, ws = col - 1;
        float vv = 0.f;
        if (r >= 0 && r < NT && ws >= 0 && ws < ND) vv = g_xdec[((size_t)ci*NT + r)*ND + ws];
        in_s[ci][dy][col] = vv;
    }
    KS2 acc2[6];
    #pragma unroll
    for (int i = 0; i < 6; i++)
        kinit2(acc2[i], F2(B[cosub + 4*i], B[cosub + 4*i + 24]));
    for (int cc = 0; cc < 12; cc++) {
        __syncthreads();
        for (int e = tid; e < 4*24*9; e += 256) {
            int cis = e / 216, rem = e % 216, co = rem / 9, kk = rem % 9;
            int cin = cc*4 + cis;
            w_u[cis][co][kk] = F2(W[((size_t)co*NC4 + cin)*9 + kk],
                                  W[((size_t)(co + 24)*NC4 + cin)*9 + kk]);
        }
        __syncthreads();
        #pragma unroll
        for (int cis = 0; cis < 4; cis++) {
            int ci = cc*4 + cis;
            ull d0 = DUP(in_s[ci][0][w]), d1 = DUP(in_s[ci][0][w+1]), d2 = DUP(in_s[ci][0][w+2]);
            ull d3 = DUP(in_s[ci][1][w]), d4 = DUP(in_s[ci][1][w+1]), d5 = DUP(in_s[ci][1][w+2]);
            ull d6 = DUP(in_s[ci][2][w]), d7 = DUP(in_s[ci][2][w+1]), d8 = DUP(in_s[ci][2][w+2]);
            #pragma unroll
            for (int i = 0; i < 6; i++) {
                const ull* wp = w_u[cis][cosub + 4*i];
                ull ch = MUL2(d0, wp[0]);
                ch = FMA2(d1, wp[1], ch); ch = FMA2(d2, wp[2], ch);
                ch = FMA2(d3, wp[3], ch); ch = FMA2(d4, wp[4], ch);
                ch = FMA2(d5, wp[5], ch); ch = FMA2(d6, wp[6], ch);
                ch = FMA2(d7, wp[7], ch); ch = FMA2(d8, wp[8], ch);
                kfold2(acc2[i], ch);
            }
        }
    }
    #pragma unroll
    for (int i = 0; i < 6; i++) {
        float r0, r1; kval2(acc2[i], r0, r1);
        int co = cosub + 4*i;
        g_c1[((size_t)co*NTH + to)*ND + w]        = fmaxf(r0, 0.f);
        g_c1[((size_t)(co + 24)*NTH + to)*ND + w] = fmaxf(r1, 0.f);
    }
}

__global__ void conv2_kernel(const float* __restrict__ W, const float* __restrict__ B)
{
    int to = blockIdx.x, tid = threadIdx.x;
    int w = tid & 63, cosub = tid >> 6;
    __shared__ float in_s[NC4][3][66];
    __shared__ ull w_u[4][24][9];
    for (int e = tid; e < NC4*3*66; e += 256) {
        int ci = e / 198, rem = e % 198, dy = rem / 66, col = rem % 66;
        int r = to + dy - 1, ws = col - 1;
        float vv = 0.f;
        if (r >= 0 && r < NTH && ws >= 0 && ws < ND) vv = g_c1[((size_t)ci*NTH + r)*ND + ws];
        in_s[ci][dy][col] = vv;
    }
    KS2 acc2[6];
    #pragma unroll
    for (int i = 0; i < 6; i++)
        kinit2(acc2[i], F2(B[cosub + 4*i], B[cosub + 4*i + 24]));
    for (int cc = 0; cc < 12; cc++) {
        __syncthreads();
        for (int e = tid; e < 4*24*9; e += 256) {
            int cis = e / 216, rem = e % 216, co = rem / 9, kk = rem % 9;
            int cin = cc*4 + cis;
            w_u[cis][co][kk] = F2(W[((size_t)co*NC4 + cin)*9 + kk],
                                  W[((size_t)(co + 24)*NC4 + cin)*9 + kk]);
        }
        __syncthreads();
        #pragma unroll
        for (int cis = 0; cis < 4; cis++) {
            int ci = cc*4 + cis;
            ull d0 = DUP(in_s[ci][0][w]), d1 = DUP(in_s[ci][0][w+1]), d2 = DUP(in_s[ci][0][w+2]);
            ull d3 = DUP(in_s[ci][1][w]), d4 = DUP(in_s[ci][1][w+1]), d5 = DUP(in_s[ci][1][w+2]);
            ull d6 = DUP(in_s[ci][2][w]), d7 = DUP(in_s[ci][2][w+1]), d8 = DUP(in_s[ci][2][w+2]);
            #pragma unroll
            for (int i = 0; i < 6; i++) {
                const ull* wp = w_u[cis][cosub + 4*i];
                ull ch = MUL2(d0, wp[0]);
                ch = FMA2(d1, wp[1], ch); ch = FMA2(d2, wp[2], ch);
                ch = FMA2(d3, wp[3], ch); ch = FMA2(d4, wp[4], ch);
                ch = FMA2(d5, wp[5], ch); ch = FMA2(d6, wp[6], ch);
                ch = FMA2(d7, wp[7], ch); ch = FMA2(d8, wp[8], ch);
                kfold2(acc2[i], ch);
            }
        }
    }
    #pragma unroll
    for (int i = 0; i < 6; i++) {
        float r0, r1; kval2(acc2[i], r0, r1);
        int co = cosub + 4*i;
        g_c2[((size_t)co*NTH + to)*ND + w]        = fmaxf(r0, 0.f);
        g_c2[((size_t)(co + 24)*NTH + to)*ND + w] = fmaxf(r1, 0.f);
    }
}

// conv3: nearest-upsample rows fused; FULL 4-op kmac2 kept (noise here hits
// the mask x directly with gain 1 — do not relax).
__global__ void conv3_kernel(const float* __restrict__ W, const float* __restrict__ B)
{
    int to = blockIdx.x, tid = threadIdx.x; // 384 threads: w = tid&63, cop = tid>>6 (0..5)
    int w = tid & 63, cop = tid >> 6;
    __shared__ float in_s[NC4][3][66];
    __shared__ ull w_u[8][6][9];
    for (int e = tid; e < NC4*3*66; e += 384) {
        int ci = e / 198, rem = e % 198, dy = rem / 66, col = rem % 66;
        int r = to + dy - 1, ws = col - 1;
        float vv = 0.f;
        if (r >= 0 && r < NT && ws >= 0 && ws < ND) vv = g_c2[((size_t)ci*NTH + (r >> 1))*ND + ws];
        in_s[ci][dy][col] = vv;
    }
    KS2 acc; kinit2(acc, F2(B[cop], B[cop + 6]));
    for (int cc = 0; cc < 6; cc++) {
        __syncthreads();
        for (int e = tid; e < 8*6*9; e += 384) {
            int cis = e / 54, rem = e % 54, c = rem / 9, kk = rem % 9;
            int cin = cc*8 + cis;
            w_u[cis][c][kk] = F2(W[((size_t)c*NC4 + cin)*9 + kk],
                                 W[((size_t)(c + 6)*NC4 + cin)*9 + kk]);
        }
        __syncthreads();
        #pragma unroll
        for (int cis = 0; cis < 8; cis++) {
            int ci = cc*8 + cis;
            const ull* wp = w_u[cis][cop];
            kmac2(acc, DUP(in_s[ci][0][w]),   wp[0]);
            kmac2(acc, DUP(in_s[ci][0][w+1]), wp[1]);
            kmac2(acc, DUP(in_s[ci][0][w+2]), wp[2]);
            kmac2(acc, DUP(in_s[ci][1][w]),   wp[3]);
            kmac2(acc, DUP(in_s[ci][1][w+1]), wp[4]);
            kmac2(acc, DUP(in_s[ci][1][w+2]), wp[5]);
            kmac2(acc, DUP(in_s[ci][2][w]),   wp[6]);
            kmac2(acc, DUP(in_s[ci][2][w+1]), wp[7]);
            kmac2(acc, DUP(in_s[ci][2][w+2]), wp[8]);
        }
    }
    float r0, r1; kval2(acc, r0, r1);
    g_c3[((size_t)cop*NT + to)*ND + w]       = r0;
    g_c3[((size_t)(cop + 6)*NT + to)*ND + w] = r1;
}

// ---------------- 5-7) est softmax with XLA-bit-matched rounding -> top-k mask ----------------
// (UNCHANGED — mask-critical)
__global__ void mask_kernel()
{
    int t = blockIdx.x, h = blockIdx.y, lane = threadIdx.x; // 32 threads
    const float* row = g_c3 + ((size_t)h*NT + t)*ND;
    float v0 = row[lane], v1 = row[lane + 32];

    float mx = fmaxf(v0, v1);
    #pragma unroll
    for (int o = 16; o; o >>= 1) mx = fmaxf(mx, __shfl_xor_sync(0xffffffffu, mx, o));

    float e0 = (float)exp((double)(v0 - mx));
    float e1 = (float)exp((double)(v1 - mx));

    float s0 = e0, s1 = e1;
    #pragma unroll
    for (int o = 8; o; o >>= 1) {
        s0 += __shfl_down_sync(0xffffffffu, s0, o);
        s1 += __shfl_down_sync(0xffffffffu, s1, o);
    }
    s0 += s0;
    s1 += s1;
    float p0 = __shfl_sync(0xffffffffu, s0, 0);
    float p1 = __shfl_sync(0xffffffffu, s0, 16);
    float p2 = __shfl_sync(0xffffffffu, s1, 0);
    float p3 = __shfl_sync(0xffffffffu, s1, 16);
    float dsum = (p0 + p2) + (p1 + p3);

    float est0 = __fdiv_rn(e0, dsum);
    float est1 = __fdiv_rn(e1, dsum);

    float a1 = fmaxf(est0, est1), a2 = fminf(est0, est1);
    #pragma unroll
    for (int o = 16; o; o >>= 1) {
        float b1 = __shfl_xor_sync(0xffffffffu, a1, o);
        float b2 = __shfl_xor_sync(0xffffffffu, a2, o);
        if (b1 > a1) { a2 = fmaxf(a1, b2); a1 = b1; }
        else         { a2 = fmaxf(a2, b1); }
    }
    float thresh = a2;
    int b0 = (est0 >= thresh) ? 1 : 0;
    int b1i = (est1 >= thresh) ? 1 : 0;
    unsigned words[4];
    #pragma unroll
    for (int k2 = 0; k2 < 4; k2++) {
        int wsrc = 16*k2 + (lane >> 1);
        int bv = __shfl_sync(0xffffffffu, (k2 < 2) ? b0 : b1i, wsrc & 31);
        words[k2] = __ballot_sync(0xffffffffu, bv);
    }
    if (lane == 0) {
        unsigned* mp = g_maskbits + ((size_t)h*NT + t)*4;
        mp[0] = words[0]; mp[1] = words[1]; mp[2] = words[2]; mp[3] = words[3];
    }
}

// ---------------- 8) block-sparse masked attention ----------------
__global__ void attn_kernel(const float* __restrict__ q, const float* __restrict__ k,
                            const float* __restrict__ v, float* __restrict__ out)
{
    int t = blockIdx.x, h = blockIdx.y, tid = threadIdx.x; // 128 threads
    __shared__ float qs[ND];
    __shared__ int blk_list[128];
    __shared__ int s_nblk;
    __shared__ float sc[2048];
    __shared__ float s4[4];
    __shared__ unsigned mw[4];
    __shared__ int flags[128];
    __shared__ float part[128];

    if (tid < 4) mw[tid] = g_maskbits[((size_t)h*NT + t)*4 + tid];
    if (tid < ND) qs[tid] = q[((size_t)h*NT + t)*ND + tid];
    __syncthreads();
    flags[tid] = (mw[tid >> 5] >> (tid & 31)) & 1;
    __syncthreads();
    if (tid == 0) {
        int n = 0;
        for (int j = 0; j < 128; j++) if (flags[j]) blk_list[n++] = j;
        s_nblk = n;
    }
    __syncthreads();
    int nk = s_nblk * 16;

    float lmax = -1e30f;
    for (int idx = tid; idx < nk; idx += 128) {
        int ss = blk_list[idx >> 4]*16 + (idx & 15);
        const float4* kr = (const float4*)(k + ((size_t)h*NT + ss)*ND);
        float acc = 0.f;
        #pragma unroll
        for (int u = 0; u < 16; u++) {
            float4 k4 = kr[u];
            acc += k4.x*qs[4*u] + k4.y*qs[4*u+1] + k4.z*qs[4*u+2] + k4.w*qs[4*u+3];
        }
        float scv = acc * 0.125f;
        sc[idx] = scv;
        lmax = fmaxf(lmax, scv);
    }
    #pragma unroll
    for (int o = 16; o; o >>= 1) lmax = fmaxf(lmax, __shfl_down_sync(0xffffffffu, lmax, o));
    if ((tid & 31) == 0) s4[tid >> 5] = lmax;
    __syncthreads();
    float gmax = fmaxf(fmaxf(s4[0], s4[1]), fmaxf(s4[2], s4[3]));

    float lsum = 0.f;
    for (int idx = tid; idx < nk; idx += 128) {
        float p = expf(sc[idx] - gmax);
        sc[idx] = p;
        lsum += p;
    }
    #pragma unroll
    for (int o = 16; o; o >>= 1) lsum += __shfl_down_sync(0xffffffffu, lsum, o);
    __syncthreads();
    if ((tid & 31) == 0) s4[tid >> 5] = lsum;
    __syncthreads();
    float denom = (s4[0] + s4[1]) + (s4[2] + s4[3]);
    float rden = (float)(1.0 / (double)denom);

    int d = tid & 63, half = tid >> 6;
    float acc = 0.f;
    for (int idx = half; idx < nk; idx += 2) {
        int ss = blk_list[idx >> 4]*16 + (idx & 15);
        acc += sc[idx] * v[((size_t)h*NT + ss)*ND + d];
    }
    part[tid] = acc;
    __syncthreads();
    if (tid < 64)
        out[((size_t)h*NT + t)*ND + d] = (part[tid] + part[tid + 64]) * rden;
}

// ---------------- launch ----------------
extern "C" void kernel_launch(void* const* d_in, const int* in_sizes, int n_in,
                              void* d_out, int out_size)
{
    const float* q     = (const float*)d_in[0];
    const float* k     = (const float*)d_in[1];
    const float* v     = (const float*)d_in[2];
    const float* vfa   = (const float*)d_in[3];
    const float* proj  = (const float*)d_in[4];
    const float* enc_w = (const float*)d_in[5];
    const float* enc_b = (const float*)d_in[6];
    const float* ln_g  = (const float*)d_in[7];
    const float* ln_b  = (const float*)d_in[8];
    const float* dec_w = (const float*)d_in[9];
    const float* dec_b = (const float*)d_in[10];
    const float* c1w   = (const float*)d_in[11];
    const float* c1b   = (const float*)d_in[12];
    const float* c2w   = (const float*)d_in[13];
    const float* c2b   = (const float*)d_in[14];
    const float* c3w   = (const float*)d_in[15];
    const float* c3b   = (const float*)d_in[16];
    float* out = (float*)d_out;

    dim3 gTH(NT, NH);

    phi_kernel<1><<<dim3(NT/4, NH), 128>>>(q, proj);
    phi_kernel<0><<<dim3(NT/4, NH), 128>>>(k, proj);
    headmax_kernel<<<NH, 256>>>();
    pk_finish_kernel<<<(NH*NT*NM + 255)/256, 256>>>();
    pksum_kernel<<<NH, 288>>>();
    kv_kernel<<<dim3((NM + 15)/16, NVH/16, NH), dim3(8, 16)>>>(vfa);
    kv2_kernel<<<dim3(NM, NH), 128>>>(enc_w);
    tperf_enc_kernel<<<dim3(NT/16, NH), 128>>>(enc_b, ln_g, ln_b);
    dec_kernel<<<dim3(NT/16, NH), 256>>>(dec_w, dec_b);
    conv1_kernel<<<NTH, 256>>>(c1w, c1b);
    conv2_kernel<<<NTH, 256>>>(c2w, c2b);
    conv3_kernel<<<NT, 384>>>(c3w, c3b);
    mask_kernel<<<gTH, 32>>>();
    attn_kernel<<<gTH, 128>>>(q, k, v, out);
}

// round 16
// speedup vs baseline: 2.9046x; 1.0722x over previous
#include <cuda_runtime.h>
#include <math.h>

// ---------------- problem constants ----------------
#define NH 12      // heads
#define NT 2048    // sequence length
#define ND 64      // head dim
#define NM 266     // performer features
#define NVH 192    // performer value hidden (3D)
#define ND2 128    // 2*D
#define NC4 48     // 4*H conv channels
#define NTH 1024   // T/2

#define DATA_NORM 0.35355339059327373f   // 64^-0.25
#define M_RS      0.06131393394849658f   // 266^-0.5

typedef unsigned long long ull;

// ---------------- scratch (device globals; no allocs allowed) ----------------
__device__ float g_pq[NH*NT*NM];
__device__ float g_pk[NH*NT*NM];
__device__ float g_krowmax[NH*NT];
__device__ float g_kdiag[NH*NT];
__device__ float g_kheadmax[NH];
__device__ float g_kv[NH*NM*NVH];
__device__ float g_kv2[NH*NM*ND2];
__device__ float g_pksum[NH*NM];
__device__ float g_tenc[NH*NT*ND2];
__device__ float g_xdec[NC4*NT*ND];
__device__ float g_c1[NC4*NTH*ND];
__device__ float g_c2[NC4*NTH*ND];
__device__ float g_c3[NH*NT*ND];
__device__ unsigned g_maskbits[NH*NT*4];

// ---------------- packed f32x2 helpers (sm_103a) ----------------
__device__ __forceinline__ ull F2(float a, float b) {
    ull r; asm("mov.b64 %0,{%1,%2};" : "=l"(r) : "f"(a), "f"(b)); return r;
}
__device__ __forceinline__ ull DUP(float a) { return F2(a, a); }
__device__ __forceinline__ void UNF2(ull p, float& a, float& b) {
    asm("mov.b64 {%0,%1},%2;" : "=f"(a), "=f"(b) : "l"(p));
}
__device__ __forceinline__ ull ADD2(ull a, ull b) {
    ull r; asm("add.rn.f32x2 %0,%1,%2;" : "=l"(r) : "l"(a), "l"(b)); return r;
}
__device__ __forceinline__ ull MUL2(ull a, ull b) {
    ull r; asm("mul.rn.f32x2 %0,%1,%2;" : "=l"(r) : "l"(a), "l"(b)); return r;
}
__device__ __forceinline__ ull FMA2(ull a, ull b, ull c) {
    ull r; asm("fma.rn.f32x2 %0,%1,%2,%3;" : "=l"(r) : "l"(a), "l"(b), "l"(c)); return r;
}
__device__ __forceinline__ ull SUB2(ull a, ull b) {
    ull r; asm("sub.rn.f32x2 %0,%1,%2;" : "=l"(r) : "l"(a), "l"(b)); return r;
}
__device__ __forceinline__ ull LDS64(const float* p) { return *(const ull*)p; }

// packed Kahan-FMA accumulator: two independent lanes, 4 fma-pipe ops per
// 2 MACs. c holds the pending correction with convention true ~= s + c.
struct KS2 { ull s, c; };
__device__ __forceinline__ void kinit2(KS2& a, ull v) { a.s = v; a.c = 0ULL; }
__device__ __forceinline__ void kmac2(KS2& a, ull x, ull y) {
    ull yy = FMA2(x, y, a.c);
    ull t  = ADD2(a.s, yy);
    ull d  = SUB2(t, a.s);
    a.c    = SUB2(yy, d);
    a.s    = t;
}
// fold a pre-accumulated chunk value into the Kahan pair (4 ops)
__device__ __forceinline__ void kfold2(KS2& a, ull chunk) {
    ull yy = ADD2(chunk, a.c);
    ull t  = ADD2(a.s, yy);
    ull d  = SUB2(t, a.s);
    a.c    = SUB2(yy, d);
    a.s    = t;
}
__device__ __forceinline__ void kval2(const KS2& a, float& r0, float& r1) {
    float s0, s1, c0, c1;
    UNF2(a.s, s0, s1); UNF2(a.c, c0, c1);
    r0 = s0 + c0; r1 = s1 + c1;
}

// ---------------- scalar compensated helpers (small paths) ----------------
struct KS { float s, c; };
__device__ __forceinline__ void kinit(KS& a, float v) { a.s = v; a.c = 0.f; }
__device__ __forceinline__ void kadd(KS& a, float v) {
    float t = a.s + v;
    if (fabsf(a.s) >= fabsf(v)) a.c += (a.s - t) + v;
    else                        a.c += (v - t) + a.s;
    a.s = t;
}
__device__ __forceinline__ void kmac(KS& a, float x, float y) {
    float p = x * y;
    float e = fmaf(x, y, -p);
    kadd(a, p);
    a.c += e;
}
__device__ __forceinline__ float kval(const KS& a) { return a.s + a.c; }

__device__ __forceinline__ float blockSum128(float v, float* s4) {
    #pragma unroll
    for (int o = 16; o; o >>= 1) v += __shfl_down_sync(0xffffffffu, v, o);
    int lane = threadIdx.x & 31, wid = threadIdx.x >> 5;
    __syncthreads();
    if (lane == 0) s4[wid] = v;
    __syncthreads();
    return (s4[0] + s4[1]) + (s4[2] + s4[3]);
}

// ---------------- 1) performer feature maps (4 t per block, t-pairs packed) ----------------
template<int IS_Q>
__global__ void phi_kernel(const float* __restrict__ x, const float* __restrict__ proj)
{
    int t0 = blockIdx.x*4, h = blockIdx.y, tid = threadIdx.x; // 128 threads
    __shared__ float xs[4][ND];
    __shared__ ull xs01_u[ND], xs23_u[ND];
    __shared__ float smax[4][4];
    for (int e = tid; e < 4*ND; e += 128) {
        int j = e >> 6, u = e & 63;
        xs[j][u] = x[((size_t)(h*NT + t0 + j))*ND + u] * DATA_NORM;
    }
    __syncthreads();
    if (tid < 64)       xs01_u[tid]      = F2(xs[0][tid], xs[1][tid]);
    else                xs23_u[tid - 64] = F2(xs[2][tid - 64], xs[3][tid - 64]);
    __syncthreads();

    KS2 dk01, dk23; kinit2(dk01, 0ULL); kinit2(dk23, 0ULL);
    #pragma unroll 8
    for (int u = 0; u < ND; u++) {
        ull a = xs01_u[u];
        ull b = xs23_u[u];
        kmac2(dk01, a, a);
        kmac2(dk23, b, b);
    }
    float dg[4];
    { float q0, q1;
      kval2(dk01, q0, q1); dg[0] = 0.5f*q0; dg[1] = 0.5f*q1;
      kval2(dk23, q0, q1); dg[2] = 0.5f*q0; dg[3] = 0.5f*q1; }

    float xpv[3][4];
    float lmax[4] = {-1e30f, -1e30f, -1e30f, -1e30f};

    {
        const float* p0 = proj + (size_t)tid*ND;
        const float* p1 = proj + (size_t)(tid + 128)*ND;
        KS2 a001, a023, a101, a123;
        kinit2(a001, 0ULL); kinit2(a023, 0ULL); kinit2(a101, 0ULL); kinit2(a123, 0ULL);
        #pragma unroll 4
        for (int u = 0; u < ND; u++) {
            ull x01 = xs01_u[u];
            ull x23 = xs23_u[u];
            ull w0 = DUP(p0[u]); ull w1 = DUP(p1[u]);
            kmac2(a001, w0, x01); kmac2(a023, w0, x23);
            kmac2(a101, w1, x01); kmac2(a123, w1, x23);
        }
        kval2(a001, xpv[0][0], xpv[0][1]); kval2(a023, xpv[0][2], xpv[0][3]);
        kval2(a101, xpv[1][0], xpv[1][1]); kval2(a123, xpv[1][2], xpv[1][3]);
        #pragma unroll
        for (int j = 0; j < 4; j++)
            lmax[j] = fmaxf(xpv[0][j], xpv[1][j]);
    }
    int m2 = tid + 256;
    if (m2 < NM) {
        const float* p2 = proj + (size_t)m2*ND;
        KS2 a201, a223; kinit2(a201, 0ULL); kinit2(a223, 0ULL);
        #pragma unroll 4
        for (int u = 0; u < ND; u++) {
            ull w2 = DUP(p2[u]);
            kmac2(a201, w2, xs01_u[u]);
            kmac2(a223, w2, xs23_u[u]);
        }
        kval2(a201, xpv[2][0], xpv[2][1]); kval2(a223, xpv[2][2], xpv[2][3]);
        #pragma unroll
        for (int j = 0; j < 4; j++)
            lmax[j] = fmaxf(lmax[j], xpv[2][j]);
    }

    #pragma unroll
    for (int j = 0; j < 4; j++) {
        float v = lmax[j];
        #pragma unroll
        for (int o = 16; o; o >>= 1) v = fmaxf(v, __shfl_down_sync(0xffffffffu, v, o));
        if ((tid & 31) == 0) smax[j][tid >> 5] = v;
    }
    __syncthreads();
    float gmax[4];
    #pragma unroll
    for (int j = 0; j < 4; j++)
        gmax[j] = fmaxf(fmaxf(smax[j][0], smax[j][1]), fmaxf(smax[j][2], smax[j][3]));

    if (IS_Q) {
        #pragma unroll
        for (int j = 0; j < 4; j++) {
            float* orow = g_pq + ((size_t)(h*NT + t0 + j))*NM;
            orow[tid]       = M_RS * (expf((xpv[0][j] - dg[j]) - gmax[j]) + 1e-6f);
            orow[tid + 128] = M_RS * (expf((xpv[1][j] - dg[j]) - gmax[j]) + 1e-6f);
            if (m2 < NM)
                orow[m2]    = M_RS * (expf((xpv[2][j] - dg[j]) - gmax[j]) + 1e-6f);
        }
    } else {
        #pragma unroll
        for (int j = 0; j < 4; j++) {
            float* orow = g_pk + ((size_t)(h*NT + t0 + j))*NM;
            orow[tid]       = xpv[0][j];
            orow[tid + 128] = xpv[1][j];
            if (m2 < NM) orow[m2] = xpv[2][j];
        }
        if (tid == 0) {
            #pragma unroll
            for (int j = 0; j < 4; j++) {
                g_krowmax[h*NT + t0 + j] = gmax[j];
                g_kdiag[h*NT + t0 + j]   = dg[j];
            }
        }
    }
}

__global__ void headmax_kernel() {
    int h = blockIdx.x, tid = threadIdx.x;
    __shared__ float sr[256];
    float m = -1e30f;
    for (int t = tid; t < NT; t += 256) m = fmaxf(m, g_krowmax[h*NT + t]);
    sr[tid] = m; __syncthreads();
    for (int s = 128; s; s >>= 1) { if (tid < s) sr[tid] = fmaxf(sr[tid], sr[tid+s]); __syncthreads(); }
    if (tid == 0) g_kheadmax[h] = sr[0];
}

__global__ void pk_finish_kernel() {
    int idx = blockIdx.x*256 + threadIdx.x;
    if (idx >= NH*NT*NM) return;
    int row = idx / NM;
    int h = row / NT;
    g_pk[idx] = M_RS * (expf((g_pk[idx] - g_kdiag[row]) - g_kheadmax[h]) + 1e-6f);
}

__global__ void pksum_kernel() {
    int h = blockIdx.x, m = threadIdx.x;
    if (m >= NM) return;
    KS s; kinit(s, 0.f);
    for (int t = 0; t < NT; t++) kadd(s, g_pk[((size_t)(h*NT + t))*NM + m]);
    g_pksum[h*NM + m] = kval(s);
}

// kv[h][m][d] = sum_t pk[h][t][m] * vfa[h][t][d]
__global__ void kv_kernel(const float* __restrict__ vfa) {
    int h = blockIdx.z;
    int m0 = blockIdx.x*16, n0 = blockIdx.y*16;
    int tx = threadIdx.x;   // 0..7
    int ty = threadIdx.y;   // 0..15
    int tid = ty*8 + tx;    // 128 threads
    __shared__ float As[64][16];
    __shared__ ull Bs_u[64][8];
    KS2 acc; kinit2(acc, 0ULL);
    for (int k0 = 0; k0 < NT; k0 += 64) {
        #pragma unroll
        for (int e = tid; e < 1024; e += 128) {
            int kk = e >> 4, j = e & 15;
            int m = m0 + j;
            As[kk][j] = (m < NM) ? g_pk[((size_t)(h*NT + k0 + kk))*NM + m] : 0.f;
        }
        #pragma unroll
        for (int e = tid; e < 512; e += 128) {
            int kk = e >> 3, j8 = e & 7;
            const float* vr = vfa + ((size_t)(h*NT + k0 + kk))*NVH + n0;
            Bs_u[kk][j8] = F2(vr[j8], vr[j8 + 8]);
        }
        __syncthreads();
        #pragma unroll
        for (int kk = 0; kk < 64; kk++)
            kmac2(acc, DUP(As[kk][ty]), Bs_u[kk][tx]);
        __syncthreads();
    }
    int m = m0 + ty;
    if (m < NM) {
        float r0, r1; kval2(acc, r0, r1);
        g_kv[((size_t)h*NM + m)*NVH + n0 + tx]     = r0;
        g_kv[((size_t)h*NM + m)*NVH + n0 + tx + 8] = r1;
    }
}

// kv2[h][m][d2] = sum_v kv[h][m][v] * enc_w[v][d2]   (tiny fused-path GEMM)
__global__ void kv2_kernel(const float* __restrict__ enc_w) {
    int m = blockIdx.x, h = blockIdx.y, tid = threadIdx.x; // 128 threads
    __shared__ float kvrow[NVH];
    for (int e = tid; e < NVH; e += 128)
        kvrow[e] = g_kv[((size_t)h*NM + m)*NVH + e];
    __syncthreads();
    KS a; kinit(a, 0.f);
    for (int v = 0; v < NVH; v++)
        kmac(a, kvrow[v], enc_w[v*ND2 + tid]);
    g_kv2[((size_t)h*NM + m)*ND2 + tid] = kval(a);
}

// ---------------- 2) FUSED t_perf + encoder ----------------
__global__ void tperf_enc_kernel(const float* __restrict__ enc_b,
                                 const float* __restrict__ ln_g, const float* __restrict__ ln_b)
{
    int h = blockIdx.y, t0 = blockIdx.x*16, tid = threadIdx.x; // 128 threads
    __shared__ __align__(8) float pqs_f[NM][18];   // [m][row], padded
    __shared__ float zs[16];
    __shared__ float s4[4];
    for (int e = tid; e < 16*NM; e += 128) {
        int r = e / NM, m = e % NM;
        pqs_f[m][r] = g_pq[((size_t)(h*NT + t0 + r))*NM + m];
    }
    __syncthreads();
    if (tid < 16) {
        KS dn; kinit(dn, 0.f);
        for (int m = 0; m < NM; m++) kmac(dn, pqs_f[m][tid], g_pksum[h*NM + m]);
        zs[tid] = (float)(1.0 / ((double)kval(dn) + 1e-8));
    }
    KS2 acc2[8];
    #pragma unroll
    for (int j = 0; j < 8; j++) kinit2(acc2[j], 0ULL);
    __syncthreads();
    for (int m = 0; m < NM; m++) {
        ull kv2v = DUP(g_kv2[((size_t)h*NM + m)*ND2 + tid]);
        const float* pr = pqs_f[m];
        #pragma unroll
        for (int j = 0; j < 8; j++)
            kmac2(acc2[j], LDS64(pr + 2*j), kv2v);
    }
    float encb = enc_b[tid];
    float av[16];
    #pragma unroll
    for (int j = 0; j < 8; j++) {
        float g0, g1; kval2(acc2[j], g0, g1);
        av[2*j]   = fmaf(zs[2*j],   g0, encb);
        av[2*j+1] = fmaf(zs[2*j+1], g1, encb);
    }

    float gg = ln_g[tid], bb = ln_b[tid];
    for (int r = 0; r < 16; r++) {
        float su = blockSum128(av[r], s4);
        float mu = su * (1.f/128.f);
        float d = av[r] - mu;
        float s2 = blockSum128(d*d, s4);
        float var = s2 * (1.f/128.f);
        float y = d * (float)(1.0 / sqrt((double)var + 1e-5)) * gg + bb;
        float ge = 0.5f*y*(1.f + erff(y*0.70710678118654752f));
        g_tenc[((size_t)(h*NT + t0 + r))*ND2 + tid] = ge;
    }
}

// ---------------- 3) decoder Linear(128->256) + channel split, 16 rows ----------------
__global__ void dec_kernel(const float* __restrict__ dec_w, const float* __restrict__ dec_b)
{
    int h = blockIdx.y, t0 = blockIdx.x*16, tid = threadIdx.x; // 256 threads
    __shared__ __align__(8) float tes_f[ND2][18];
    for (int e = tid; e < 16*ND2; e += 256) {
        int r = e >> 7, vv = e & 127;
        tes_f[vv][r] = g_tenc[((size_t)(h*NT + t0 + r))*ND2 + vv];
    }
    __syncthreads();
    KS2 acc2[8];
    #pragma unroll
    for (int j = 0; j < 8; j++) kinit2(acc2[j], DUP(dec_b[tid]));
    for (int vv = 0; vv < ND2; vv++) {
        ull w2 = DUP(dec_w[vv*256 + tid]);
        const float* pr = tes_f[vv];
        #pragma unroll
        for (int j = 0; j < 8; j++)
            kmac2(acc2[j], LDS64(pr + 2*j), w2);
    }
    int g = tid >> 6, wc = tid & 63, c = h*4 + g;
    #pragma unroll
    for (int j = 0; j < 8; j++) {
        float r0, r1; kval2(acc2[j], r0, r1);
        g_xdec[((size_t)c*NT + (t0 + 2*j))*ND + wc]     = r0;
        g_xdec[((size_t)c*NT + (t0 + 2*j + 1))*ND + wc] = r1;
    }
}

// ---------------- 4) CNN stack ----------------
__global__ void conv1_kernel(const float* __restrict__ W, const float* __restrict__ B)
{
    int to = blockIdx.x, tid = threadIdx.x; // 256 threads
    int w = tid & 63, cosub = tid >> 6;
    __shared__ float in_s[NC4][3][66];
    __shared__ ull w_u[4][24][9];
    for (int e = tid; e < NC4*3*66; e += 256) {
        int ci = e / 198, rem = e % 198, dy = rem / 66, col = rem % 66;
        int r = 2*to + dy - 1, ws = col - 1;
        float vv = 0.f;
        if (r >= 0 && r < NT && ws >= 0 && ws < ND) vv = g_xdec[((size_t)ci*NT + r)*ND + ws];
        in_s[ci][dy][col] = vv;
    }
    KS2 acc2[6];
    #pragma unroll
    for (int i = 0; i < 6; i++)
        kinit2(acc2[i], F2(B[cosub + 4*i], B[cosub + 4*i + 24]));
    for (int cc = 0; cc < 12; cc++) {
        __syncthreads();
        for (int e = tid; e < 4*24*9; e += 256) {
            int cis = e / 216, rem = e % 216, co = rem / 9, kk = rem % 9;
            int cin = cc*4 + cis;
            w_u[cis][co][kk] = F2(W[((size_t)co*NC4 + cin)*9 + kk],
                                  W[((size_t)(co + 24)*NC4 + cin)*9 + kk]);
        }
        __syncthreads();
        #pragma unroll
        for (int cis = 0; cis < 4; cis++) {
            int ci = cc*4 + cis;
            ull d0 = DUP(in_s[ci][0][w]), d1 = DUP(in_s[ci][0][w+1]), d2 = DUP(in_s[ci][0][w+2]);
            ull d3 = DUP(in_s[ci][1][w]), d4 = DUP(in_s[ci][1][w+1]), d5 = DUP(in_s[ci][1][w+2]);
            ull d6 = DUP(in_s[ci][2][w]), d7 = DUP(in_s[ci][2][w+1]), d8 = DUP(in_s[ci][2][w+2]);
            #pragma unroll
            for (int i = 0; i < 6; i++) {
                const ull* wp = w_u[cis][cosub + 4*i];
                ull ch = MUL2(d0, wp[0]);
                ch = FMA2(d1, wp[1], ch); ch = FMA2(d2, wp[2], ch);
                ch = FMA2(d3, wp[3], ch); ch = FMA2(d4, wp[4], ch);
                ch = FMA2(d5, wp[5], ch); ch = FMA2(d6, wp[6], ch);
                ch = FMA2(d7, wp[7], ch); ch = FMA2(d8, wp[8], ch);
                kfold2(acc2[i], ch);
            }
        }
    }
    #pragma unroll
    for (int i = 0; i < 6; i++) {
        float r0, r1; kval2(acc2[i], r0, r1);
        int co = cosub + 4*i;
        g_c1[((size_t)co*NTH + to)*ND + w]        = fmaxf(r0, 0.f);
        g_c1[((size_t)(co + 24)*NTH + to)*ND + w] = fmaxf(r1, 0.f);
    }
}

__global__ void conv2_kernel(const float* __restrict__ W, const float* __restrict__ B)
{
    int to = blockIdx.x, tid = threadIdx.x;
    int w = tid & 63, cosub = tid >> 6;
    __shared__ float in_s[NC4][3][66];
    __shared__ ull w_u[4][24][9];
    for (int e = tid; e < NC4*3*66; e += 256) {
        int ci = e / 198, rem = e % 198, dy = rem / 66, col = rem % 66;
        int r = to + dy - 1, ws = col - 1;
        float vv = 0.f;
        if (r >= 0 && r < NTH && ws >= 0 && ws < ND) vv = g_c1[((size_t)ci*NTH + r)*ND + ws];
        in_s[ci][dy][col] = vv;
    }
    KS2 acc2[6];
    #pragma unroll
    for (int i = 0; i < 6; i++)
        kinit2(acc2[i], F2(B[cosub + 4*i], B[cosub + 4*i + 24]));
    for (int cc = 0; cc < 12; cc++) {
        __syncthreads();
        for (int e = tid; e < 4*24*9; e += 256) {
            int cis = e / 216, rem = e % 216, co = rem / 9, kk = rem % 9;
            int cin = cc*4 + cis;
            w_u[cis][co][kk] = F2(W[((size_t)co*NC4 + cin)*9 + kk],
                                  W[((size_t)(co + 24)*NC4 + cin)*9 + kk]);
        }
        __syncthreads();
        #pragma unroll
        for (int cis = 0; cis < 4; cis++) {
            int ci = cc*4 + cis;
            ull d0 = DUP(in_s[ci][0][w]), d1 = DUP(in_s[ci][0][w+1]), d2 = DUP(in_s[ci][0][w+2]);
            ull d3 = DUP(in_s[ci][1][w]), d4 = DUP(in_s[ci][1][w+1]), d5 = DUP(in_s[ci][1][w+2]);
            ull d6 = DUP(in_s[ci][2][w]), d7 = DUP(in_s[ci][2][w+1]), d8 = DUP(in_s[ci][2][w+2]);
            #pragma unroll
            for (int i = 0; i < 6; i++) {
                const ull* wp = w_u[cis][cosub + 4*i];
                ull ch = MUL2(d0, wp[0]);
                ch = FMA2(d1, wp[1], ch); ch = FMA2(d2, wp[2], ch);
                ch = FMA2(d3, wp[3], ch); ch = FMA2(d4, wp[4], ch);
                ch = FMA2(d5, wp[5], ch); ch = FMA2(d6, wp[6], ch);
                ch = FMA2(d7, wp[7], ch); ch = FMA2(d8, wp[8], ch);
                kfold2(acc2[i], ch);
            }
        }
    }
    #pragma unroll
    for (int i = 0; i < 6; i++) {
        float r0, r1; kval2(acc2[i], r0, r1);
        int co = cosub + 4*i;
        g_c2[((size_t)co*NTH + to)*ND + w]        = fmaxf(r0, 0.f);
        g_c2[((size_t)(co + 24)*NTH + to)*ND + w] = fmaxf(r1, 0.f);
    }
}

// conv3: nearest-upsample rows fused; FULL 4-op kmac2 kept (mask-critical path)
__global__ void conv3_kernel(const float* __restrict__ W, const float* __restrict__ B)
{
    int to = blockIdx.x, tid = threadIdx.x; // 384 threads
    int w = tid & 63, cop = tid >> 6;
    __shared__ float in_s[NC4][3][66];
    __shared__ ull w_u[8][6][9];
    for (int e = tid; e < NC4*3*66; e += 384) {
        int ci = e / 198, rem = e % 198, dy = rem / 66, col = rem % 66;
        int r = to + dy - 1, ws = col - 1;
        float vv = 0.f;
        if (r >= 0 && r < NT && ws >= 0 && ws < ND) vv = g_c2[((size_t)ci*NTH + (r >> 1))*ND + ws];
        in_s[ci][dy][col] = vv;
    }
    KS2 acc; kinit2(acc, F2(B[cop], B[cop + 6]));
    for (int cc = 0; cc < 6; cc++) {
        __syncthreads();
        for (int e = tid; e < 8*6*9; e += 384) {
            int cis = e / 54, rem = e % 54, c = rem / 9, kk = rem % 9;
            int cin = cc*8 + cis;
            w_u[cis][c][kk] = F2(W[((size_t)c*NC4 + cin)*9 + kk],
                                 W[((size_t)(c + 6)*NC4 + cin)*9 + kk]);
        }
        __syncthreads();
        #pragma unroll
        for (int cis = 0; cis < 8; cis++) {
            int ci = cc*8 + cis;
            const ull* wp = w_u[cis][cop];
            kmac2(acc, DUP(in_s[ci][0][w]),   wp[0]);
            kmac2(acc, DUP(in_s[ci][0][w+1]), wp[1]);
            kmac2(acc, DUP(in_s[ci][0][w+2]), wp[2]);
            kmac2(acc, DUP(in_s[ci][1][w]),   wp[3]);
            kmac2(acc, DUP(in_s[ci][1][w+1]), wp[4]);
            kmac2(acc, DUP(in_s[ci][1][w+2]), wp[5]);
            kmac2(acc, DUP(in_s[ci][2][w]),   wp[6]);
            kmac2(acc, DUP(in_s[ci][2][w+1]), wp[7]);
            kmac2(acc, DUP(in_s[ci][2][w+2]), wp[8]);
        }
    }
    float r0, r1; kval2(acc, r0, r1);
    g_c3[((size_t)cop*NT + to)*ND + w]       = r0;
    g_c3[((size_t)(cop + 6)*NT + to)*ND + w] = r1;
}

// ---------------- 5-7) est softmax with XLA-bit-matched rounding -> top-k mask ----------------
// (logic UNCHANGED — mask-critical; now 8 rows/block, one warp per row)
__global__ void mask_kernel()
{
    int tid = threadIdx.x;                          // 256 threads = 8 warps
    int t = blockIdx.x*8 + (tid >> 5), h = blockIdx.y;
    int lane = tid & 31;
    const float* row = g_c3 + ((size_t)h*NT + t)*ND;
    float v0 = row[lane], v1 = row[lane + 32];

    float mx = fmaxf(v0, v1);
    #pragma unroll
    for (int o = 16; o; o >>= 1) mx = fmaxf(mx, __shfl_xor_sync(0xffffffffu, mx, o));

    float e0 = (float)exp((double)(v0 - mx));
    float e1 = (float)exp((double)(v1 - mx));

    float s0 = e0, s1 = e1;
    #pragma unroll
    for (int o = 8; o; o >>= 1) {
        s0 += __shfl_down_sync(0xffffffffu, s0, o);
        s1 += __shfl_down_sync(0xffffffffu, s1, o);
    }
    s0 += s0;
    s1 += s1;
    float p0 = __shfl_sync(0xffffffffu, s0, 0);
    float p1 = __shfl_sync(0xffffffffu, s0, 16);
    float p2 = __shfl_sync(0xffffffffu, s1, 0);
    float p3 = __shfl_sync(0xffffffffu, s1, 16);
    float dsum = (p0 + p2) + (p1 + p3);

    float est0 = __fdiv_rn(e0, dsum);
    float est1 = __fdiv_rn(e1, dsum);

    float a1 = fmaxf(est0, est1), a2 = fminf(est0, est1);
    #pragma unroll
    for (int o = 16; o; o >>= 1) {
        float b1 = __shfl_xor_sync(0xffffffffu, a1, o);
        float b2 = __shfl_xor_sync(0xffffffffu, a2, o);
        if (b1 > a1) { a2 = fmaxf(a1, b2); a1 = b1; }
        else         { a2 = fmaxf(a2, b1); }
    }
    float thresh = a2;
    int b0 = (est0 >= thresh) ? 1 : 0;
    int b1i = (est1 >= thresh) ? 1 : 0;
    unsigned words[4];
    #pragma unroll
    for (int k2 = 0; k2 < 4; k2++) {
        int wsrc = 16*k2 + (lane >> 1);
        int bv = __shfl_sync(0xffffffffu, (k2 < 2) ? b0 : b1i, wsrc & 31);
        words[k2] = __ballot_sync(0xffffffffu, bv);
    }
    if (lane == 0) {
        unsigned* mp = g_maskbits + ((size_t)h*NT + t)*4;
        mp[0] = words[0]; mp[1] = words[1]; mp[2] = words[2]; mp[3] = words[3];
    }
}

// ---------------- 8) block-sparse masked attention ----------------
// Scoring reworked: 16 lanes cooperate per key (lane owns 4 dims, q-slice in
// a register); one LDG.128 covers 2 keys x 2 lines = 4 L1 wavefronts vs the
// previous key-per-lane pattern's 32. Dot closed with shfl_xor tree (8,4,2,1).
// sc[] layout, exp, sum order and AV path unchanged.
__global__ void attn_kernel(const float* __restrict__ q, const float* __restrict__ k,
                            const float* __restrict__ v, float* __restrict__ out)
{
    int t = blockIdx.x, h = blockIdx.y, tid = threadIdx.x; // 128 threads
    __shared__ int blk_list[128];
    __shared__ int s_nblk;
    __shared__ float sc[2048];
    __shared__ float s4[4];
    __shared__ unsigned mw[4];
    __shared__ int flags[128];
    __shared__ float part[128];

    int w = tid >> 5, lane = tid & 31;
    int lane16 = lane & 15, hi = lane >> 4;

    if (tid < 4) mw[tid] = g_maskbits[((size_t)h*NT + t)*4 + tid];
    const float4 qreg = *(const float4*)(q + ((size_t)h*NT + t)*ND + lane16*4);
    __syncthreads();
    flags[tid] = (mw[tid >> 5] >> (tid & 31)) & 1;
    __syncthreads();
    if (tid == 0) {
        int n = 0;
        for (int j = 0; j < 128; j++) if (flags[j]) blk_list[n++] = j;
        s_nblk = n;
    }
    __syncthreads();
    int nk = s_nblk * 16;

    float lmax = -1e30f;
    for (int p = w; p < (nk >> 1); p += 4) {
        int key = 2*p + hi;
        int ss = blk_list[key >> 4]*16 + (key & 15);
        const float4 k4 = *(const float4*)(k + ((size_t)h*NT + ss)*ND + lane16*4);
        float dv = k4.x*qreg.x + k4.y*qreg.y + k4.z*qreg.z + k4.w*qreg.w;
        dv += __shfl_xor_sync(0xffffffffu, dv, 8);
        dv += __shfl_xor_sync(0xffffffffu, dv, 4);
        dv += __shfl_xor_sync(0xffffffffu, dv, 2);
        dv += __shfl_xor_sync(0xffffffffu, dv, 1);
        float scv = dv * 0.125f;
        if (lane16 == 0) sc[key] = scv;
        lmax = fmaxf(lmax, scv);
    }
    #pragma unroll
    for (int o = 16; o; o >>= 1) lmax = fmaxf(lmax, __shfl_down_sync(0xffffffffu, lmax, o));
    if (lane == 0) s4[w] = lmax;
    __syncthreads();
    float gmax = fmaxf(fmaxf(s4[0], s4[1]), fmaxf(s4[2], s4[3]));

    float lsum = 0.f;
    for (int idx = tid; idx < nk; idx += 128) {
        float p = expf(sc[idx] - gmax);
        sc[idx] = p;
        lsum += p;
    }
    #pragma unroll
    for (int o = 16; o; o >>= 1) lsum += __shfl_down_sync(0xffffffffu, lsum, o);
    __syncthreads();
    if (lane == 0) s4[w] = lsum;
    __syncthreads();
    float denom = (s4[0] + s4[1]) + (s4[2] + s4[3]);
    float rden = (float)(1.0 / (double)denom);

    int d = tid & 63, half = tid >> 6;
    float acc = 0.f;
    for (int idx = half; idx < nk; idx += 2) {
        int ss = blk_list[idx >> 4]*16 + (idx & 15);
        acc += sc[idx] * v[((size_t)h*NT + ss)*ND + d];
    }
    part[tid] = acc;
    __syncthreads();
    if (tid < 64)
        out[((size_t)h*NT + t)*ND + d] = (part[tid] + part[tid + 64]) * rden;
}

// ---------------- launch ----------------
extern "C" void kernel_launch(void* const* d_in, const int* in_sizes, int n_in,
                              void* d_out, int out_size)
{
    const float* q     = (const float*)d_in[0];
    const float* k     = (const float*)d_in[1];
    const float* v     = (const float*)d_in[2];
    const float* vfa   = (const float*)d_in[3];
    const float* proj  = (const float*)d_in[4];
    const float* enc_w = (const float*)d_in[5];
    const float* enc_b = (const float*)d_in[6];
    const float* ln_g  = (const float*)d_in[7];
    const float* ln_b  = (const float*)d_in[8];
    const float* dec_w = (const float*)d_in[9];
    const float* dec_b = (const float*)d_in[10];
    const float* c1w   = (const float*)d_in[11];
    const float* c1b   = (const float*)d_in[12];
    const float* c2w   = (const float*)d_in[13];
    const float* c2b   = (const float*)d_in[14];
    const float* c3w   = (const float*)d_in[15];
    const float* c3b   = (const float*)d_in[16];
    float* out = (float*)d_out;

    phi_kernel<1><<<dim3(NT/4, NH), 128>>>(q, proj);
    phi_kernel<0><<<dim3(NT/4, NH), 128>>>(k, proj);
    headmax_kernel<<<NH, 256>>>();
    pk_finish_kernel<<<(NH*NT*NM + 255)/256, 256>>>();
    pksum_kernel<<<NH, 288>>>();
    kv_kernel<<<dim3((NM + 15)/16, NVH/16, NH), dim3(8, 16)>>>(vfa);
    kv2_kernel<<<dim3(NM, NH), 128>>>(enc_w);
    tperf_enc_kernel<<<dim3(NT/16, NH), 128>>>(enc_b, ln_g, ln_b);
    dec_kernel<<<dim3(NT/16, NH), 256>>>(dec_w, dec_b);
    conv1_kernel<<<NTH, 256>>>(c1w, c1b);
    conv2_kernel<<<NTH, 256>>>(c2w, c2b);
    conv3_kernel<<<NT, 384>>>(c3w, c3b);
    mask_kernel<<<dim3(NT/8, NH), 256>>>();
    attn_kernel<<<dim3(NT, NH), 128>>>(q, k, v, out);
}